// round 9
// baseline (speedup 1.0000x reference)
#include <cuda_runtime.h>
#include <cuda_fp16.h>
#include <math.h>
#include <stdint.h>

// ---------------- problem constants ----------------
#define BB 8
#define SS 4096
#define EE 1024
#define SD 8
#define MM (BB*SS)          // 32768
#define LDIN 1032           // E + SD
#define NITER 16            // K=1024 / 64

// ================= portable PTX helpers (sm_80+) =================
__device__ __forceinline__ uint32_t smem_to_u32(const void* smem_ptr) {
    uint32_t addr;
    asm("{ .reg .u64 tmp; cvta.to.shared.u64 tmp, %1; cvt.u32.u64 %0, tmp; }"
        : "=r"(addr) : "l"(smem_ptr));
    return addr;
}

#define CP_ASYNC16(dst, src) \
    asm volatile("cp.async.cg.shared.global [%0], [%1], 16;" \
                 :: "r"(dst), "l"(src) : "memory")
#define CP_COMMIT() asm volatile("cp.async.commit_group;" ::: "memory")
#define CP_WAIT1()  asm volatile("cp.async.wait_group 1;"  ::: "memory")

__device__ __forceinline__ void ldsm_x4(uint32_t& r0, uint32_t& r1,
                                        uint32_t& r2, uint32_t& r3,
                                        uint32_t addr) {
    asm volatile("ldmatrix.sync.aligned.m8n8.x4.shared.b16 {%0,%1,%2,%3}, [%4];"
                 : "=r"(r0), "=r"(r1), "=r"(r2), "=r"(r3) : "r"(addr));
}

__device__ __forceinline__ void mma16816(float* d, const uint32_t* a,
                                         const uint32_t* b) {
    asm volatile("mma.sync.aligned.m16n8k16.row.col.f32.f16.f16.f32 "
                 "{%0,%1,%2,%3}, {%4,%5,%6,%7}, {%8,%9}, {%0,%1,%2,%3};"
                 : "+f"(d[0]), "+f"(d[1]), "+f"(d[2]), "+f"(d[3])
                 : "r"(a[0]), "r"(a[1]), "r"(a[2]), "r"(a[3]),
                   "r"(b[0]), "r"(b[1]));
}

// ---------------- scratch (device globals, no allocs) ----------------
__device__ float g_Weff[EE * EE];
__device__ float g_Wg_eff[EE * SD];
__device__ float g_bg_eff[SD];
__device__ float g_bout_eff[EE];
__device__ float g_gate[MM * SD];
__device__ float g_si[MM * SD];
__device__ float g_states[MM * SD];
__device__ __half g_XHi[(size_t)MM * EE];      // 64 MB, x fp16 (written by gate_si)
__device__ __half g_WinHi[(size_t)EE * EE];    // 32*W_in top square, hi
__device__ __half g_WinLo[(size_t)EE * EE];
__device__ __half g_WoutHi[(size_t)EE * EE];   // 32*W_out top, transposed
__device__ __half g_WoutLo[(size_t)EE * EE];
__device__ __half g_BweffH[(size_t)EE * EE];   // Weff fp16, transposed, single

// ---------------- precompute small folded weights ----------------
__global__ void precompute_kernel(const float* __restrict__ W_in,
                                  const float* __restrict__ W_g,
                                  const float* __restrict__ b_g,
                                  const float* __restrict__ b_in,
                                  const float* __restrict__ W_out,
                                  const float* __restrict__ b_out,
                                  float* __restrict__ Wg_eff,
                                  float* __restrict__ bg_eff,
                                  float* __restrict__ bout_eff)
{
    int gid = blockIdx.x * blockDim.x + threadIdx.x;
    if (gid < EE * SD) {
        int e = gid >> 3, d = gid & 7;
        float s = 0.f;
        const float* wr = W_in + (size_t)e * LDIN;
        #pragma unroll 4
        for (int c = 0; c < LDIN; c++) s = fmaf(wr[c], W_g[c * SD + d], s);
        Wg_eff[e * SD + d] = s;
    } else if (gid < EE * SD + SD) {
        int d = gid - EE * SD;
        float s = b_g[d];
        for (int c = 0; c < LDIN; c++) s = fmaf(b_in[c], W_g[c * SD + d], s);
        bg_eff[d] = s;
    } else if (gid < EE * SD + SD + EE) {
        int n = gid - (EE * SD + SD);
        float s = b_out[n];
        for (int c = 0; c < EE; c++) s = fmaf(b_in[c], W_out[(size_t)c * EE + n], s);
        bout_eff[n] = s;
    }
}

// ---------------- hi/lo fp16 decomposition with scale, row-major ----------
__global__ void decompose_rows_f16(const float* __restrict__ src, int srcld,
                                   float scale,
                                   __half* __restrict__ Hi,
                                   __half* __restrict__ Lo)
{
    int r = blockIdx.x;
    int c4 = threadIdx.x * 4;
    float4 v = *(const float4*)(src + (size_t)r * srcld + c4);
    struct alignas(8) H4 { __half h[4]; };
    H4 H, L;
    float vv[4] = {v.x, v.y, v.z, v.w};
    #pragma unroll
    for (int i = 0; i < 4; i++) {
        float sv = vv[i] * scale;
        __half h = __float2half(sv);
        H.h[i] = h;
        L.h[i] = __float2half(sv - __half2float(h));
    }
    *(H4*)(Hi + (size_t)r * EE + c4) = H;
    *(H4*)(Lo + (size_t)r * EE + c4) = L;
}

// ---------------- hi/lo fp16 decomposition with scale, transposed ---------
__global__ void decompose_trans_f16(const float* __restrict__ src,
                                    float scale,
                                    __half* __restrict__ Hi,
                                    __half* __restrict__ Lo)
{
    __shared__ float tile[32][33];
    int e0 = blockIdx.x * 32, n0 = blockIdx.y * 32;
    int tx = threadIdx.x, ty = threadIdx.y;     // 32 x 8
    #pragma unroll
    for (int i = 0; i < 4; i++)
        tile[ty + i * 8][tx] = src[(size_t)(e0 + ty + i * 8) * 1024 + n0 + tx];
    __syncthreads();
    #pragma unroll
    for (int i = 0; i < 4; i++) {
        int n = n0 + ty + i * 8;
        float v = tile[tx][ty + i * 8] * scale;
        __half h = __float2half(v);
        Hi[(size_t)n * EE + e0 + tx] = h;
        if (Lo) Lo[(size_t)n * EE + e0 + tx] = __float2half(v - __half2float(h));
    }
}

// ================= 3-term fp16 GEMM (Weff precompute; proven R7 config) ====
// CTA 128x128, K-chunk 64, double buffer; A hi/lo, B hi/lo; 3 mma passes.
__global__ void __launch_bounds__(256, 2)
gemm_f16x3_kernel(const __half* __restrict__ Ahi,
                  const __half* __restrict__ Alo,
                  const __half* __restrict__ Bhi,
                  const __half* __restrict__ Blo,
                  float* __restrict__ C, float osc)
{
    constexpr uint32_t STAGE = 65536u;
    extern __shared__ char smem[];
    const uint32_t sb = smem_to_u32(smem);
    const int tid  = threadIdx.x;
    const int lane = tid & 31;
    const int wid  = tid >> 5;
    const int wm   = wid >> 2;
    const int wn   = wid & 3;
    const int n0   = blockIdx.x * 128;
    const int m0   = blockIdx.y * 128;

    float acc[4][4][4];
    #pragma unroll
    for (int mi = 0; mi < 4; mi++)
        #pragma unroll
        for (int ni = 0; ni < 4; ni++)
            #pragma unroll
            for (int e = 0; e < 4; e++) acc[mi][ni][e] = 0.f;

    const int row0 = tid >> 3;
    const int seg  = tid & 7;

    auto prefetch = [&](int buf, int kb) {
        const uint32_t st = sb + (uint32_t)buf * STAGE;
        #pragma unroll
        for (int i = 0; i < 4; i++) {
            int row = row0 + i * 32;
            uint32_t sw = (uint32_t)row * 128u + (uint32_t)((seg ^ (row & 7)) * 16);
            CP_ASYNC16(st + sw,          Ahi + (size_t)(m0 + row) * EE + kb + seg * 8);
            CP_ASYNC16(st + 16384u + sw, Bhi + (size_t)(n0 + row) * EE + kb + seg * 8);
            CP_ASYNC16(st + 32768u + sw, Blo + (size_t)(n0 + row) * EE + kb + seg * 8);
            CP_ASYNC16(st + 49152u + sw, Alo + (size_t)(m0 + row) * EE + kb + seg * 8);
        }
    };

    prefetch(0, 0);
    CP_COMMIT();

    const int rA  = ((lane >> 3) & 1) * 8 + (lane & 7);
    const int kA8 = lane >> 4;
    const int rB  = (lane >> 4) * 8 + (lane & 7);
    const int kB8 = (lane >> 3) & 1;

    for (int it = 0; it < NITER; it++) {
        if (it + 1 < NITER) prefetch((it + 1) & 1, (it + 1) * 64);
        CP_COMMIT();
        CP_WAIT1();
        __syncthreads();

        const uint32_t aB = sb + (uint32_t)(it & 1) * STAGE;

        #pragma unroll
        for (int ks = 0; ks < 4; ks++) {
            uint32_t af[4][4], afl[4][4], bh[4][2], bl[4][2];
            #pragma unroll
            for (int mi = 0; mi < 4; mi++) {
                int row = wm * 64 + mi * 16 + rA;
                int sh  = ks * 2 + kA8;
                uint32_t roff = (uint32_t)row * 128u + (uint32_t)((sh ^ (row & 7)) * 16);
                ldsm_x4(af[mi][0], af[mi][1], af[mi][2], af[mi][3], aB + roff);
                ldsm_x4(afl[mi][0], afl[mi][1], afl[mi][2], afl[mi][3],
                        aB + 49152u + roff);
            }
            #pragma unroll
            for (int np = 0; np < 2; np++) {
                int row = wn * 32 + np * 16 + rB;
                int sh  = ks * 2 + kB8;
                uint32_t roff = (uint32_t)row * 128u + (uint32_t)((sh ^ (row & 7)) * 16);
                uint32_t r0, r1, r2, r3;
                ldsm_x4(r0, r1, r2, r3, aB + 16384u + roff);
                bh[np * 2][0] = r0;     bh[np * 2][1] = r1;
                bh[np * 2 + 1][0] = r2; bh[np * 2 + 1][1] = r3;
                ldsm_x4(r0, r1, r2, r3, aB + 32768u + roff);
                bl[np * 2][0] = r0;     bl[np * 2][1] = r1;
                bl[np * 2 + 1][0] = r2; bl[np * 2 + 1][1] = r3;
            }
            #pragma unroll
            for (int mi = 0; mi < 4; mi++)
                #pragma unroll
                for (int ni = 0; ni < 4; ni++) {
                    mma16816(acc[mi][ni], af[mi], bh[ni]);
                    mma16816(acc[mi][ni], af[mi], bl[ni]);
                    mma16816(acc[mi][ni], afl[mi], bh[ni]);
                }
        }
        __syncthreads();
    }

    const int lr  = lane >> 2;
    const int lc2 = (lane & 3) * 2;
    #pragma unroll
    for (int mi = 0; mi < 4; mi++) {
        int r0l = wm * 64 + mi * 16 + lr;
        int r1l = r0l + 8;
        #pragma unroll
        for (int ni = 0; ni < 4; ni++) {
            int cg = wn * 32 + ni * 8 + lc2;
            float* d = acc[mi][ni];
            float2 o0 = { d[0] * osc, d[1] * osc };
            float2 o1 = { d[2] * osc, d[3] * osc };
            *(float2*)(C + (size_t)(m0 + r0l) * 1024 + n0 + cg) = o0;
            *(float2*)(C + (size_t)(m0 + r1l) * 1024 + n0 + cg) = o1;
        }
    }
}

// ================= wide 1-term fp16 GEMM (main) =================
// CTA 128(M)x256(N), 8 warps 2x4, warp tile 64x64. K-chunk 64, double buffer.
// Stage: A @0 (16KB), B @16K (32KB); STAGE=48KB. Epilogue: bias + Srank·Wbot.
__global__ void __launch_bounds__(256, 1)
gemm_wide_kernel(const __half* __restrict__ A,
                 const __half* __restrict__ Bm,
                 float* __restrict__ C,
                 const float* __restrict__ bias,
                 const float* __restrict__ Srank,
                 const float* __restrict__ Wbot)
{
    constexpr uint32_t STAGE = 49152u;
    extern __shared__ char smem[];
    const uint32_t sb = smem_to_u32(smem);
    const int tid  = threadIdx.x;
    const int lane = tid & 31;
    const int wid  = tid >> 5;
    const int wm   = wid >> 2;                   // 0..1
    const int wn   = wid & 3;                    // 0..3
    const int n0   = blockIdx.x * 256;
    const int m0   = blockIdx.y * 128;

    float acc[4][8][4];
    #pragma unroll
    for (int mi = 0; mi < 4; mi++)
        #pragma unroll
        for (int ni = 0; ni < 8; ni++)
            #pragma unroll
            for (int e = 0; e < 4; e++) acc[mi][ni][e] = 0.f;

    const int row0 = tid >> 3;     // 0..31
    const int seg  = tid & 7;

    auto prefetch = [&](int buf, int kb) {
        const uint32_t st = sb + (uint32_t)buf * STAGE;
        #pragma unroll
        for (int i = 0; i < 4; i++) {          // A: 128 rows
            int row = row0 + i * 32;
            uint32_t sw = (uint32_t)row * 128u + (uint32_t)((seg ^ (row & 7)) * 16);
            CP_ASYNC16(st + sw, A + (size_t)(m0 + row) * EE + kb + seg * 8);
        }
        #pragma unroll
        for (int i = 0; i < 8; i++) {          // B: 256 rows
            int row = row0 + i * 32;
            uint32_t sw = (uint32_t)row * 128u + (uint32_t)((seg ^ (row & 7)) * 16);
            CP_ASYNC16(st + 16384u + sw, Bm + (size_t)(n0 + row) * EE + kb + seg * 8);
        }
    };

    prefetch(0, 0);
    CP_COMMIT();

    const int rA  = ((lane >> 3) & 1) * 8 + (lane & 7);
    const int kA8 = lane >> 4;
    const int rB  = (lane >> 4) * 8 + (lane & 7);
    const int kB8 = (lane >> 3) & 1;

    for (int it = 0; it < NITER; it++) {
        if (it + 1 < NITER) prefetch((it + 1) & 1, (it + 1) * 64);
        CP_COMMIT();
        CP_WAIT1();
        __syncthreads();

        const uint32_t aB = sb + (uint32_t)(it & 1) * STAGE;
        const uint32_t bB = aB + 16384u;

        #pragma unroll
        for (int ks = 0; ks < 4; ks++) {
            uint32_t af[4][4], bf[8][2];
            #pragma unroll
            for (int mi = 0; mi < 4; mi++) {
                int row = wm * 64 + mi * 16 + rA;
                int sh  = ks * 2 + kA8;
                ldsm_x4(af[mi][0], af[mi][1], af[mi][2], af[mi][3],
                        aB + (uint32_t)row * 128u + (uint32_t)((sh ^ (row & 7)) * 16));
            }
            #pragma unroll
            for (int np = 0; np < 4; np++) {
                int row = wn * 64 + np * 16 + rB;
                int sh  = ks * 2 + kB8;
                uint32_t r0, r1, r2, r3;
                ldsm_x4(r0, r1, r2, r3,
                        bB + (uint32_t)row * 128u + (uint32_t)((sh ^ (row & 7)) * 16));
                bf[np * 2][0] = r0;     bf[np * 2][1] = r1;
                bf[np * 2 + 1][0] = r2; bf[np * 2 + 1][1] = r3;
            }
            #pragma unroll
            for (int mi = 0; mi < 4; mi++)
                #pragma unroll
                for (int ni = 0; ni < 8; ni++)
                    mma16816(acc[mi][ni], af[mi], bf[ni]);
        }
        __syncthreads();
    }

    // ---------------- epilogue ----------------
    float* const sBias = (float*)smem;                  // 256 f
    float* const sSt   = (float*)(smem + 1024);         // 128 x 8
    float* const sWb   = (float*)(smem + 1024 + 4096);  // 8 x 256
    sBias[tid] = bias[n0 + tid];
    ((float4*)sSt)[tid] = ((const float4*)(Srank + (size_t)m0 * SD))[tid];
    #pragma unroll
    for (int d8 = 0; d8 < SD; d8++)
        sWb[d8 * 256 + tid] = Wbot[(size_t)d8 * 1024 + n0 + tid];
    __syncthreads();

    const int lr  = lane >> 2;
    const int lc2 = (lane & 3) * 2;
    #pragma unroll
    for (int mi = 0; mi < 4; mi++) {
        int r0l = wm * 64 + mi * 16 + lr;
        int r1l = r0l + 8;
        float st0[SD], st1[SD];
        #pragma unroll
        for (int d = 0; d < SD; d++) {
            st0[d] = sSt[r0l * SD + d];
            st1[d] = sSt[r1l * SD + d];
        }
        #pragma unroll
        for (int ni = 0; ni < 8; ni++) {
            int cg = wn * 64 + ni * 8 + lc2;
            float* d = acc[mi][ni];
            float s00 = sBias[cg], s01 = sBias[cg + 1];
            float s10 = s00, s11 = s01;
            #pragma unroll
            for (int dd = 0; dd < SD; dd++) {
                float w0 = sWb[dd * 256 + cg], w1 = sWb[dd * 256 + cg + 1];
                s00 = fmaf(st0[dd], w0, s00); s01 = fmaf(st0[dd], w1, s01);
                s10 = fmaf(st1[dd], w0, s10); s11 = fmaf(st1[dd], w1, s11);
            }
            float2 o0 = { d[0] + s00, d[1] + s01 };
            float2 o1 = { d[2] + s10, d[3] + s11 };
            *(float2*)(C + (size_t)(m0 + r0l) * 1024 + n0 + cg) = o0;
            *(float2*)(C + (size_t)(m0 + r1l) * 1024 + n0 + cg) = o1;
        }
    }
}

// ---------------- skinny pass: gate + state_in + x->fp16 cast -------------
__global__ __launch_bounds__(256)
void gate_si_kernel(const float* __restrict__ x,
                    const float* __restrict__ Wg_eff,
                    const float* __restrict__ W_in,
                    const float* __restrict__ bg_eff,
                    const float* __restrict__ b_in,
                    float* __restrict__ gate,
                    float* __restrict__ si,
                    __half* __restrict__ xh)
{
    __shared__ float sWT[16][512];
    const int tid = threadIdx.x;
    const int lane = tid & 31;
    const int warp = tid >> 5;
    const int m0 = blockIdx.x * 32 + warp * 4;

    float acc[4][16];
    #pragma unroll
    for (int r = 0; r < 4; r++)
        #pragma unroll
        for (int d = 0; d < 16; d++) acc[r][d] = 0.f;

    for (int p = 0; p < 2; p++) {
        for (int idx = tid; idx < 16 * 512; idx += 256) {
            int d = idx >> 9, el = idx & 511;
            int e = p * 512 + el;
            sWT[d][el] = (d < 8) ? Wg_eff[e * SD + d]
                                 : W_in[(size_t)e * LDIN + EE + (d - 8)];
        }
        __syncthreads();

        for (int eb = 0; eb < 512; eb += 32) {
            float xv[4];
            #pragma unroll
            for (int r = 0; r < 4; r++) {
                size_t xi = (size_t)(m0 + r) * EE + p * 512 + eb + lane;
                xv[r] = x[xi];
                xh[xi] = __float2half(xv[r]);      // fused fp16 cast
            }
            #pragma unroll
            for (int d = 0; d < 16; d++) {
                float w = sWT[d][eb + lane];
                #pragma unroll
                for (int r = 0; r < 4; r++)
                    acc[r][d] = fmaf(xv[r], w, acc[r][d]);
            }
        }
        __syncthreads();
    }

    #pragma unroll
    for (int r = 0; r < 4; r++) {
        #pragma unroll
        for (int d = 0; d < 16; d++) {
            float v = acc[r][d];
            v += __shfl_xor_sync(0xffffffffu, v, 16);
            v += __shfl_xor_sync(0xffffffffu, v, 8);
            v += __shfl_xor_sync(0xffffffffu, v, 4);
            v += __shfl_xor_sync(0xffffffffu, v, 2);
            v += __shfl_xor_sync(0xffffffffu, v, 1);
            acc[r][d] = v;
        }
        int m = m0 + r;
        if (lane < 8) {
            float logit = acc[r][lane] + bg_eff[lane];
            gate[m * SD + lane] = 1.0f / (1.0f + expf(-logit));
        } else if (lane < 16) {
            si[m * SD + (lane - 8)] = acc[r][lane] + b_in[EE + (lane - 8)];
        }
    }
}

// ---------------- parallel linear-recurrence scan ----------------
__global__ __launch_bounds__(128)
void scan_par_kernel(const float* __restrict__ gate,
                     const float* __restrict__ si,
                     float* __restrict__ states,
                     float* __restrict__ final_state)
{
    const int chain = blockIdx.x;            // 0..63
    const int b = chain >> 3, d = chain & 7;
    const int t = threadIdx.x;               // 0..127
    const int lane = t & 31, warp = t >> 5;
    const float* gp = gate + (size_t)b * SS * SD + d;
    const float* sp = si   + (size_t)b * SS * SD + d;
    float*       op = states + (size_t)b * SS * SD + d;
    const int s0 = t * 32;

    float g[32], cc[32];
    float G = 1.f, C = 0.f;
    #pragma unroll
    for (int u = 0; u < 32; u++) {
        float gv = gp[(s0 + u) * SD];
        float sv = sp[(s0 + u) * SD];
        float cv = sv - gv * sv;
        g[u] = gv; cc[u] = cv;
        C = fmaf(gv, C, cv);
        G = gv * G;
    }
    #pragma unroll
    for (int off = 1; off < 32; off <<= 1) {
        float pG = __shfl_up_sync(0xffffffffu, G, off);
        float pC = __shfl_up_sync(0xffffffffu, C, off);
        if (lane >= off) { C = fmaf(G, pC, C); G *= pG; }
    }
    __shared__ float wG[4], wC[4];
    if (lane == 31) { wG[warp] = G; wC[warp] = C; }
    __syncthreads();
    float preC = 0.f;
    for (int w = 0; w < warp; w++) { preC = fmaf(wG[w], preC, wC[w]); }
    float eG = __shfl_up_sync(0xffffffffu, G, 1);
    float eC = __shfl_up_sync(0xffffffffu, C, 1);
    if (lane == 0) { eG = 1.f; eC = 0.f; }
    float s = fmaf(eG, preC, eC);
    #pragma unroll
    for (int u = 0; u < 32; u++) {
        s = fmaf(g[u], s, cc[u]);
        op[(s0 + u) * SD] = s;
    }
    if (t == 127) final_state[b * SD + d] = s;
}

// ---------------- launch ----------------
extern "C" void kernel_launch(void* const* d_in, const int* in_sizes, int n_in,
                              void* d_out, int out_size)
{
    const float* x     = (const float*)d_in[0];
    const float* W_in  = (const float*)d_in[1];
    const float* b_in  = (const float*)d_in[2];
    const float* W_g   = (const float*)d_in[3];
    const float* b_g   = (const float*)d_in[4];
    const float* W_out = (const float*)d_in[5];
    const float* b_out = (const float*)d_in[6];
    float* out = (float*)d_out;

    float *Weff, *Wg_eff, *bg_eff, *bout_eff, *gate, *si, *states;
    __half *XHi, *WinHi, *WinLo, *WoutHi, *WoutLo, *BweffH;
    cudaGetSymbolAddress((void**)&Weff,     g_Weff);
    cudaGetSymbolAddress((void**)&Wg_eff,   g_Wg_eff);
    cudaGetSymbolAddress((void**)&bg_eff,   g_bg_eff);
    cudaGetSymbolAddress((void**)&bout_eff, g_bout_eff);
    cudaGetSymbolAddress((void**)&gate,     g_gate);
    cudaGetSymbolAddress((void**)&si,       g_si);
    cudaGetSymbolAddress((void**)&states,   g_states);
    cudaGetSymbolAddress((void**)&XHi,      g_XHi);
    cudaGetSymbolAddress((void**)&WinHi,    g_WinHi);
    cudaGetSymbolAddress((void**)&WinLo,    g_WinLo);
    cudaGetSymbolAddress((void**)&WoutHi,   g_WoutHi);
    cudaGetSymbolAddress((void**)&WoutLo,   g_WoutLo);
    cudaGetSymbolAddress((void**)&BweffH,   g_BweffH);

    cudaFuncSetAttribute(gemm_f16x3_kernel,
                         cudaFuncAttributeMaxDynamicSharedMemorySize, 131072);
    cudaFuncSetAttribute(gemm_wide_kernel,
                         cudaFuncAttributeMaxDynamicSharedMemorySize, 98304);

    // 1) small folded weights
    int tot = EE * SD + SD + EE;
    precompute_kernel<<<(tot + 255) / 256, 256>>>(W_in, W_g, b_g, b_in, W_out, b_out,
                                                  Wg_eff, bg_eff, bout_eff);

    // 2) decompose 32*W_in top-square (rows) + 32*W_out top (transposed), hi/lo
    decompose_rows_f16<<<EE, 256>>>(W_in, LDIN, 32.0f, WinHi, WinLo);
    decompose_trans_f16<<<dim3(32, 32), dim3(32, 8)>>>(W_out, 32.0f, WoutHi, WoutLo);

    // 3) Weff = W_in[:, :E] @ W_out[:E, :]  (3-term accurate; /1024 undoes 32*32)
    gemm_f16x3_kernel<<<dim3(8, 8), 256, 131072>>>(
        WinHi, WinLo, WoutHi, WoutLo, Weff, 1.0f / 1024.0f);

    // 4) Weff -> single fp16, transposed
    decompose_trans_f16<<<dim3(32, 32), dim3(32, 8)>>>(Weff, 1.0f, BweffH, nullptr);

    // 5) gate + state_in + fused x->fp16 cast
    gate_si_kernel<<<MM / 32, 256>>>(x, Wg_eff, W_in, bg_eff, b_in, gate, si, XHi);

    // 6) parallel scan (also writes final_state at tail of output)
    scan_par_kernel<<<64, 128>>>(gate, si, states, out + (size_t)MM * EE);

    // 7) out = x @ Weff + states @ W_out[E:, :] + bout_eff   (wide 1-term)
    gemm_wide_kernel<<<dim3(4, MM / 128), 256, 98304>>>(
        XHi, BweffH, out, bout_eff, states, W_out + (size_t)EE * EE);
}

// round 10
// speedup vs baseline: 1.0067x; 1.0067x over previous
#include <cuda_runtime.h>
#include <cuda_fp16.h>
#include <math.h>
#include <stdint.h>

// ---------------- problem constants ----------------
#define BB 8
#define SS 4096
#define EE 1024
#define SD 8
#define MM (BB*SS)          // 32768
#define LDIN 1032           // E + SD
#define NITER 16            // K=1024 / 64

// ================= portable PTX helpers (sm_80+) =================
__device__ __forceinline__ uint32_t smem_to_u32(const void* smem_ptr) {
    uint32_t addr;
    asm("{ .reg .u64 tmp; cvta.to.shared.u64 tmp, %1; cvt.u32.u64 %0, tmp; }"
        : "=r"(addr) : "l"(smem_ptr));
    return addr;
}

#define CP_ASYNC16(dst, src) \
    asm volatile("cp.async.cg.shared.global [%0], [%1], 16;" \
                 :: "r"(dst), "l"(src) : "memory")
#define CP_COMMIT() asm volatile("cp.async.commit_group;" ::: "memory")
#define CP_WAIT1()  asm volatile("cp.async.wait_group 1;"  ::: "memory")
#define CP_WAIT2()  asm volatile("cp.async.wait_group 2;"  ::: "memory")

__device__ __forceinline__ void ldsm_x4(uint32_t& r0, uint32_t& r1,
                                        uint32_t& r2, uint32_t& r3,
                                        uint32_t addr) {
    asm volatile("ldmatrix.sync.aligned.m8n8.x4.shared.b16 {%0,%1,%2,%3}, [%4];"
                 : "=r"(r0), "=r"(r1), "=r"(r2), "=r"(r3) : "r"(addr));
}

__device__ __forceinline__ void mma16816(float* d, const uint32_t* a,
                                         const uint32_t* b) {
    asm volatile("mma.sync.aligned.m16n8k16.row.col.f32.f16.f16.f32 "
                 "{%0,%1,%2,%3}, {%4,%5,%6,%7}, {%8,%9}, {%0,%1,%2,%3};"
                 : "+f"(d[0]), "+f"(d[1]), "+f"(d[2]), "+f"(d[3])
                 : "r"(a[0]), "r"(a[1]), "r"(a[2]), "r"(a[3]),
                   "r"(b[0]), "r"(b[1]));
}

// ---------------- scratch (device globals, no allocs) ----------------
__device__ float g_Wg_eff[EE * SD];
__device__ float g_bg_eff[SD];
__device__ float g_bout_eff[EE];
__device__ float g_gate[MM * SD];
__device__ float g_si[MM * SD];
__device__ float g_states[MM * SD];
__device__ __half g_XHi[(size_t)MM * EE];      // 64 MB, x fp16 (written by gate_si)
__device__ __half g_WinHi[(size_t)EE * EE];    // 32*W_in top square, hi  (rows)
__device__ __half g_WinLo[(size_t)EE * EE];
__device__ __half g_WoutHi[(size_t)EE * EE];   // 32*W_out top, transposed
__device__ __half g_WoutLo[(size_t)EE * EE];
__device__ __half g_BweffH[(size_t)EE * EE];   // Weff^T fp16 (written by x3 gemm)

// ---------------- precompute small folded weights ----------------
__global__ void precompute_kernel(const float* __restrict__ W_in,
                                  const float* __restrict__ W_g,
                                  const float* __restrict__ b_g,
                                  const float* __restrict__ b_in,
                                  const float* __restrict__ W_out,
                                  const float* __restrict__ b_out,
                                  float* __restrict__ Wg_eff,
                                  float* __restrict__ bg_eff,
                                  float* __restrict__ bout_eff)
{
    int gid = blockIdx.x * blockDim.x + threadIdx.x;
    if (gid < EE * SD) {
        int e = gid >> 3, d = gid & 7;
        float s = 0.f;
        const float* wr = W_in + (size_t)e * LDIN;
        #pragma unroll 4
        for (int c = 0; c < LDIN; c++) s = fmaf(wr[c], W_g[c * SD + d], s);
        Wg_eff[e * SD + d] = s;
    } else if (gid < EE * SD + SD) {
        int d = gid - EE * SD;
        float s = b_g[d];
        for (int c = 0; c < LDIN; c++) s = fmaf(b_in[c], W_g[c * SD + d], s);
        bg_eff[d] = s;
    } else if (gid < EE * SD + SD + EE) {
        int n = gid - (EE * SD + SD);
        float s = b_out[n];
        for (int c = 0; c < EE; c++) s = fmaf(b_in[c], W_out[(size_t)c * EE + n], s);
        bout_eff[n] = s;
    }
}

// ------- fused decompose: W_in rows (blocks 0..1023) + W_out^T (1024..2047) --
__global__ void fused_decompose_kernel(const float* __restrict__ W_in,
                                       const float* __restrict__ W_out,
                                       __half* __restrict__ WinHi,
                                       __half* __restrict__ WinLo,
                                       __half* __restrict__ WoutHi,
                                       __half* __restrict__ WoutLo)
{
    const int tid = threadIdx.x;
    if (blockIdx.x < 1024) {
        // rows: 32 * W_in[r][0:1024]
        int r = blockIdx.x;
        int c4 = tid * 4;
        float4 v = *(const float4*)(W_in + (size_t)r * LDIN + c4);
        struct alignas(8) H4 { __half h[4]; };
        H4 H, L;
        float vv[4] = {v.x, v.y, v.z, v.w};
        #pragma unroll
        for (int i = 0; i < 4; i++) {
            float sv = vv[i] * 32.0f;
            __half h = __float2half(sv);
            H.h[i] = h;
            L.h[i] = __float2half(sv - __half2float(h));
        }
        *(H4*)(WinHi + (size_t)r * EE + c4) = H;
        *(H4*)(WinLo + (size_t)r * EE + c4) = L;
    } else {
        // transposed: 32 * W_out[e][n] -> [n][e]
        __shared__ float tile[32][33];
        int b = blockIdx.x - 1024;
        int e0 = (b & 31) * 32, n0 = (b >> 5) * 32;
        int tx = tid & 31, ty = tid >> 5;       // 32 x 8
        #pragma unroll
        for (int i = 0; i < 4; i++)
            tile[ty + i * 8][tx] = W_out[(size_t)(e0 + ty + i * 8) * 1024 + n0 + tx];
        __syncthreads();
        #pragma unroll
        for (int i = 0; i < 4; i++) {
            int n = n0 + ty + i * 8;
            float v = tile[tx][ty + i * 8] * 32.0f;
            __half h = __float2half(v);
            WoutHi[(size_t)n * EE + e0 + tx] = h;
            WoutLo[(size_t)n * EE + e0 + tx] = __float2half(v - __half2float(h));
        }
    }
}

// ================= 3-term fp16 GEMM -> fp16 output (Weff^T precompute) =====
// D[i][j] = osc * sum_k A[i][k]*B[j][k], written as __half at D[i*1024+j].
// Called with A=WoutT (i = Weff col n), B=Win rows (j = Weff row m) -> D = Weff^T.
__global__ void __launch_bounds__(256, 2)
gemm_f16x3_kernel(const __half* __restrict__ Ahi,
                  const __half* __restrict__ Alo,
                  const __half* __restrict__ Bhi,
                  const __half* __restrict__ Blo,
                  __half* __restrict__ C, float osc)
{
    constexpr uint32_t STAGE = 65536u;
    extern __shared__ char smem[];
    const uint32_t sb = smem_to_u32(smem);
    const int tid  = threadIdx.x;
    const int lane = tid & 31;
    const int wid  = tid >> 5;
    const int wm   = wid >> 2;
    const int wn   = wid & 3;
    const int n0   = blockIdx.x * 128;
    const int m0   = blockIdx.y * 128;

    float acc[4][4][4];
    #pragma unroll
    for (int mi = 0; mi < 4; mi++)
        #pragma unroll
        for (int ni = 0; ni < 4; ni++)
            #pragma unroll
            for (int e = 0; e < 4; e++) acc[mi][ni][e] = 0.f;

    const int row0 = tid >> 3;
    const int seg  = tid & 7;

    auto prefetch = [&](int buf, int kb) {
        const uint32_t st = sb + (uint32_t)buf * STAGE;
        #pragma unroll
        for (int i = 0; i < 4; i++) {
            int row = row0 + i * 32;
            uint32_t sw = (uint32_t)row * 128u + (uint32_t)((seg ^ (row & 7)) * 16);
            CP_ASYNC16(st + sw,          Ahi + (size_t)(m0 + row) * EE + kb + seg * 8);
            CP_ASYNC16(st + 16384u + sw, Bhi + (size_t)(n0 + row) * EE + kb + seg * 8);
            CP_ASYNC16(st + 32768u + sw, Blo + (size_t)(n0 + row) * EE + kb + seg * 8);
            CP_ASYNC16(st + 49152u + sw, Alo + (size_t)(m0 + row) * EE + kb + seg * 8);
        }
    };

    prefetch(0, 0);
    CP_COMMIT();

    const int rA  = ((lane >> 3) & 1) * 8 + (lane & 7);
    const int kA8 = lane >> 4;
    const int rB  = (lane >> 4) * 8 + (lane & 7);
    const int kB8 = (lane >> 3) & 1;

    for (int it = 0; it < NITER; it++) {
        if (it + 1 < NITER) prefetch((it + 1) & 1, (it + 1) * 64);
        CP_COMMIT();
        CP_WAIT1();
        __syncthreads();

        const uint32_t aB = sb + (uint32_t)(it & 1) * STAGE;

        #pragma unroll
        for (int ks = 0; ks < 4; ks++) {
            uint32_t af[4][4], afl[4][4], bh[4][2], bl[4][2];
            #pragma unroll
            for (int mi = 0; mi < 4; mi++) {
                int row = wm * 64 + mi * 16 + rA;
                int sh  = ks * 2 + kA8;
                uint32_t roff = (uint32_t)row * 128u + (uint32_t)((sh ^ (row & 7)) * 16);
                ldsm_x4(af[mi][0], af[mi][1], af[mi][2], af[mi][3], aB + roff);
                ldsm_x4(afl[mi][0], afl[mi][1], afl[mi][2], afl[mi][3],
                        aB + 49152u + roff);
            }
            #pragma unroll
            for (int np = 0; np < 2; np++) {
                int row = wn * 32 + np * 16 + rB;
                int sh  = ks * 2 + kB8;
                uint32_t roff = (uint32_t)row * 128u + (uint32_t)((sh ^ (row & 7)) * 16);
                uint32_t r0, r1, r2, r3;
                ldsm_x4(r0, r1, r2, r3, aB + 16384u + roff);
                bh[np * 2][0] = r0;     bh[np * 2][1] = r1;
                bh[np * 2 + 1][0] = r2; bh[np * 2 + 1][1] = r3;
                ldsm_x4(r0, r1, r2, r3, aB + 32768u + roff);
                bl[np * 2][0] = r0;     bl[np * 2][1] = r1;
                bl[np * 2 + 1][0] = r2; bl[np * 2 + 1][1] = r3;
            }
            #pragma unroll
            for (int mi = 0; mi < 4; mi++)
                #pragma unroll
                for (int ni = 0; ni < 4; ni++) {
                    mma16816(acc[mi][ni], af[mi], bh[ni]);
                    mma16816(acc[mi][ni], af[mi], bl[ni]);
                    mma16816(acc[mi][ni], afl[mi], bh[ni]);
                }
        }
        __syncthreads();
    }

    const int lr  = lane >> 2;
    const int lc2 = (lane & 3) * 2;
    #pragma unroll
    for (int mi = 0; mi < 4; mi++) {
        int r0l = wm * 64 + mi * 16 + lr;
        int r1l = r0l + 8;
        #pragma unroll
        for (int ni = 0; ni < 4; ni++) {
            int cg = wn * 32 + ni * 8 + lc2;
            float* d = acc[mi][ni];
            __half2 o0 = { __float2half(d[0] * osc), __float2half(d[1] * osc) };
            __half2 o1 = { __float2half(d[2] * osc), __float2half(d[3] * osc) };
            *(__half2*)(C + (size_t)(m0 + r0l) * 1024 + n0 + cg) = o0;
            *(__half2*)(C + (size_t)(m0 + r1l) * 1024 + n0 + cg) = o1;
        }
    }
}

// ================= main 1-term fp16 GEMM, 3-stage pipeline =================
// C[m][n] = sum_k A[m][k]*B[n][k] + bias[n] + Srank[m][.]·Wbot[.][n].
// CTA 128x128, 8 warps (64x32), K-chunk 64, 3-stage cp.async (32KB/stage).
__global__ void __launch_bounds__(256, 2)
gemm_main_kernel(const __half* __restrict__ A,
                 const __half* __restrict__ Bm,
                 float* __restrict__ C,
                 const float* __restrict__ bias,
                 const float* __restrict__ Srank,
                 const float* __restrict__ Wbot)
{
    constexpr uint32_t STAGE = 32768u;
    extern __shared__ char smem[];
    const uint32_t sb = smem_to_u32(smem);
    const int tid  = threadIdx.x;
    const int lane = tid & 31;
    const int wid  = tid >> 5;
    const int wm   = wid >> 2;
    const int wn   = wid & 3;
    const int n0   = blockIdx.x * 128;
    const int m0   = blockIdx.y * 128;

    float acc[4][4][4];
    #pragma unroll
    for (int mi = 0; mi < 4; mi++)
        #pragma unroll
        for (int ni = 0; ni < 4; ni++)
            #pragma unroll
            for (int e = 0; e < 4; e++) acc[mi][ni][e] = 0.f;

    const int row0 = tid >> 3;
    const int seg  = tid & 7;

    auto prefetch = [&](int stage, int kb) {
        const uint32_t st = sb + (uint32_t)stage * STAGE;
        #pragma unroll
        for (int i = 0; i < 4; i++) {
            int row = row0 + i * 32;
            uint32_t sw = (uint32_t)row * 128u + (uint32_t)((seg ^ (row & 7)) * 16);
            CP_ASYNC16(st + sw,          A  + (size_t)(m0 + row) * EE + kb + seg * 8);
            CP_ASYNC16(st + 16384u + sw, Bm + (size_t)(n0 + row) * EE + kb + seg * 8);
        }
    };

    prefetch(0, 0);  CP_COMMIT();
    prefetch(1, 64); CP_COMMIT();

    const int rA  = ((lane >> 3) & 1) * 8 + (lane & 7);
    const int kA8 = lane >> 4;
    const int rB  = (lane >> 4) * 8 + (lane & 7);
    const int kB8 = (lane >> 3) & 1;

    int sc = 0;                            // current stage, mod-free rotation
    for (int it = 0; it < NITER; it++) {
        int sn = sc + 2; if (sn >= 3) sn -= 3;
        if (it + 2 < NITER) prefetch(sn, (it + 2) * 64);
        CP_COMMIT();
        CP_WAIT2();
        __syncthreads();

        const uint32_t aB = sb + (uint32_t)sc * STAGE;
        const uint32_t bB = aB + 16384u;

        #pragma unroll
        for (int ks = 0; ks < 4; ks++) {
            uint32_t af[4][4], bf[4][2];
            #pragma unroll
            for (int mi = 0; mi < 4; mi++) {
                int row = wm * 64 + mi * 16 + rA;
                int sh  = ks * 2 + kA8;
                ldsm_x4(af[mi][0], af[mi][1], af[mi][2], af[mi][3],
                        aB + (uint32_t)row * 128u + (uint32_t)((sh ^ (row & 7)) * 16));
            }
            #pragma unroll
            for (int np = 0; np < 2; np++) {
                int row = wn * 32 + np * 16 + rB;
                int sh  = ks * 2 + kB8;
                uint32_t r0, r1, r2, r3;
                ldsm_x4(r0, r1, r2, r3,
                        bB + (uint32_t)row * 128u + (uint32_t)((sh ^ (row & 7)) * 16));
                bf[np * 2][0] = r0;     bf[np * 2][1] = r1;
                bf[np * 2 + 1][0] = r2; bf[np * 2 + 1][1] = r3;
            }
            #pragma unroll
            for (int mi = 0; mi < 4; mi++)
                #pragma unroll
                for (int ni = 0; ni < 4; ni++)
                    mma16816(acc[mi][ni], af[mi], bf[ni]);
        }
        __syncthreads();
        if (++sc == 3) sc = 0;
    }

    // ---------------- epilogue ----------------
    float* const sBias = (float*)smem;                 // 128 f
    float* const sSt   = (float*)(smem + 512);         // 128 x 8
    float* const sWb   = (float*)(smem + 512 + 4096);  // 8 x 128
    if (tid < 128) sBias[tid] = bias[n0 + tid];
    ((float4*)sSt)[tid] = ((const float4*)(Srank + (size_t)m0 * SD))[tid];
    for (int i = tid; i < 1024; i += 256) {
        int d8 = i >> 7, nl = i & 127;
        sWb[d8 * 128 + nl] = Wbot[(size_t)d8 * 1024 + n0 + nl];
    }
    __syncthreads();

    const int lr  = lane >> 2;
    const int lc2 = (lane & 3) * 2;
    #pragma unroll
    for (int mi = 0; mi < 4; mi++) {
        int r0l = wm * 64 + mi * 16 + lr;
        int r1l = r0l + 8;
        float st0[SD], st1[SD];
        #pragma unroll
        for (int d = 0; d < SD; d++) {
            st0[d] = sSt[r0l * SD + d];
            st1[d] = sSt[r1l * SD + d];
        }
        #pragma unroll
        for (int ni = 0; ni < 4; ni++) {
            int cg = wn * 32 + ni * 8 + lc2;
            float* d = acc[mi][ni];
            float s00 = sBias[cg], s01 = sBias[cg + 1];
            float s10 = s00, s11 = s01;
            #pragma unroll
            for (int dd = 0; dd < SD; dd++) {
                float w0 = sWb[dd * 128 + cg], w1 = sWb[dd * 128 + cg + 1];
                s00 = fmaf(st0[dd], w0, s00); s01 = fmaf(st0[dd], w1, s01);
                s10 = fmaf(st1[dd], w0, s10); s11 = fmaf(st1[dd], w1, s11);
            }
            float2 o0 = { d[0] + s00, d[1] + s01 };
            float2 o1 = { d[2] + s10, d[3] + s11 };
            *(float2*)(C + (size_t)(m0 + r0l) * 1024 + n0 + cg) = o0;
            *(float2*)(C + (size_t)(m0 + r1l) * 1024 + n0 + cg) = o1;
        }
    }
}

// ---------------- skinny pass: gate + state_in + x->fp16 cast -------------
__global__ __launch_bounds__(256)
void gate_si_kernel(const float* __restrict__ x,
                    const float* __restrict__ Wg_eff,
                    const float* __restrict__ W_in,
                    const float* __restrict__ bg_eff,
                    const float* __restrict__ b_in,
                    float* __restrict__ gate,
                    float* __restrict__ si,
                    __half* __restrict__ xh)
{
    __shared__ float sWT[16][512];
    const int tid = threadIdx.x;
    const int lane = tid & 31;
    const int warp = tid >> 5;
    const int m0 = blockIdx.x * 32 + warp * 4;

    float acc[4][16];
    #pragma unroll
    for (int r = 0; r < 4; r++)
        #pragma unroll
        for (int d = 0; d < 16; d++) acc[r][d] = 0.f;

    for (int p = 0; p < 2; p++) {
        for (int idx = tid; idx < 16 * 512; idx += 256) {
            int d = idx >> 9, el = idx & 511;
            int e = p * 512 + el;
            sWT[d][el] = (d < 8) ? Wg_eff[e * SD + d]
                                 : W_in[(size_t)e * LDIN + EE + (d - 8)];
        }
        __syncthreads();

        for (int eb = 0; eb < 512; eb += 32) {
            float xv[4];
            #pragma unroll
            for (int r = 0; r < 4; r++) {
                size_t xi = (size_t)(m0 + r) * EE + p * 512 + eb + lane;
                xv[r] = x[xi];
                xh[xi] = __float2half(xv[r]);      // fused fp16 cast
            }
            #pragma unroll
            for (int d = 0; d < 16; d++) {
                float w = sWT[d][eb + lane];
                #pragma unroll
                for (int r = 0; r < 4; r++)
                    acc[r][d] = fmaf(xv[r], w, acc[r][d]);
            }
        }
        __syncthreads();
    }

    #pragma unroll
    for (int r = 0; r < 4; r++) {
        #pragma unroll
        for (int d = 0; d < 16; d++) {
            float v = acc[r][d];
            v += __shfl_xor_sync(0xffffffffu, v, 16);
            v += __shfl_xor_sync(0xffffffffu, v, 8);
            v += __shfl_xor_sync(0xffffffffu, v, 4);
            v += __shfl_xor_sync(0xffffffffu, v, 2);
            v += __shfl_xor_sync(0xffffffffu, v, 1);
            acc[r][d] = v;
        }
        int m = m0 + r;
        if (lane < 8) {
            float logit = acc[r][lane] + bg_eff[lane];
            gate[m * SD + lane] = 1.0f / (1.0f + expf(-logit));
        } else if (lane < 16) {
            si[m * SD + (lane - 8)] = acc[r][lane] + b_in[EE + (lane - 8)];
        }
    }
}

// ---------------- parallel linear-recurrence scan ----------------
__global__ __launch_bounds__(128)
void scan_par_kernel(const float* __restrict__ gate,
                     const float* __restrict__ si,
                     float* __restrict__ states,
                     float* __restrict__ final_state)
{
    const int chain = blockIdx.x;            // 0..63
    const int b = chain >> 3, d = chain & 7;
    const int t = threadIdx.x;               // 0..127
    const int lane = t & 31, warp = t >> 5;
    const float* gp = gate + (size_t)b * SS * SD + d;
    const float* sp = si   + (size_t)b * SS * SD + d;
    float*       op = states + (size_t)b * SS * SD + d;
    const int s0 = t * 32;

    float g[32], cc[32];
    float G = 1.f, C = 0.f;
    #pragma unroll
    for (int u = 0; u < 32; u++) {
        float gv = gp[(s0 + u) * SD];
        float sv = sp[(s0 + u) * SD];
        float cv = sv - gv * sv;
        g[u] = gv; cc[u] = cv;
        C = fmaf(gv, C, cv);
        G = gv * G;
    }
    #pragma unroll
    for (int off = 1; off < 32; off <<= 1) {
        float pG = __shfl_up_sync(0xffffffffu, G, off);
        float pC = __shfl_up_sync(0xffffffffu, C, off);
        if (lane >= off) { C = fmaf(G, pC, C); G *= pG; }
    }
    __shared__ float wG[4], wC[4];
    if (lane == 31) { wG[warp] = G; wC[warp] = C; }
    __syncthreads();
    float preC = 0.f;
    for (int w = 0; w < warp; w++) { preC = fmaf(wG[w], preC, wC[w]); }
    float eG = __shfl_up_sync(0xffffffffu, G, 1);
    float eC = __shfl_up_sync(0xffffffffu, C, 1);
    if (lane == 0) { eG = 1.f; eC = 0.f; }
    float s = fmaf(eG, preC, eC);
    #pragma unroll
    for (int u = 0; u < 32; u++) {
        s = fmaf(g[u], s, cc[u]);
        op[(s0 + u) * SD] = s;
    }
    if (t == 127) final_state[b * SD + d] = s;
}

// ---------------- launch ----------------
extern "C" void kernel_launch(void* const* d_in, const int* in_sizes, int n_in,
                              void* d_out, int out_size)
{
    const float* x     = (const float*)d_in[0];
    const float* W_in  = (const float*)d_in[1];
    const float* b_in  = (const float*)d_in[2];
    const float* W_g   = (const float*)d_in[3];
    const float* b_g   = (const float*)d_in[4];
    const float* W_out = (const float*)d_in[5];
    const float* b_out = (const float*)d_in[6];
    float* out = (float*)d_out;

    float *Wg_eff, *bg_eff, *bout_eff, *gate, *si, *states;
    __half *XHi, *WinHi, *WinLo, *WoutHi, *WoutLo, *BweffH;
    cudaGetSymbolAddress((void**)&Wg_eff,   g_Wg_eff);
    cudaGetSymbolAddress((void**)&bg_eff,   g_bg_eff);
    cudaGetSymbolAddress((void**)&bout_eff, g_bout_eff);
    cudaGetSymbolAddress((void**)&gate,     g_gate);
    cudaGetSymbolAddress((void**)&si,       g_si);
    cudaGetSymbolAddress((void**)&states,   g_states);
    cudaGetSymbolAddress((void**)&XHi,      g_XHi);
    cudaGetSymbolAddress((void**)&WinHi,    g_WinHi);
    cudaGetSymbolAddress((void**)&WinLo,    g_WinLo);
    cudaGetSymbolAddress((void**)&WoutHi,   g_WoutHi);
    cudaGetSymbolAddress((void**)&WoutLo,   g_WoutLo);
    cudaGetSymbolAddress((void**)&BweffH,   g_BweffH);

    cudaFuncSetAttribute(gemm_f16x3_kernel,
                         cudaFuncAttributeMaxDynamicSharedMemorySize, 131072);
    cudaFuncSetAttribute(gemm_main_kernel,
                         cudaFuncAttributeMaxDynamicSharedMemorySize, 98304);

    // 0) small folded weights
    int tot = EE * SD + SD + EE;
    precompute_kernel<<<(tot + 255) / 256, 256>>>(W_in, W_g, b_g, b_in, W_out, b_out,
                                                  Wg_eff, bg_eff, bout_eff);

    // 1) fused decompose: 32*W_in rows + 32*W_out transposed (hi/lo)
    fused_decompose_kernel<<<2048, 256>>>(W_in, W_out, WinHi, WinLo, WoutHi, WoutLo);

    // 2) BweffH = fp16(Weff^T) = (W_out^T) @ (W_in rows), 3-term; /1024 undoes 32*32
    gemm_f16x3_kernel<<<dim3(8, 8), 256, 131072>>>(
        WoutHi, WoutLo, WinHi, WinLo, BweffH, 1.0f / 1024.0f);

    // 3) gate + state_in + fused x->fp16 cast
    gate_si_kernel<<<MM / 32, 256>>>(x, Wg_eff, W_in, bg_eff, b_in, gate, si, XHi);

    // 4) parallel scan (also writes final_state at tail of output)
    scan_par_kernel<<<64, 128>>>(gate, si, states, out + (size_t)MM * EE);

    // 5) out = x @ Weff + states @ W_out[E:, :] + bout_eff   (main; 3-stage)
    gemm_main_kernel<<<dim3(8, MM / 128), 256, 98304>>>(
        XHi, BweffH, out, bout_eff, states, W_out + (size_t)EE * EE);
}

// round 11
// speedup vs baseline: 1.2758x; 1.2672x over previous
#include <cuda_runtime.h>
#include <cuda_fp16.h>
#include <math.h>
#include <stdint.h>

// ---------------- problem constants ----------------
#define BB 8
#define SS 4096
#define EE 1024
#define SD 8
#define MM (BB*SS)          // 32768
#define LDIN 1032           // E + SD
#define NITER 16            // K=1024 / 64

// ================= portable PTX helpers (sm_80+) =================
__device__ __forceinline__ uint32_t smem_to_u32(const void* smem_ptr) {
    uint32_t addr;
    asm("{ .reg .u64 tmp; cvta.to.shared.u64 tmp, %1; cvt.u32.u64 %0, tmp; }"
        : "=r"(addr) : "l"(smem_ptr));
    return addr;
}

#define CP_ASYNC16(dst, src) \
    asm volatile("cp.async.cg.shared.global [%0], [%1], 16;" \
                 :: "r"(dst), "l"(src) : "memory")
#define CP_COMMIT() asm volatile("cp.async.commit_group;" ::: "memory")
#define CP_WAIT1()  asm volatile("cp.async.wait_group 1;"  ::: "memory")

__device__ __forceinline__ void ldsm_x4(uint32_t& r0, uint32_t& r1,
                                        uint32_t& r2, uint32_t& r3,
                                        uint32_t addr) {
    asm volatile("ldmatrix.sync.aligned.m8n8.x4.shared.b16 {%0,%1,%2,%3}, [%4];"
                 : "=r"(r0), "=r"(r1), "=r"(r2), "=r"(r3) : "r"(addr));
}

__device__ __forceinline__ void mma16816(float* d, const uint32_t* a,
                                         const uint32_t* b) {
    asm volatile("mma.sync.aligned.m16n8k16.row.col.f32.f16.f16.f32 "
                 "{%0,%1,%2,%3}, {%4,%5,%6,%7}, {%8,%9}, {%0,%1,%2,%3};"
                 : "+f"(d[0]), "+f"(d[1]), "+f"(d[2]), "+f"(d[3])
                 : "r"(a[0]), "r"(a[1]), "r"(a[2]), "r"(a[3]),
                   "r"(b[0]), "r"(b[1]));
}

// ---------------- scratch (device globals, no allocs) ----------------
__device__ float g_Wg_eff[EE * SD];
__device__ float g_bg_eff[SD];
__device__ float g_bout_eff[EE];
__device__ float g_gate[MM * SD];
__device__ float g_si[MM * SD];
__device__ float g_states[MM * SD];
__device__ __half g_XHi[(size_t)MM * EE];      // x fp16 (written by gate_si)
__device__ __half g_WinHi[(size_t)EE * EE];    // 32*W_in top square, hi (rows)
__device__ __half g_WinLo[(size_t)EE * EE];
__device__ __half g_WoutHi[(size_t)EE * EE];   // 32*W_out top, transposed
__device__ __half g_WoutLo[(size_t)EE * EE];
__device__ __half g_BweffH[(size_t)EE * EE];   // Weff^T fp16 (written by x3 gemm)

// ---------------- precompute: warp per output, coalesced K ----------------
__global__ void precompute_kernel(const float* __restrict__ W_in,
                                  const float* __restrict__ W_g,
                                  const float* __restrict__ b_g,
                                  const float* __restrict__ b_in,
                                  const float* __restrict__ W_out,
                                  const float* __restrict__ b_out,
                                  float* __restrict__ Wg_eff,
                                  float* __restrict__ bg_eff,
                                  float* __restrict__ bout_eff)
{
    const int w    = (blockIdx.x * blockDim.x + threadIdx.x) >> 5;
    const int lane = threadIdx.x & 31;
    float s = 0.f;
    if (w < EE * SD) {
        int e = w >> 3, d = w & 7;
        const float* wr = W_in + (size_t)e * LDIN;
        for (int c = lane; c < LDIN; c += 32)
            s = fmaf(wr[c], W_g[c * SD + d], s);
        #pragma unroll
        for (int o = 16; o; o >>= 1) s += __shfl_xor_sync(0xffffffffu, s, o);
        if (lane == 0) Wg_eff[w] = s;
    } else if (w < EE * SD + SD) {
        int d = w - EE * SD;
        for (int c = lane; c < LDIN; c += 32)
            s = fmaf(b_in[c], W_g[c * SD + d], s);
        #pragma unroll
        for (int o = 16; o; o >>= 1) s += __shfl_xor_sync(0xffffffffu, s, o);
        if (lane == 0) bg_eff[d] = s + b_g[d];
    } else if (w < EE * SD + SD + EE) {
        int n = w - (EE * SD + SD);
        for (int c = lane; c < EE; c += 32)
            s = fmaf(b_in[c], W_out[(size_t)c * EE + n], s);
        #pragma unroll
        for (int o = 16; o; o >>= 1) s += __shfl_xor_sync(0xffffffffu, s, o);
        if (lane == 0) bout_eff[n] = s + b_out[n];
    }
}

// ------- fused decompose: W_in rows (blocks 0..1023) + W_out^T (1024..2047) --
__global__ void fused_decompose_kernel(const float* __restrict__ W_in,
                                       const float* __restrict__ W_out,
                                       __half* __restrict__ WinHi,
                                       __half* __restrict__ WinLo,
                                       __half* __restrict__ WoutHi,
                                       __half* __restrict__ WoutLo)
{
    const int tid = threadIdx.x;
    if (blockIdx.x < 1024) {
        int r = blockIdx.x;
        int c4 = tid * 4;
        float4 v = *(const float4*)(W_in + (size_t)r * LDIN + c4);
        struct alignas(8) H4 { __half h[4]; };
        H4 H, L;
        float vv[4] = {v.x, v.y, v.z, v.w};
        #pragma unroll
        for (int i = 0; i < 4; i++) {
            float sv = vv[i] * 32.0f;
            __half h = __float2half(sv);
            H.h[i] = h;
            L.h[i] = __float2half(sv - __half2float(h));
        }
        *(H4*)(WinHi + (size_t)r * EE + c4) = H;
        *(H4*)(WinLo + (size_t)r * EE + c4) = L;
    } else {
        __shared__ float tile[32][33];
        int b = blockIdx.x - 1024;
        int e0 = (b & 31) * 32, n0 = (b >> 5) * 32;
        int tx = tid & 31, ty = tid >> 5;       // 32 x 8
        #pragma unroll
        for (int i = 0; i < 4; i++)
            tile[ty + i * 8][tx] = W_out[(size_t)(e0 + ty + i * 8) * 1024 + n0 + tx];
        __syncthreads();
        #pragma unroll
        for (int i = 0; i < 4; i++) {
            int n = n0 + ty + i * 8;
            float v = tile[tx][ty + i * 8] * 32.0f;
            __half h = __float2half(v);
            WoutHi[(size_t)n * EE + e0 + tx] = h;
            WoutLo[(size_t)n * EE + e0 + tx] = __float2half(v - __half2float(h));
        }
    }
}

// ================= 3-term fp16 GEMM -> fp16 output (Weff^T precompute) =====
__global__ void __launch_bounds__(256, 2)
gemm_f16x3_kernel(const __half* __restrict__ Ahi,
                  const __half* __restrict__ Alo,
                  const __half* __restrict__ Bhi,
                  const __half* __restrict__ Blo,
                  __half* __restrict__ C, float osc)
{
    constexpr uint32_t STAGE = 65536u;
    extern __shared__ char smem[];
    const uint32_t sb = smem_to_u32(smem);
    const int tid  = threadIdx.x;
    const int lane = tid & 31;
    const int wid  = tid >> 5;
    const int wm   = wid >> 2;
    const int wn   = wid & 3;
    const int n0   = blockIdx.x * 128;
    const int m0   = blockIdx.y * 128;

    float acc[4][4][4];
    #pragma unroll
    for (int mi = 0; mi < 4; mi++)
        #pragma unroll
        for (int ni = 0; ni < 4; ni++)
            #pragma unroll
            for (int e = 0; e < 4; e++) acc[mi][ni][e] = 0.f;

    const int row0 = tid >> 3;
    const int seg  = tid & 7;

    auto prefetch = [&](int buf, int kb) {
        const uint32_t st = sb + (uint32_t)buf * STAGE;
        #pragma unroll
        for (int i = 0; i < 4; i++) {
            int row = row0 + i * 32;
            uint32_t sw = (uint32_t)row * 128u + (uint32_t)((seg ^ (row & 7)) * 16);
            CP_ASYNC16(st + sw,          Ahi + (size_t)(m0 + row) * EE + kb + seg * 8);
            CP_ASYNC16(st + 16384u + sw, Bhi + (size_t)(n0 + row) * EE + kb + seg * 8);
            CP_ASYNC16(st + 32768u + sw, Blo + (size_t)(n0 + row) * EE + kb + seg * 8);
            CP_ASYNC16(st + 49152u + sw, Alo + (size_t)(m0 + row) * EE + kb + seg * 8);
        }
    };

    prefetch(0, 0);
    CP_COMMIT();

    const int rA  = ((lane >> 3) & 1) * 8 + (lane & 7);
    const int kA8 = lane >> 4;
    const int rB  = (lane >> 4) * 8 + (lane & 7);
    const int kB8 = (lane >> 3) & 1;

    for (int it = 0; it < NITER; it++) {
        if (it + 1 < NITER) prefetch((it + 1) & 1, (it + 1) * 64);
        CP_COMMIT();
        CP_WAIT1();
        __syncthreads();

        const uint32_t aB = sb + (uint32_t)(it & 1) * STAGE;

        #pragma unroll
        for (int ks = 0; ks < 4; ks++) {
            uint32_t af[4][4], afl[4][4], bh[4][2], bl[4][2];
            #pragma unroll
            for (int mi = 0; mi < 4; mi++) {
                int row = wm * 64 + mi * 16 + rA;
                int sh  = ks * 2 + kA8;
                uint32_t roff = (uint32_t)row * 128u + (uint32_t)((sh ^ (row & 7)) * 16);
                ldsm_x4(af[mi][0], af[mi][1], af[mi][2], af[mi][3], aB + roff);
                ldsm_x4(afl[mi][0], afl[mi][1], afl[mi][2], afl[mi][3],
                        aB + 49152u + roff);
            }
            #pragma unroll
            for (int np = 0; np < 2; np++) {
                int row = wn * 32 + np * 16 + rB;
                int sh  = ks * 2 + kB8;
                uint32_t roff = (uint32_t)row * 128u + (uint32_t)((sh ^ (row & 7)) * 16);
                uint32_t r0, r1, r2, r3;
                ldsm_x4(r0, r1, r2, r3, aB + 16384u + roff);
                bh[np * 2][0] = r0;     bh[np * 2][1] = r1;
                bh[np * 2 + 1][0] = r2; bh[np * 2 + 1][1] = r3;
                ldsm_x4(r0, r1, r2, r3, aB + 32768u + roff);
                bl[np * 2][0] = r0;     bl[np * 2][1] = r1;
                bl[np * 2 + 1][0] = r2; bl[np * 2 + 1][1] = r3;
            }
            #pragma unroll
            for (int mi = 0; mi < 4; mi++)
                #pragma unroll
                for (int ni = 0; ni < 4; ni++) {
                    mma16816(acc[mi][ni], af[mi], bh[ni]);
                    mma16816(acc[mi][ni], af[mi], bl[ni]);
                    mma16816(acc[mi][ni], afl[mi], bh[ni]);
                }
        }
        __syncthreads();
    }

    const int lr  = lane >> 2;
    const int lc2 = (lane & 3) * 2;
    #pragma unroll
    for (int mi = 0; mi < 4; mi++) {
        int r0l = wm * 64 + mi * 16 + lr;
        int r1l = r0l + 8;
        #pragma unroll
        for (int ni = 0; ni < 4; ni++) {
            int cg = wn * 32 + ni * 8 + lc2;
            float* d = acc[mi][ni];
            __half2 o0 = { __float2half(d[0] * osc), __float2half(d[1] * osc) };
            __half2 o1 = { __float2half(d[2] * osc), __float2half(d[3] * osc) };
            *(__half2*)(C + (size_t)(m0 + r0l) * 1024 + n0 + cg) = o0;
            *(__half2*)(C + (size_t)(m0 + r1l) * 1024 + n0 + cg) = o1;
        }
    }
}

// ================= main 1-term fp16 GEMM (proven R8 2-stage config) ========
__global__ void __launch_bounds__(256, 2)
gemm_main_kernel(const __half* __restrict__ A,
                 const __half* __restrict__ Bm,
                 float* __restrict__ C,
                 const float* __restrict__ bias,
                 const float* __restrict__ Srank,
                 const float* __restrict__ Wbot)
{
    constexpr uint32_t STAGE = 32768u;
    extern __shared__ char smem[];
    const uint32_t sb = smem_to_u32(smem);
    const int tid  = threadIdx.x;
    const int lane = tid & 31;
    const int wid  = tid >> 5;
    const int wm   = wid >> 2;
    const int wn   = wid & 3;
    const int n0   = blockIdx.x * 128;
    const int m0   = blockIdx.y * 128;

    float acc[4][4][4];
    #pragma unroll
    for (int mi = 0; mi < 4; mi++)
        #pragma unroll
        for (int ni = 0; ni < 4; ni++)
            #pragma unroll
            for (int e = 0; e < 4; e++) acc[mi][ni][e] = 0.f;

    const int row0 = tid >> 3;
    const int seg  = tid & 7;

    auto prefetch = [&](int buf, int kb) {
        const uint32_t st = sb + (uint32_t)buf * STAGE;
        #pragma unroll
        for (int i = 0; i < 4; i++) {
            int row = row0 + i * 32;
            uint32_t sw = (uint32_t)row * 128u + (uint32_t)((seg ^ (row & 7)) * 16);
            CP_ASYNC16(st + sw,          A  + (size_t)(m0 + row) * EE + kb + seg * 8);
            CP_ASYNC16(st + 16384u + sw, Bm + (size_t)(n0 + row) * EE + kb + seg * 8);
        }
    };

    prefetch(0, 0);
    CP_COMMIT();

    const int rA  = ((lane >> 3) & 1) * 8 + (lane & 7);
    const int kA8 = lane >> 4;
    const int rB  = (lane >> 4) * 8 + (lane & 7);
    const int kB8 = (lane >> 3) & 1;

    for (int it = 0; it < NITER; it++) {
        if (it + 1 < NITER) prefetch((it + 1) & 1, (it + 1) * 64);
        CP_COMMIT();
        CP_WAIT1();
        __syncthreads();

        const uint32_t aB = sb + (uint32_t)(it & 1) * STAGE;
        const uint32_t bB = aB + 16384u;

        #pragma unroll
        for (int ks = 0; ks < 4; ks++) {
            uint32_t af[4][4], bf[4][2];
            #pragma unroll
            for (int mi = 0; mi < 4; mi++) {
                int row = wm * 64 + mi * 16 + rA;
                int sh  = ks * 2 + kA8;
                ldsm_x4(af[mi][0], af[mi][1], af[mi][2], af[mi][3],
                        aB + (uint32_t)row * 128u + (uint32_t)((sh ^ (row & 7)) * 16));
            }
            #pragma unroll
            for (int np = 0; np < 2; np++) {
                int row = wn * 32 + np * 16 + rB;
                int sh  = ks * 2 + kB8;
                uint32_t r0, r1, r2, r3;
                ldsm_x4(r0, r1, r2, r3,
                        bB + (uint32_t)row * 128u + (uint32_t)((sh ^ (row & 7)) * 16));
                bf[np * 2][0] = r0;     bf[np * 2][1] = r1;
                bf[np * 2 + 1][0] = r2; bf[np * 2 + 1][1] = r3;
            }
            #pragma unroll
            for (int mi = 0; mi < 4; mi++)
                #pragma unroll
                for (int ni = 0; ni < 4; ni++)
                    mma16816(acc[mi][ni], af[mi], bf[ni]);
        }
        __syncthreads();
    }

    // ---------------- epilogue ----------------
    float* const sBias = (float*)smem;                 // 128 f
    float* const sSt   = (float*)(smem + 512);         // 128 x 8
    float* const sWb   = (float*)(smem + 512 + 4096);  // 8 x 128
    if (tid < 128) sBias[tid] = bias[n0 + tid];
    ((float4*)sSt)[tid] = ((const float4*)(Srank + (size_t)m0 * SD))[tid];
    for (int i = tid; i < 1024; i += 256) {
        int d8 = i >> 7, nl = i & 127;
        sWb[d8 * 128 + nl] = Wbot[(size_t)d8 * 1024 + n0 + nl];
    }
    __syncthreads();

    const int lr  = lane >> 2;
    const int lc2 = (lane & 3) * 2;
    #pragma unroll
    for (int mi = 0; mi < 4; mi++) {
        int r0l = wm * 64 + mi * 16 + lr;
        int r1l = r0l + 8;
        float st0[SD], st1[SD];
        #pragma unroll
        for (int d = 0; d < SD; d++) {
            st0[d] = sSt[r0l * SD + d];
            st1[d] = sSt[r1l * SD + d];
        }
        #pragma unroll
        for (int ni = 0; ni < 4; ni++) {
            int cg = wn * 32 + ni * 8 + lc2;
            float* d = acc[mi][ni];
            float s00 = sBias[cg], s01 = sBias[cg + 1];
            float s10 = s00, s11 = s01;
            #pragma unroll
            for (int dd = 0; dd < SD; dd++) {
                float w0 = sWb[dd * 128 + cg], w1 = sWb[dd * 128 + cg + 1];
                s00 = fmaf(st0[dd], w0, s00); s01 = fmaf(st0[dd], w1, s01);
                s10 = fmaf(st1[dd], w0, s10); s11 = fmaf(st1[dd], w1, s11);
            }
            float2 o0 = { d[0] + s00, d[1] + s01 };
            float2 o1 = { d[2] + s10, d[3] + s11 };
            *(float2*)(C + (size_t)(m0 + r0l) * 1024 + n0 + cg) = o0;
            *(float2*)(C + (size_t)(m0 + r1l) * 1024 + n0 + cg) = o1;
        }
    }
}

// ---------------- gate_si: vectorized, weights staged once per block -------
// Block: 256 threads, 64 rows; weights [16][1024] in 64KB dynamic smem.
// Each warp: 2 rows per pass, 4 passes. float4 x-loads, half4 xh-stores.
__global__ void __launch_bounds__(256, 3)
gate_si_kernel(const float* __restrict__ x,
               const float* __restrict__ Wg_eff,
               const float* __restrict__ W_in,
               const float* __restrict__ bg_eff,
               const float* __restrict__ b_in,
               float* __restrict__ gate,
               float* __restrict__ si,
               __half* __restrict__ xh)
{
    extern __shared__ float4 sW4[];          // [16][256] float4 = 64KB
    const int tid  = threadIdx.x;
    const int lane = tid & 31;
    const int warp = tid >> 5;

    // stage weights once: d<8 -> Wg_eff col d; d>=8 -> W_in col 1024+(d-8)
    for (int i = tid; i < 16 * 256; i += 256) {
        int d = i >> 8, e4 = i & 255;
        int e = e4 * 4;
        float4 w;
        if (d < 8) {
            w.x = Wg_eff[(e + 0) * SD + d];
            w.y = Wg_eff[(e + 1) * SD + d];
            w.z = Wg_eff[(e + 2) * SD + d];
            w.w = Wg_eff[(e + 3) * SD + d];
        } else {
            int c = EE + (d - 8);
            w.x = W_in[(size_t)(e + 0) * LDIN + c];
            w.y = W_in[(size_t)(e + 1) * LDIN + c];
            w.z = W_in[(size_t)(e + 2) * LDIN + c];
            w.w = W_in[(size_t)(e + 3) * LDIN + c];
        }
        sW4[i] = w;
    }
    __syncthreads();

    struct alignas(8) H4 { __half2 a, b; };
    const int mbase = blockIdx.x * 64;

    for (int pass = 0; pass < 4; pass++) {
        const int r = mbase + pass * 16 + warp * 2;
        const float* xr0 = x + (size_t)r * EE;
        const float* xr1 = xr0 + EE;
        __half* xh0 = xh + (size_t)r * EE;
        __half* xh1 = xh0 + EE;

        float acc0[16], acc1[16];
        #pragma unroll
        for (int d = 0; d < 16; d++) { acc0[d] = 0.f; acc1[d] = 0.f; }

        #pragma unroll 2
        for (int it = 0; it < 8; it++) {
            int e4 = it * 32 + lane;
            float4 x0 = *(const float4*)(xr0 + e4 * 4);
            float4 x1 = *(const float4*)(xr1 + e4 * 4);
            H4 h0, h1;
            h0.a = __floats2half2_rn(x0.x, x0.y);
            h0.b = __floats2half2_rn(x0.z, x0.w);
            h1.a = __floats2half2_rn(x1.x, x1.y);
            h1.b = __floats2half2_rn(x1.z, x1.w);
            *(H4*)(xh0 + e4 * 4) = h0;
            *(H4*)(xh1 + e4 * 4) = h1;
            #pragma unroll
            for (int d = 0; d < 16; d++) {
                float4 w = sW4[d * 256 + e4];
                acc0[d] = fmaf(x0.x, w.x, fmaf(x0.y, w.y,
                          fmaf(x0.z, w.z, fmaf(x0.w, w.w, acc0[d]))));
                acc1[d] = fmaf(x1.x, w.x, fmaf(x1.y, w.y,
                          fmaf(x1.z, w.z, fmaf(x1.w, w.w, acc1[d]))));
            }
        }

        float sel0 = 0.f, sel1 = 0.f;
        #pragma unroll
        for (int d = 0; d < 16; d++) {
            float v0 = acc0[d], v1 = acc1[d];
            #pragma unroll
            for (int o = 16; o; o >>= 1) {
                v0 += __shfl_xor_sync(0xffffffffu, v0, o);
                v1 += __shfl_xor_sync(0xffffffffu, v1, o);
            }
            if (lane == d) { sel0 = v0; sel1 = v1; }
        }
        if (lane < 8) {
            float l0 = sel0 + bg_eff[lane];
            float l1 = sel1 + bg_eff[lane];
            gate[(size_t)r * SD + lane]       = 1.0f / (1.0f + expf(-l0));
            gate[(size_t)(r + 1) * SD + lane] = 1.0f / (1.0f + expf(-l1));
        } else if (lane < 16) {
            int d = lane - 8;
            float bi = b_in[EE + d];
            si[(size_t)r * SD + d]       = sel0 + bi;
            si[(size_t)(r + 1) * SD + d] = sel1 + bi;
        }
    }
}

// ---------------- parallel linear-recurrence scan ----------------
__global__ __launch_bounds__(128)
void scan_par_kernel(const float* __restrict__ gate,
                     const float* __restrict__ si,
                     float* __restrict__ states,
                     float* __restrict__ final_state)
{
    const int chain = blockIdx.x;            // 0..63
    const int b = chain >> 3, d = chain & 7;
    const int t = threadIdx.x;               // 0..127
    const int lane = t & 31, warp = t >> 5;
    const float* gp = gate + (size_t)b * SS * SD + d;
    const float* sp = si   + (size_t)b * SS * SD + d;
    float*       op = states + (size_t)b * SS * SD + d;
    const int s0 = t * 32;

    float g[32], cc[32];
    float G = 1.f, C = 0.f;
    #pragma unroll
    for (int u = 0; u < 32; u++) {
        float gv = gp[(s0 + u) * SD];
        float sv = sp[(s0 + u) * SD];
        float cv = sv - gv * sv;
        g[u] = gv; cc[u] = cv;
        C = fmaf(gv, C, cv);
        G = gv * G;
    }
    #pragma unroll
    for (int off = 1; off < 32; off <<= 1) {
        float pG = __shfl_up_sync(0xffffffffu, G, off);
        float pC = __shfl_up_sync(0xffffffffu, C, off);
        if (lane >= off) { C = fmaf(G, pC, C); G *= pG; }
    }
    __shared__ float wG[4], wC[4];
    if (lane == 31) { wG[warp] = G; wC[warp] = C; }
    __syncthreads();
    float preC = 0.f;
    for (int w = 0; w < warp; w++) { preC = fmaf(wG[w], preC, wC[w]); }
    float eG = __shfl_up_sync(0xffffffffu, G, 1);
    float eC = __shfl_up_sync(0xffffffffu, C, 1);
    if (lane == 0) { eG = 1.f; eC = 0.f; }
    float s = fmaf(eG, preC, eC);
    #pragma unroll
    for (int u = 0; u < 32; u++) {
        s = fmaf(g[u], s, cc[u]);
        op[(s0 + u) * SD] = s;
    }
    if (t == 127) final_state[b * SD + d] = s;
}

// ---------------- launch ----------------
extern "C" void kernel_launch(void* const* d_in, const int* in_sizes, int n_in,
                              void* d_out, int out_size)
{
    const float* x     = (const float*)d_in[0];
    const float* W_in  = (const float*)d_in[1];
    const float* b_in  = (const float*)d_in[2];
    const float* W_g   = (const float*)d_in[3];
    const float* b_g   = (const float*)d_in[4];
    const float* W_out = (const float*)d_in[5];
    const float* b_out = (const float*)d_in[6];
    float* out = (float*)d_out;

    float *Wg_eff, *bg_eff, *bout_eff, *gate, *si, *states;
    __half *XHi, *WinHi, *WinLo, *WoutHi, *WoutLo, *BweffH;
    cudaGetSymbolAddress((void**)&Wg_eff,   g_Wg_eff);
    cudaGetSymbolAddress((void**)&bg_eff,   g_bg_eff);
    cudaGetSymbolAddress((void**)&bout_eff, g_bout_eff);
    cudaGetSymbolAddress((void**)&gate,     g_gate);
    cudaGetSymbolAddress((void**)&si,       g_si);
    cudaGetSymbolAddress((void**)&states,   g_states);
    cudaGetSymbolAddress((void**)&XHi,      g_XHi);
    cudaGetSymbolAddress((void**)&WinHi,    g_WinHi);
    cudaGetSymbolAddress((void**)&WinLo,    g_WinLo);
    cudaGetSymbolAddress((void**)&WoutHi,   g_WoutHi);
    cudaGetSymbolAddress((void**)&WoutLo,   g_WoutLo);
    cudaGetSymbolAddress((void**)&BweffH,   g_BweffH);

    cudaFuncSetAttribute(gemm_f16x3_kernel,
                         cudaFuncAttributeMaxDynamicSharedMemorySize, 131072);
    cudaFuncSetAttribute(gemm_main_kernel,
                         cudaFuncAttributeMaxDynamicSharedMemorySize, 65536);
    cudaFuncSetAttribute(gate_si_kernel,
                         cudaFuncAttributeMaxDynamicSharedMemorySize, 65536);

    // 0) small folded weights (warp per output)
    int nwarps = EE * SD + SD + EE;                 // 9224
    precompute_kernel<<<(nwarps * 32 + 255) / 256, 256>>>(
        W_in, W_g, b_g, b_in, W_out, b_out, Wg_eff, bg_eff, bout_eff);

    // 1) fused decompose: 32*W_in rows + 32*W_out transposed (hi/lo)
    fused_decompose_kernel<<<2048, 256>>>(W_in, W_out, WinHi, WinLo, WoutHi, WoutLo);

    // 2) BweffH = fp16(Weff^T) = (W_out^T)@(W_in rows), 3-term; /1024 undoes 32*32
    gemm_f16x3_kernel<<<dim3(8, 8), 256, 131072>>>(
        WoutHi, WoutLo, WinHi, WinLo, BweffH, 1.0f / 1024.0f);

    // 3) gate + state_in + fused x->fp16 cast (vectorized, 64 rows/block)
    gate_si_kernel<<<MM / 64, 256, 65536>>>(x, Wg_eff, W_in, bg_eff, b_in,
                                            gate, si, XHi);

    // 4) parallel scan (also writes final_state at tail of output)
    scan_par_kernel<<<64, 128>>>(gate, si, states, out + (size_t)MM * EE);

    // 5) out = x @ Weff + states @ W_out[E:, :] + bout_eff   (main; 2-stage)
    gemm_main_kernel<<<dim3(8, MM / 128), 256, 65536>>>(
        XHi, BweffH, out, bout_eff, states, W_out + (size_t)EE * EE);
}

// round 12
// speedup vs baseline: 1.3782x; 1.0803x over previous
#include <cuda_runtime.h>
#include <cuda_fp16.h>
#include <math.h>
#include <stdint.h>

// ---------------- problem constants ----------------
#define BB 8
#define SS 4096
#define EE 1024
#define SD 8
#define MM (BB*SS)          // 32768
#define LDIN 1032           // E + SD
#define NITER 16            // K=1024 / 64

// ================= portable PTX helpers (sm_80+) =================
__device__ __forceinline__ uint32_t smem_to_u32(const void* smem_ptr) {
    uint32_t addr;
    asm("{ .reg .u64 tmp; cvta.to.shared.u64 tmp, %1; cvt.u32.u64 %0, tmp; }"
        : "=r"(addr) : "l"(smem_ptr));
    return addr;
}

#define CP_ASYNC16(dst, src) \
    asm volatile("cp.async.cg.shared.global [%0], [%1], 16;" \
                 :: "r"(dst), "l"(src) : "memory")
#define CP_COMMIT() asm volatile("cp.async.commit_group;" ::: "memory")
#define CP_WAIT1()  asm volatile("cp.async.wait_group 1;"  ::: "memory")

__device__ __forceinline__ void ldsm_x4(uint32_t& r0, uint32_t& r1,
                                        uint32_t& r2, uint32_t& r3,
                                        uint32_t addr) {
    asm volatile("ldmatrix.sync.aligned.m8n8.x4.shared.b16 {%0,%1,%2,%3}, [%4];"
                 : "=r"(r0), "=r"(r1), "=r"(r2), "=r"(r3) : "r"(addr));
}

__device__ __forceinline__ void mma16816(float* d, const uint32_t* a,
                                         const uint32_t* b) {
    asm volatile("mma.sync.aligned.m16n8k16.row.col.f32.f16.f16.f32 "
                 "{%0,%1,%2,%3}, {%4,%5,%6,%7}, {%8,%9}, {%0,%1,%2,%3};"
                 : "+f"(d[0]), "+f"(d[1]), "+f"(d[2]), "+f"(d[3])
                 : "r"(a[0]), "r"(a[1]), "r"(a[2]), "r"(a[3]),
                   "r"(b[0]), "r"(b[1]));
}

// ---------------- scratch (device globals, no allocs) ----------------
__device__ float g_Wg_eff[EE * SD];
__device__ float g_bg_eff[SD];
__device__ float g_bout_eff[EE];
__device__ float g_gate[MM * SD];
__device__ float g_si[MM * SD];
__device__ float g_states[MM * SD];
__device__ __half g_XHi[(size_t)MM * EE];      // x fp16 (written by gate_si_tc)
__device__ __half g_WinHi[(size_t)EE * EE];    // 32*W_in top square, hi (rows)
__device__ __half g_WinLo[(size_t)EE * EE];
__device__ __half g_WoutHi[(size_t)EE * EE];   // 32*W_out top, transposed
__device__ __half g_WoutLo[(size_t)EE * EE];
__device__ __half g_BweffH[(size_t)EE * EE];   // Weff^T fp16 (written by x3 gemm)
__device__ __half g_Wcomb[16 * EE];            // [d][e]: gate cols 0-7, si cols 8-15

// ---------------- precompute: warp per output, coalesced K ----------------
__global__ void precompute_kernel(const float* __restrict__ W_in,
                                  const float* __restrict__ W_g,
                                  const float* __restrict__ b_g,
                                  const float* __restrict__ b_in,
                                  const float* __restrict__ W_out,
                                  const float* __restrict__ b_out,
                                  float* __restrict__ Wg_eff,
                                  float* __restrict__ bg_eff,
                                  float* __restrict__ bout_eff)
{
    const int w    = (blockIdx.x * blockDim.x + threadIdx.x) >> 5;
    const int lane = threadIdx.x & 31;
    float s = 0.f;
    if (w < EE * SD) {
        int e = w >> 3, d = w & 7;
        const float* wr = W_in + (size_t)e * LDIN;
        for (int c = lane; c < LDIN; c += 32)
            s = fmaf(wr[c], W_g[c * SD + d], s);
        #pragma unroll
        for (int o = 16; o; o >>= 1) s += __shfl_xor_sync(0xffffffffu, s, o);
        if (lane == 0) Wg_eff[w] = s;
    } else if (w < EE * SD + SD) {
        int d = w - EE * SD;
        for (int c = lane; c < LDIN; c += 32)
            s = fmaf(b_in[c], W_g[c * SD + d], s);
        #pragma unroll
        for (int o = 16; o; o >>= 1) s += __shfl_xor_sync(0xffffffffu, s, o);
        if (lane == 0) bg_eff[d] = s + b_g[d];
    } else if (w < EE * SD + SD + EE) {
        int n = w - (EE * SD + SD);
        for (int c = lane; c < EE; c += 32)
            s = fmaf(b_in[c], W_out[(size_t)c * EE + n], s);
        #pragma unroll
        for (int o = 16; o; o >>= 1) s += __shfl_xor_sync(0xffffffffu, s, o);
        if (lane == 0) bout_eff[n] = s + b_out[n];
    }
}

// -- fused decompose: W_in rows (0..1023) + W_out^T (1024..2047) + Wcomb (2048..2111)
__global__ void fused_decompose_kernel(const float* __restrict__ W_in,
                                       const float* __restrict__ W_out,
                                       const float* __restrict__ Wg_eff,
                                       __half* __restrict__ WinHi,
                                       __half* __restrict__ WinLo,
                                       __half* __restrict__ WoutHi,
                                       __half* __restrict__ WoutLo,
                                       __half* __restrict__ Wcomb)
{
    const int tid = threadIdx.x;
    if (blockIdx.x < 1024) {
        int r = blockIdx.x;
        int c4 = tid * 4;
        float4 v = *(const float4*)(W_in + (size_t)r * LDIN + c4);
        struct alignas(8) H4 { __half h[4]; };
        H4 H, L;
        float vv[4] = {v.x, v.y, v.z, v.w};
        #pragma unroll
        for (int i = 0; i < 4; i++) {
            float sv = vv[i] * 32.0f;
            __half h = __float2half(sv);
            H.h[i] = h;
            L.h[i] = __float2half(sv - __half2float(h));
        }
        *(H4*)(WinHi + (size_t)r * EE + c4) = H;
        *(H4*)(WinLo + (size_t)r * EE + c4) = L;
    } else if (blockIdx.x < 2048) {
        __shared__ float tile[32][33];
        int b = blockIdx.x - 1024;
        int e0 = (b & 31) * 32, n0 = (b >> 5) * 32;
        int tx = tid & 31, ty = tid >> 5;       // 32 x 8
        #pragma unroll
        for (int i = 0; i < 4; i++)
            tile[ty + i * 8][tx] = W_out[(size_t)(e0 + ty + i * 8) * 1024 + n0 + tx];
        __syncthreads();
        #pragma unroll
        for (int i = 0; i < 4; i++) {
            int n = n0 + ty + i * 8;
            float v = tile[tx][ty + i * 8] * 32.0f;
            __half h = __float2half(v);
            WoutHi[(size_t)n * EE + e0 + tx] = h;
            WoutLo[(size_t)n * EE + e0 + tx] = __float2half(v - __half2float(h));
        }
    } else {
        int idx = (blockIdx.x - 2048) * 256 + tid;   // 0..16383
        int d = idx >> 10, e = idx & 1023;
        float v = (d < 8) ? Wg_eff[e * SD + d]
                          : W_in[(size_t)e * LDIN + EE + (d - 8)];
        Wcomb[idx] = __float2half(v);
    }
}

// ================= 3-term fp16 GEMM -> fp16 output (Weff^T precompute) =====
__global__ void __launch_bounds__(256, 2)
gemm_f16x3_kernel(const __half* __restrict__ Ahi,
                  const __half* __restrict__ Alo,
                  const __half* __restrict__ Bhi,
                  const __half* __restrict__ Blo,
                  __half* __restrict__ C, float osc)
{
    constexpr uint32_t STAGE = 65536u;
    extern __shared__ char smem[];
    const uint32_t sb = smem_to_u32(smem);
    const int tid  = threadIdx.x;
    const int lane = tid & 31;
    const int wid  = tid >> 5;
    const int wm   = wid >> 2;
    const int wn   = wid & 3;
    const int n0   = blockIdx.x * 128;
    const int m0   = blockIdx.y * 128;

    float acc[4][4][4];
    #pragma unroll
    for (int mi = 0; mi < 4; mi++)
        #pragma unroll
        for (int ni = 0; ni < 4; ni++)
            #pragma unroll
            for (int e = 0; e < 4; e++) acc[mi][ni][e] = 0.f;

    const int row0 = tid >> 3;
    const int seg  = tid & 7;

    auto prefetch = [&](int buf, int kb) {
        const uint32_t st = sb + (uint32_t)buf * STAGE;
        #pragma unroll
        for (int i = 0; i < 4; i++) {
            int row = row0 + i * 32;
            uint32_t sw = (uint32_t)row * 128u + (uint32_t)((seg ^ (row & 7)) * 16);
            CP_ASYNC16(st + sw,          Ahi + (size_t)(m0 + row) * EE + kb + seg * 8);
            CP_ASYNC16(st + 16384u + sw, Bhi + (size_t)(n0 + row) * EE + kb + seg * 8);
            CP_ASYNC16(st + 32768u + sw, Blo + (size_t)(n0 + row) * EE + kb + seg * 8);
            CP_ASYNC16(st + 49152u + sw, Alo + (size_t)(m0 + row) * EE + kb + seg * 8);
        }
    };

    prefetch(0, 0);
    CP_COMMIT();

    const int rA  = ((lane >> 3) & 1) * 8 + (lane & 7);
    const int kA8 = lane >> 4;
    const int rB  = (lane >> 4) * 8 + (lane & 7);
    const int kB8 = (lane >> 3) & 1;

    for (int it = 0; it < NITER; it++) {
        if (it + 1 < NITER) prefetch((it + 1) & 1, (it + 1) * 64);
        CP_COMMIT();
        CP_WAIT1();
        __syncthreads();

        const uint32_t aB = sb + (uint32_t)(it & 1) * STAGE;

        #pragma unroll
        for (int ks = 0; ks < 4; ks++) {
            uint32_t af[4][4], afl[4][4], bh[4][2], bl[4][2];
            #pragma unroll
            for (int mi = 0; mi < 4; mi++) {
                int row = wm * 64 + mi * 16 + rA;
                int sh  = ks * 2 + kA8;
                uint32_t roff = (uint32_t)row * 128u + (uint32_t)((sh ^ (row & 7)) * 16);
                ldsm_x4(af[mi][0], af[mi][1], af[mi][2], af[mi][3], aB + roff);
                ldsm_x4(afl[mi][0], afl[mi][1], afl[mi][2], afl[mi][3],
                        aB + 49152u + roff);
            }
            #pragma unroll
            for (int np = 0; np < 2; np++) {
                int row = wn * 32 + np * 16 + rB;
                int sh  = ks * 2 + kB8;
                uint32_t roff = (uint32_t)row * 128u + (uint32_t)((sh ^ (row & 7)) * 16);
                uint32_t r0, r1, r2, r3;
                ldsm_x4(r0, r1, r2, r3, aB + 16384u + roff);
                bh[np * 2][0] = r0;     bh[np * 2][1] = r1;
                bh[np * 2 + 1][0] = r2; bh[np * 2 + 1][1] = r3;
                ldsm_x4(r0, r1, r2, r3, aB + 32768u + roff);
                bl[np * 2][0] = r0;     bl[np * 2][1] = r1;
                bl[np * 2 + 1][0] = r2; bl[np * 2 + 1][1] = r3;
            }
            #pragma unroll
            for (int mi = 0; mi < 4; mi++)
                #pragma unroll
                for (int ni = 0; ni < 4; ni++) {
                    mma16816(acc[mi][ni], af[mi], bh[ni]);
                    mma16816(acc[mi][ni], af[mi], bl[ni]);
                    mma16816(acc[mi][ni], afl[mi], bh[ni]);
                }
        }
        __syncthreads();
    }

    const int lr  = lane >> 2;
    const int lc2 = (lane & 3) * 2;
    #pragma unroll
    for (int mi = 0; mi < 4; mi++) {
        int r0l = wm * 64 + mi * 16 + lr;
        int r1l = r0l + 8;
        #pragma unroll
        for (int ni = 0; ni < 4; ni++) {
            int cg = wn * 32 + ni * 8 + lc2;
            float* d = acc[mi][ni];
            __half2 o0 = { __float2half(d[0] * osc), __float2half(d[1] * osc) };
            __half2 o1 = { __float2half(d[2] * osc), __float2half(d[3] * osc) };
            *(__half2*)(C + (size_t)(m0 + r0l) * 1024 + n0 + cg) = o0;
            *(__half2*)(C + (size_t)(m0 + r1l) * 1024 + n0 + cg) = o1;
        }
    }
}

// ================= main 1-term fp16 GEMM (proven R8 2-stage config) ========
__global__ void __launch_bounds__(256, 2)
gemm_main_kernel(const __half* __restrict__ A,
                 const __half* __restrict__ Bm,
                 float* __restrict__ C,
                 const float* __restrict__ bias,
                 const float* __restrict__ Srank,
                 const float* __restrict__ Wbot)
{
    constexpr uint32_t STAGE = 32768u;
    extern __shared__ char smem[];
    const uint32_t sb = smem_to_u32(smem);
    const int tid  = threadIdx.x;
    const int lane = tid & 31;
    const int wid  = tid >> 5;
    const int wm   = wid >> 2;
    const int wn   = wid & 3;
    const int n0   = blockIdx.x * 128;
    const int m0   = blockIdx.y * 128;

    float acc[4][4][4];
    #pragma unroll
    for (int mi = 0; mi < 4; mi++)
        #pragma unroll
        for (int ni = 0; ni < 4; ni++)
            #pragma unroll
            for (int e = 0; e < 4; e++) acc[mi][ni][e] = 0.f;

    const int row0 = tid >> 3;
    const int seg  = tid & 7;

    auto prefetch = [&](int buf, int kb) {
        const uint32_t st = sb + (uint32_t)buf * STAGE;
        #pragma unroll
        for (int i = 0; i < 4; i++) {
            int row = row0 + i * 32;
            uint32_t sw = (uint32_t)row * 128u + (uint32_t)((seg ^ (row & 7)) * 16);
            CP_ASYNC16(st + sw,          A  + (size_t)(m0 + row) * EE + kb + seg * 8);
            CP_ASYNC16(st + 16384u + sw, Bm + (size_t)(n0 + row) * EE + kb + seg * 8);
        }
    };

    prefetch(0, 0);
    CP_COMMIT();

    const int rA  = ((lane >> 3) & 1) * 8 + (lane & 7);
    const int kA8 = lane >> 4;
    const int rB  = (lane >> 4) * 8 + (lane & 7);
    const int kB8 = (lane >> 3) & 1;

    for (int it = 0; it < NITER; it++) {
        if (it + 1 < NITER) prefetch((it + 1) & 1, (it + 1) * 64);
        CP_COMMIT();
        CP_WAIT1();
        __syncthreads();

        const uint32_t aB = sb + (uint32_t)(it & 1) * STAGE;
        const uint32_t bB = aB + 16384u;

        #pragma unroll
        for (int ks = 0; ks < 4; ks++) {
            uint32_t af[4][4], bf[4][2];
            #pragma unroll
            for (int mi = 0; mi < 4; mi++) {
                int row = wm * 64 + mi * 16 + rA;
                int sh  = ks * 2 + kA8;
                ldsm_x4(af[mi][0], af[mi][1], af[mi][2], af[mi][3],
                        aB + (uint32_t)row * 128u + (uint32_t)((sh ^ (row & 7)) * 16));
            }
            #pragma unroll
            for (int np = 0; np < 2; np++) {
                int row = wn * 32 + np * 16 + rB;
                int sh  = ks * 2 + kB8;
                uint32_t r0, r1, r2, r3;
                ldsm_x4(r0, r1, r2, r3,
                        bB + (uint32_t)row * 128u + (uint32_t)((sh ^ (row & 7)) * 16));
                bf[np * 2][0] = r0;     bf[np * 2][1] = r1;
                bf[np * 2 + 1][0] = r2; bf[np * 2 + 1][1] = r3;
            }
            #pragma unroll
            for (int mi = 0; mi < 4; mi++)
                #pragma unroll
                for (int ni = 0; ni < 4; ni++)
                    mma16816(acc[mi][ni], af[mi], bf[ni]);
        }
        __syncthreads();
    }

    // ---------------- epilogue ----------------
    float* const sBias = (float*)smem;                 // 128 f
    float* const sSt   = (float*)(smem + 512);         // 128 x 8
    float* const sWb   = (float*)(smem + 512 + 4096);  // 8 x 128
    if (tid < 128) sBias[tid] = bias[n0 + tid];
    ((float4*)sSt)[tid] = ((const float4*)(Srank + (size_t)m0 * SD))[tid];
    for (int i = tid; i < 1024; i += 256) {
        int d8 = i >> 7, nl = i & 127;
        sWb[d8 * 128 + nl] = Wbot[(size_t)d8 * 1024 + n0 + nl];
    }
    __syncthreads();

    const int lr  = lane >> 2;
    const int lc2 = (lane & 3) * 2;
    #pragma unroll
    for (int mi = 0; mi < 4; mi++) {
        int r0l = wm * 64 + mi * 16 + lr;
        int r1l = r0l + 8;
        float st0[SD], st1[SD];
        #pragma unroll
        for (int d = 0; d < SD; d++) {
            st0[d] = sSt[r0l * SD + d];
            st1[d] = sSt[r1l * SD + d];
        }
        #pragma unroll
        for (int ni = 0; ni < 4; ni++) {
            int cg = wn * 32 + ni * 8 + lc2;
            float* d = acc[mi][ni];
            float s00 = sBias[cg], s01 = sBias[cg + 1];
            float s10 = s00, s11 = s01;
            #pragma unroll
            for (int dd = 0; dd < SD; dd++) {
                float w0 = sWb[dd * 128 + cg], w1 = sWb[dd * 128 + cg + 1];
                s00 = fmaf(st0[dd], w0, s00); s01 = fmaf(st0[dd], w1, s01);
                s10 = fmaf(st1[dd], w0, s10); s11 = fmaf(st1[dd], w1, s11);
            }
            float2 o0 = { d[0] + s00, d[1] + s01 };
            float2 o1 = { d[2] + s10, d[3] + s11 };
            *(float2*)(C + (size_t)(m0 + r0l) * 1024 + n0 + cg) = o0;
            *(float2*)(C + (size_t)(m0 + r1l) * 1024 + n0 + cg) = o1;
        }
    }
}

// ============ gate_si via tensor cores + fused x->fp16 cast ============
// CTA: 128 rows, N=16 (gate 0-7 | si 8-15), K=1024 in 16 chunks of 64.
// smem: B (Wcomb swizzled) 32KB @0; A fp16 double buffer 2x16KB @32K,48K.
// Warp w handles rows w*16..w*16+15; 2 mma per k16 step.
__global__ void __launch_bounds__(256, 2)
gate_si_tc_kernel(const float* __restrict__ x,
                  const __half* __restrict__ Wcomb,
                  const float* __restrict__ bg_eff,
                  const float* __restrict__ b_in,
                  float* __restrict__ gate,
                  float* __restrict__ si,
                  __half* __restrict__ xh)
{
    extern __shared__ char smem[];
    const uint32_t sb = smem_to_u32(smem);
    const int tid  = threadIdx.x;
    const int lane = tid & 31;
    const int wid  = tid >> 5;
    const int m0   = blockIdx.x * 128;

    // stage B once: Wcomb[d][k] -> row (k/64)*16 + d, swizzled 128B rows
    for (int i = tid; i < 2048; i += 256) {
        int h8 = i * 8;
        int d = h8 >> 10, k = h8 & 1023;
        int row = (k >> 6) * 16 + d;
        int seg = (k & 63) >> 3;
        uint4 v = *(const uint4*)(Wcomb + (size_t)d * 1024 + k);
        *(uint4*)(smem + row * 128 + ((seg ^ (row & 7)) * 16)) = v;
    }

    const int arow  = tid >> 1;         // 0..127
    const int ahalf = tid & 1;          // cols 0..31 / 32..63 of chunk
    const float* xbase = x  + (size_t)(m0 + arow) * EE + ahalf * 32;
    __half*     xhbase = xh + (size_t)(m0 + arow) * EE + ahalf * 32;

    float xv[32];
    #pragma unroll
    for (int j = 0; j < 8; j++)
        *(float4*)(xv + j * 4) = *(const float4*)(xbase + j * 4);

    float acc[2][4] = {{0.f,0.f,0.f,0.f},{0.f,0.f,0.f,0.f}};

    struct alignas(16) HV { __half2 h[4]; };
    auto cvtstore = [&](int c, int buf) {
        char* abase = smem + 32768 + buf * 16384;
        __half* xhg = xhbase + c * 64;
        #pragma unroll
        for (int j = 0; j < 4; j++) {
            HV p;
            p.h[0] = __floats2half2_rn(xv[j*8+0], xv[j*8+1]);
            p.h[1] = __floats2half2_rn(xv[j*8+2], xv[j*8+3]);
            p.h[2] = __floats2half2_rn(xv[j*8+4], xv[j*8+5]);
            p.h[3] = __floats2half2_rn(xv[j*8+6], xv[j*8+7]);
            int seg = ahalf * 4 + j;
            *(HV*)(abase + arow * 128 + ((seg ^ (arow & 7)) * 16)) = p;
            *(HV*)(xhg + j * 8) = p;
        }
    };

    cvtstore(0, 0);
    __syncthreads();

    const int rA  = ((lane >> 3) & 1) * 8 + (lane & 7);
    const int kA8 = lane >> 4;
    const int rB  = (lane >> 4) * 8 + (lane & 7);
    const int kB8 = (lane >> 3) & 1;
    const int wrow = wid * 16;

    for (int c = 0; c < 16; c++) {
        if (c + 1 < 16) {
            const float* xn = xbase + (c + 1) * 64;
            #pragma unroll
            for (int j = 0; j < 8; j++)
                *(float4*)(xv + j * 4) = *(const float4*)(xn + j * 4);
        }
        const uint32_t aB = sb + 32768u + (uint32_t)(c & 1) * 16384u;
        #pragma unroll
        for (int ks = 0; ks < 4; ks++) {
            uint32_t af[4], bf[2][2];
            {
                int row = wrow + rA;
                int sh  = ks * 2 + kA8;
                ldsm_x4(af[0], af[1], af[2], af[3],
                        aB + (uint32_t)row * 128u + (uint32_t)((sh ^ (row & 7)) * 16));
            }
            {
                int row = c * 16 + rB;
                int sh  = ks * 2 + kB8;
                uint32_t r0, r1, r2, r3;
                ldsm_x4(r0, r1, r2, r3,
                        sb + (uint32_t)row * 128u + (uint32_t)((sh ^ (row & 7)) * 16));
                bf[0][0] = r0; bf[0][1] = r1;
                bf[1][0] = r2; bf[1][1] = r3;
            }
            mma16816(acc[0], af, bf[0]);
            mma16816(acc[1], af, bf[1]);
        }
        if (c + 1 < 16) cvtstore(c + 1, (c + 1) & 1);
        __syncthreads();
    }

    // epilogue: gate (cols 0-7) + si (cols 8-15)
    const int lr  = lane >> 2;
    const int lc2 = (lane & 3) * 2;
    const float bg0 = bg_eff[lc2],      bg1 = bg_eff[lc2 + 1];
    const float bi0 = b_in[EE + lc2],   bi1 = b_in[EE + lc2 + 1];
    const int r0 = m0 + wrow + lr;
    const int r1 = r0 + 8;
    float2 gg0 = { 1.0f / (1.0f + expf(-(acc[0][0] + bg0))),
                   1.0f / (1.0f + expf(-(acc[0][1] + bg1))) };
    float2 gg1 = { 1.0f / (1.0f + expf(-(acc[0][2] + bg0))),
                   1.0f / (1.0f + expf(-(acc[0][3] + bg1))) };
    *(float2*)(gate + (size_t)r0 * SD + lc2) = gg0;
    *(float2*)(gate + (size_t)r1 * SD + lc2) = gg1;
    float2 ss0 = { acc[1][0] + bi0, acc[1][1] + bi1 };
    float2 ss1 = { acc[1][2] + bi0, acc[1][3] + bi1 };
    *(float2*)(si + (size_t)r0 * SD + lc2) = ss0;
    *(float2*)(si + (size_t)r1 * SD + lc2) = ss1;
}

// ---------------- parallel linear-recurrence scan ----------------
__global__ __launch_bounds__(128)
void scan_par_kernel(const float* __restrict__ gate,
                     const float* __restrict__ si,
                     float* __restrict__ states,
                     float* __restrict__ final_state)
{
    const int chain = blockIdx.x;            // 0..63
    const int b = chain >> 3, d = chain & 7;
    const int t = threadIdx.x;               // 0..127
    const int lane = t & 31, warp = t >> 5;
    const float* gp = gate + (size_t)b * SS * SD + d;
    const float* sp = si   + (size_t)b * SS * SD + d;
    float*       op = states + (size_t)b * SS * SD + d;
    const int s0 = t * 32;

    float g[32], cc[32];
    float G = 1.f, C = 0.f;
    #pragma unroll
    for (int u = 0; u < 32; u++) {
        float gv = gp[(s0 + u) * SD];
        float sv = sp[(s0 + u) * SD];
        float cv = sv - gv * sv;
        g[u] = gv; cc[u] = cv;
        C = fmaf(gv, C, cv);
        G = gv * G;
    }
    #pragma unroll
    for (int off = 1; off < 32; off <<= 1) {
        float pG = __shfl_up_sync(0xffffffffu, G, off);
        float pC = __shfl_up_sync(0xffffffffu, C, off);
        if (lane >= off) { C = fmaf(G, pC, C); G *= pG; }
    }
    __shared__ float wG[4], wC[4];
    if (lane == 31) { wG[warp] = G; wC[warp] = C; }
    __syncthreads();
    float preC = 0.f;
    for (int w = 0; w < warp; w++) { preC = fmaf(wG[w], preC, wC[w]); }
    float eG = __shfl_up_sync(0xffffffffu, G, 1);
    float eC = __shfl_up_sync(0xffffffffu, C, 1);
    if (lane == 0) { eG = 1.f; eC = 0.f; }
    float s = fmaf(eG, preC, eC);
    #pragma unroll
    for (int u = 0; u < 32; u++) {
        s = fmaf(g[u], s, cc[u]);
        op[(s0 + u) * SD] = s;
    }
    if (t == 127) final_state[b * SD + d] = s;
}

// ---------------- launch ----------------
extern "C" void kernel_launch(void* const* d_in, const int* in_sizes, int n_in,
                              void* d_out, int out_size)
{
    const float* x     = (const float*)d_in[0];
    const float* W_in  = (const float*)d_in[1];
    const float* b_in  = (const float*)d_in[2];
    const float* W_g   = (const float*)d_in[3];
    const float* b_g   = (const float*)d_in[4];
    const float* W_out = (const float*)d_in[5];
    const float* b_out = (const float*)d_in[6];
    float* out = (float*)d_out;

    float *Wg_eff, *bg_eff, *bout_eff, *gate, *si, *states;
    __half *XHi, *WinHi, *WinLo, *WoutHi, *WoutLo, *BweffH, *Wcomb;
    cudaGetSymbolAddress((void**)&Wg_eff,   g_Wg_eff);
    cudaGetSymbolAddress((void**)&bg_eff,   g_bg_eff);
    cudaGetSymbolAddress((void**)&bout_eff, g_bout_eff);
    cudaGetSymbolAddress((void**)&gate,     g_gate);
    cudaGetSymbolAddress((void**)&si,       g_si);
    cudaGetSymbolAddress((void**)&states,   g_states);
    cudaGetSymbolAddress((void**)&XHi,      g_XHi);
    cudaGetSymbolAddress((void**)&WinHi,    g_WinHi);
    cudaGetSymbolAddress((void**)&WinLo,    g_WinLo);
    cudaGetSymbolAddress((void**)&WoutHi,   g_WoutHi);
    cudaGetSymbolAddress((void**)&WoutLo,   g_WoutLo);
    cudaGetSymbolAddress((void**)&BweffH,   g_BweffH);
    cudaGetSymbolAddress((void**)&Wcomb,    g_Wcomb);

    cudaFuncSetAttribute(gemm_f16x3_kernel,
                         cudaFuncAttributeMaxDynamicSharedMemorySize, 131072);
    cudaFuncSetAttribute(gemm_main_kernel,
                         cudaFuncAttributeMaxDynamicSharedMemorySize, 65536);
    cudaFuncSetAttribute(gate_si_tc_kernel,
                         cudaFuncAttributeMaxDynamicSharedMemorySize, 65536);

    // 0) small folded weights (warp per output)
    int nwarps = EE * SD + SD + EE;                 // 9224
    precompute_kernel<<<(nwarps * 32 + 255) / 256, 256>>>(
        W_in, W_g, b_g, b_in, W_out, b_out, Wg_eff, bg_eff, bout_eff);

    // 1) fused decompose: W_in rows + W_out^T (hi/lo) + Wcomb fp16
    fused_decompose_kernel<<<2112, 256>>>(W_in, W_out, Wg_eff,
                                          WinHi, WinLo, WoutHi, WoutLo, Wcomb);

    // 2) BweffH = fp16(Weff^T) = (W_out^T)@(W_in rows), 3-term; /1024 undoes 32*32
    gemm_f16x3_kernel<<<dim3(8, 8), 256, 131072>>>(
        WoutHi, WoutLo, WinHi, WinLo, BweffH, 1.0f / 1024.0f);

    // 3) gate + si + x->fp16 cast, tensor-core path
    gate_si_tc_kernel<<<MM / 128, 256, 65536>>>(x, Wcomb, bg_eff, b_in,
                                                gate, si, XHi);

    // 4) parallel scan (also writes final_state at tail of output)
    scan_par_kernel<<<64, 128>>>(gate, si, states, out + (size_t)MM * EE);

    // 5) out = x @ Weff + states @ W_out[E:, :] + bout_eff   (main; 2-stage)
    gemm_main_kernel<<<dim3(8, MM / 128), 256, 65536>>>(
        XHi, BweffH, out, bout_eff, states, W_out + (size_t)EE * EE);
}

// round 13
// speedup vs baseline: 1.6577x; 1.2029x over previous
#include <cuda_runtime.h>
#include <cuda_fp16.h>
#include <math.h>
#include <stdint.h>

// ---------------- problem constants ----------------
#define BB 8
#define SS 4096
#define EE 1024
#define SD 8
#define MM (BB*SS)          // 32768
#define LDIN 1032           // E + SD
#define NITER 16            // K=1024 / 64

// ================= portable PTX helpers (sm_80+) =================
__device__ __forceinline__ uint32_t smem_to_u32(const void* smem_ptr) {
    uint32_t addr;
    asm("{ .reg .u64 tmp; cvta.to.shared.u64 tmp, %1; cvt.u32.u64 %0, tmp; }"
        : "=r"(addr) : "l"(smem_ptr));
    return addr;
}

#define CP_ASYNC16(dst, src) \
    asm volatile("cp.async.cg.shared.global [%0], [%1], 16;" \
                 :: "r"(dst), "l"(src) : "memory")
#define CP_COMMIT() asm volatile("cp.async.commit_group;" ::: "memory")
#define CP_WAIT1()  asm volatile("cp.async.wait_group 1;"  ::: "memory")

__device__ __forceinline__ void ldsm_x4(uint32_t& r0, uint32_t& r1,
                                        uint32_t& r2, uint32_t& r3,
                                        uint32_t addr) {
    asm volatile("ldmatrix.sync.aligned.m8n8.x4.shared.b16 {%0,%1,%2,%3}, [%4];"
                 : "=r"(r0), "=r"(r1), "=r"(r2), "=r"(r3) : "r"(addr));
}

__device__ __forceinline__ void mma16816(float* d, const uint32_t* a,
                                         const uint32_t* b) {
    asm volatile("mma.sync.aligned.m16n8k16.row.col.f32.f16.f16.f32 "
                 "{%0,%1,%2,%3}, {%4,%5,%6,%7}, {%8,%9}, {%0,%1,%2,%3};"
                 : "+f"(d[0]), "+f"(d[1]), "+f"(d[2]), "+f"(d[3])
                 : "r"(a[0]), "r"(a[1]), "r"(a[2]), "r"(a[3]),
                   "r"(b[0]), "r"(b[1]));
}

// ---------------- scratch (device globals, no allocs) ----------------
__device__ float g_Wg_eff[EE * SD];
__device__ float g_bg_eff[SD];
__device__ float g_bout_eff[EE];
__device__ float g_gate[MM * SD];
__device__ float g_si[MM * SD];
__device__ float g_states[MM * SD];
__device__ __half g_XHi[(size_t)MM * EE];      // x fp16 (written by gate_si_tc)
__device__ __half g_WinHi[(size_t)EE * EE];    // 32*W_in top square, hi (rows)
__device__ __half g_WinLo[(size_t)EE * EE];
__device__ __half g_WoutHi[(size_t)EE * EE];   // 32*W_out top, transposed
__device__ __half g_WoutLo[(size_t)EE * EE];
__device__ __half g_BweffH[(size_t)EE * EE];   // Weff^T fp16 (written by x3 gemm)
__device__ __half g_Wcomb[16 * EE];            // [d][e]: gate cols 0-7, si cols 8-15

// ---------------- precompute: warp per output, coalesced K ----------------
__global__ void precompute_kernel(const float* __restrict__ W_in,
                                  const float* __restrict__ W_g,
                                  const float* __restrict__ b_g,
                                  const float* __restrict__ b_in,
                                  const float* __restrict__ W_out,
                                  const float* __restrict__ b_out,
                                  float* __restrict__ Wg_eff,
                                  float* __restrict__ bg_eff,
                                  float* __restrict__ bout_eff)
{
    const int w    = (blockIdx.x * blockDim.x + threadIdx.x) >> 5;
    const int lane = threadIdx.x & 31;
    float s = 0.f;
    if (w < EE * SD) {
        int e = w >> 3, d = w & 7;
        const float* wr = W_in + (size_t)e * LDIN;
        for (int c = lane; c < LDIN; c += 32)
            s = fmaf(wr[c], W_g[c * SD + d], s);
        #pragma unroll
        for (int o = 16; o; o >>= 1) s += __shfl_xor_sync(0xffffffffu, s, o);
        if (lane == 0) Wg_eff[w] = s;
    } else if (w < EE * SD + SD) {
        int d = w - EE * SD;
        for (int c = lane; c < LDIN; c += 32)
            s = fmaf(b_in[c], W_g[c * SD + d], s);
        #pragma unroll
        for (int o = 16; o; o >>= 1) s += __shfl_xor_sync(0xffffffffu, s, o);
        if (lane == 0) bg_eff[d] = s + b_g[d];
    } else if (w < EE * SD + SD + EE) {
        int n = w - (EE * SD + SD);
        for (int c = lane; c < EE; c += 32)
            s = fmaf(b_in[c], W_out[(size_t)c * EE + n], s);
        #pragma unroll
        for (int o = 16; o; o >>= 1) s += __shfl_xor_sync(0xffffffffu, s, o);
        if (lane == 0) bout_eff[n] = s + b_out[n];
    }
}

// -- fused decompose: W_in rows (0..1023) + W_out^T (1024..2047) + Wcomb (2048..2111)
__global__ void fused_decompose_kernel(const float* __restrict__ W_in,
                                       const float* __restrict__ W_out,
                                       const float* __restrict__ Wg_eff,
                                       __half* __restrict__ WinHi,
                                       __half* __restrict__ WinLo,
                                       __half* __restrict__ WoutHi,
                                       __half* __restrict__ WoutLo,
                                       __half* __restrict__ Wcomb)
{
    const int tid = threadIdx.x;
    if (blockIdx.x < 1024) {
        int r = blockIdx.x;
        int c4 = tid * 4;
        float4 v = *(const float4*)(W_in + (size_t)r * LDIN + c4);
        struct alignas(8) H4 { __half h[4]; };
        H4 H, L;
        float vv[4] = {v.x, v.y, v.z, v.w};
        #pragma unroll
        for (int i = 0; i < 4; i++) {
            float sv = vv[i] * 32.0f;
            __half h = __float2half(sv);
            H.h[i] = h;
            L.h[i] = __float2half(sv - __half2float(h));
        }
        *(H4*)(WinHi + (size_t)r * EE + c4) = H;
        *(H4*)(WinLo + (size_t)r * EE + c4) = L;
    } else if (blockIdx.x < 2048) {
        __shared__ float tile[32][33];
        int b = blockIdx.x - 1024;
        int e0 = (b & 31) * 32, n0 = (b >> 5) * 32;
        int tx = tid & 31, ty = tid >> 5;       // 32 x 8
        #pragma unroll
        for (int i = 0; i < 4; i++)
            tile[ty + i * 8][tx] = W_out[(size_t)(e0 + ty + i * 8) * 1024 + n0 + tx];
        __syncthreads();
        #pragma unroll
        for (int i = 0; i < 4; i++) {
            int n = n0 + ty + i * 8;
            float v = tile[tx][ty + i * 8] * 32.0f;
            __half h = __float2half(v);
            WoutHi[(size_t)n * EE + e0 + tx] = h;
            WoutLo[(size_t)n * EE + e0 + tx] = __float2half(v - __half2float(h));
        }
    } else {
        int idx = (blockIdx.x - 2048) * 256 + tid;   // 0..16383
        int d = idx >> 10, e = idx & 1023;
        float v = (d < 8) ? Wg_eff[e * SD + d]
                          : W_in[(size_t)e * LDIN + EE + (d - 8)];
        Wcomb[idx] = __float2half(v);
    }
}

// ================= 3-term fp16 GEMM -> fp16 output (Weff^T precompute) =====
__global__ void __launch_bounds__(256, 2)
gemm_f16x3_kernel(const __half* __restrict__ Ahi,
                  const __half* __restrict__ Alo,
                  const __half* __restrict__ Bhi,
                  const __half* __restrict__ Blo,
                  __half* __restrict__ C, float osc)
{
    constexpr uint32_t STAGE = 65536u;
    extern __shared__ char smem[];
    const uint32_t sb = smem_to_u32(smem);
    const int tid  = threadIdx.x;
    const int lane = tid & 31;
    const int wid  = tid >> 5;
    const int wm   = wid >> 2;
    const int wn   = wid & 3;
    const int n0   = blockIdx.x * 128;
    const int m0   = blockIdx.y * 128;

    float acc[4][4][4];
    #pragma unroll
    for (int mi = 0; mi < 4; mi++)
        #pragma unroll
        for (int ni = 0; ni < 4; ni++)
            #pragma unroll
            for (int e = 0; e < 4; e++) acc[mi][ni][e] = 0.f;

    const int row0 = tid >> 3;
    const int seg  = tid & 7;

    auto prefetch = [&](int buf, int kb) {
        const uint32_t st = sb + (uint32_t)buf * STAGE;
        #pragma unroll
        for (int i = 0; i < 4; i++) {
            int row = row0 + i * 32;
            uint32_t sw = (uint32_t)row * 128u + (uint32_t)((seg ^ (row & 7)) * 16);
            CP_ASYNC16(st + sw,          Ahi + (size_t)(m0 + row) * EE + kb + seg * 8);
            CP_ASYNC16(st + 16384u + sw, Bhi + (size_t)(n0 + row) * EE + kb + seg * 8);
            CP_ASYNC16(st + 32768u + sw, Blo + (size_t)(n0 + row) * EE + kb + seg * 8);
            CP_ASYNC16(st + 49152u + sw, Alo + (size_t)(m0 + row) * EE + kb + seg * 8);
        }
    };

    prefetch(0, 0);
    CP_COMMIT();

    const int rA  = ((lane >> 3) & 1) * 8 + (lane & 7);
    const int kA8 = lane >> 4;
    const int rB  = (lane >> 4) * 8 + (lane & 7);
    const int kB8 = (lane >> 3) & 1;

    for (int it = 0; it < NITER; it++) {
        if (it + 1 < NITER) prefetch((it + 1) & 1, (it + 1) * 64);
        CP_COMMIT();
        CP_WAIT1();
        __syncthreads();

        const uint32_t aB = sb + (uint32_t)(it & 1) * STAGE;

        #pragma unroll
        for (int ks = 0; ks < 4; ks++) {
            uint32_t af[4][4], afl[4][4], bh[4][2], bl[4][2];
            #pragma unroll
            for (int mi = 0; mi < 4; mi++) {
                int row = wm * 64 + mi * 16 + rA;
                int sh  = ks * 2 + kA8;
                uint32_t roff = (uint32_t)row * 128u + (uint32_t)((sh ^ (row & 7)) * 16);
                ldsm_x4(af[mi][0], af[mi][1], af[mi][2], af[mi][3], aB + roff);
                ldsm_x4(afl[mi][0], afl[mi][1], afl[mi][2], afl[mi][3],
                        aB + 49152u + roff);
            }
            #pragma unroll
            for (int np = 0; np < 2; np++) {
                int row = wn * 32 + np * 16 + rB;
                int sh  = ks * 2 + kB8;
                uint32_t roff = (uint32_t)row * 128u + (uint32_t)((sh ^ (row & 7)) * 16);
                uint32_t r0, r1, r2, r3;
                ldsm_x4(r0, r1, r2, r3, aB + 16384u + roff);
                bh[np * 2][0] = r0;     bh[np * 2][1] = r1;
                bh[np * 2 + 1][0] = r2; bh[np * 2 + 1][1] = r3;
                ldsm_x4(r0, r1, r2, r3, aB + 32768u + roff);
                bl[np * 2][0] = r0;     bl[np * 2][1] = r1;
                bl[np * 2 + 1][0] = r2; bl[np * 2 + 1][1] = r3;
            }
            #pragma unroll
            for (int mi = 0; mi < 4; mi++)
                #pragma unroll
                for (int ni = 0; ni < 4; ni++) {
                    mma16816(acc[mi][ni], af[mi], bh[ni]);
                    mma16816(acc[mi][ni], af[mi], bl[ni]);
                    mma16816(acc[mi][ni], afl[mi], bh[ni]);
                }
        }
        __syncthreads();
    }

    const int lr  = lane >> 2;
    const int lc2 = (lane & 3) * 2;
    #pragma unroll
    for (int mi = 0; mi < 4; mi++) {
        int r0l = wm * 64 + mi * 16 + lr;
        int r1l = r0l + 8;
        #pragma unroll
        for (int ni = 0; ni < 4; ni++) {
            int cg = wn * 32 + ni * 8 + lc2;
            float* d = acc[mi][ni];
            __half2 o0 = { __float2half(d[0] * osc), __float2half(d[1] * osc) };
            __half2 o1 = { __float2half(d[2] * osc), __float2half(d[3] * osc) };
            *(__half2*)(C + (size_t)(m0 + r0l) * 1024 + n0 + cg) = o0;
            *(__half2*)(C + (size_t)(m0 + r1l) * 1024 + n0 + cg) = o1;
        }
    }
}

// ================= main 1-term fp16 GEMM (proven R8 2-stage config) ========
__global__ void __launch_bounds__(256, 2)
gemm_main_kernel(const __half* __restrict__ A,
                 const __half* __restrict__ Bm,
                 float* __restrict__ C,
                 const float* __restrict__ bias,
                 const float* __restrict__ Srank,
                 const float* __restrict__ Wbot)
{
    constexpr uint32_t STAGE = 32768u;
    extern __shared__ char smem[];
    const uint32_t sb = smem_to_u32(smem);
    const int tid  = threadIdx.x;
    const int lane = tid & 31;
    const int wid  = tid >> 5;
    const int wm   = wid >> 2;
    const int wn   = wid & 3;
    const int n0   = blockIdx.x * 128;
    const int m0   = blockIdx.y * 128;

    float acc[4][4][4];
    #pragma unroll
    for (int mi = 0; mi < 4; mi++)
        #pragma unroll
        for (int ni = 0; ni < 4; ni++)
            #pragma unroll
            for (int e = 0; e < 4; e++) acc[mi][ni][e] = 0.f;

    const int row0 = tid >> 3;
    const int seg  = tid & 7;

    auto prefetch = [&](int buf, int kb) {
        const uint32_t st = sb + (uint32_t)buf * STAGE;
        #pragma unroll
        for (int i = 0; i < 4; i++) {
            int row = row0 + i * 32;
            uint32_t sw = (uint32_t)row * 128u + (uint32_t)((seg ^ (row & 7)) * 16);
            CP_ASYNC16(st + sw,          A  + (size_t)(m0 + row) * EE + kb + seg * 8);
            CP_ASYNC16(st + 16384u + sw, Bm + (size_t)(n0 + row) * EE + kb + seg * 8);
        }
    };

    prefetch(0, 0);
    CP_COMMIT();

    const int rA  = ((lane >> 3) & 1) * 8 + (lane & 7);
    const int kA8 = lane >> 4;
    const int rB  = (lane >> 4) * 8 + (lane & 7);
    const int kB8 = (lane >> 3) & 1;

    for (int it = 0; it < NITER; it++) {
        if (it + 1 < NITER) prefetch((it + 1) & 1, (it + 1) * 64);
        CP_COMMIT();
        CP_WAIT1();
        __syncthreads();

        const uint32_t aB = sb + (uint32_t)(it & 1) * STAGE;
        const uint32_t bB = aB + 16384u;

        #pragma unroll
        for (int ks = 0; ks < 4; ks++) {
            uint32_t af[4][4], bf[4][2];
            #pragma unroll
            for (int mi = 0; mi < 4; mi++) {
                int row = wm * 64 + mi * 16 + rA;
                int sh  = ks * 2 + kA8;
                ldsm_x4(af[mi][0], af[mi][1], af[mi][2], af[mi][3],
                        aB + (uint32_t)row * 128u + (uint32_t)((sh ^ (row & 7)) * 16));
            }
            #pragma unroll
            for (int np = 0; np < 2; np++) {
                int row = wn * 32 + np * 16 + rB;
                int sh  = ks * 2 + kB8;
                uint32_t r0, r1, r2, r3;
                ldsm_x4(r0, r1, r2, r3,
                        bB + (uint32_t)row * 128u + (uint32_t)((sh ^ (row & 7)) * 16));
                bf[np * 2][0] = r0;     bf[np * 2][1] = r1;
                bf[np * 2 + 1][0] = r2; bf[np * 2 + 1][1] = r3;
            }
            #pragma unroll
            for (int mi = 0; mi < 4; mi++)
                #pragma unroll
                for (int ni = 0; ni < 4; ni++)
                    mma16816(acc[mi][ni], af[mi], bf[ni]);
        }
        __syncthreads();
    }

    // ---------------- epilogue ----------------
    float* const sBias = (float*)smem;                 // 128 f
    float* const sSt   = (float*)(smem + 512);         // 128 x 8
    float* const sWb   = (float*)(smem + 512 + 4096);  // 8 x 128
    if (tid < 128) sBias[tid] = bias[n0 + tid];
    ((float4*)sSt)[tid] = ((const float4*)(Srank + (size_t)m0 * SD))[tid];
    for (int i = tid; i < 1024; i += 256) {
        int d8 = i >> 7, nl = i & 127;
        sWb[d8 * 128 + nl] = Wbot[(size_t)d8 * 1024 + n0 + nl];
    }
    __syncthreads();

    const int lr  = lane >> 2;
    const int lc2 = (lane & 3) * 2;
    #pragma unroll
    for (int mi = 0; mi < 4; mi++) {
        int r0l = wm * 64 + mi * 16 + lr;
        int r1l = r0l + 8;
        float st0[SD], st1[SD];
        #pragma unroll
        for (int d = 0; d < SD; d++) {
            st0[d] = sSt[r0l * SD + d];
            st1[d] = sSt[r1l * SD + d];
        }
        #pragma unroll
        for (int ni = 0; ni < 4; ni++) {
            int cg = wn * 32 + ni * 8 + lc2;
            float* d = acc[mi][ni];
            float s00 = sBias[cg], s01 = sBias[cg + 1];
            float s10 = s00, s11 = s01;
            #pragma unroll
            for (int dd = 0; dd < SD; dd++) {
                float w0 = sWb[dd * 128 + cg], w1 = sWb[dd * 128 + cg + 1];
                s00 = fmaf(st0[dd], w0, s00); s01 = fmaf(st0[dd], w1, s01);
                s10 = fmaf(st1[dd], w0, s10); s11 = fmaf(st1[dd], w1, s11);
            }
            float2 o0 = { d[0] + s00, d[1] + s01 };
            float2 o1 = { d[2] + s10, d[3] + s11 };
            *(float2*)(C + (size_t)(m0 + r0l) * 1024 + n0 + cg) = o0;
            *(float2*)(C + (size_t)(m0 + r1l) * 1024 + n0 + cg) = o1;
        }
    }
}

// ============ gate_si via tensor cores, coalesced x path ============
// CTA: 128 rows, N=16 (gate 0-7 | si 8-15), K=1024 in 16 chunks of 64.
// smem: B (Wcomb swizzled) 32KB @0; A fp16 double buffer 2x16KB @32K,48K.
// x loads: thread -> (rowg = tid>>4, f4 = tid&15); lanes 0-15 cover 256B
// contiguous of one row (coalesced); each thread owns rows rowg+16i, i<8.
__global__ void __launch_bounds__(256, 2)
gate_si_tc_kernel(const float* __restrict__ x,
                  const __half* __restrict__ Wcomb,
                  const float* __restrict__ bg_eff,
                  const float* __restrict__ b_in,
                  float* __restrict__ gate,
                  float* __restrict__ si,
                  __half* __restrict__ xh)
{
    extern __shared__ char smem[];
    const uint32_t sb = smem_to_u32(smem);
    const int tid  = threadIdx.x;
    const int lane = tid & 31;
    const int wid  = tid >> 5;
    const int m0   = blockIdx.x * 128;

    // stage B once: Wcomb[d][k] -> row (k/64)*16 + d, swizzled 128B rows
    for (int i = tid; i < 2048; i += 256) {
        int h8 = i * 8;
        int d = h8 >> 10, k = h8 & 1023;
        int row = (k >> 6) * 16 + d;
        int seg = (k & 63) >> 3;
        uint4 v = *(const uint4*)(Wcomb + (size_t)d * 1024 + k);
        *(uint4*)(smem + row * 128 + ((seg ^ (row & 7)) * 16)) = v;
    }

    const int rowg = tid >> 4;          // 0..15
    const int f4i  = tid & 15;          // 0..15 (float4 index within 64-col chunk)
    const int segA = f4i >> 1;          // 16B segment 0..7
    const int off8 = (f4i & 1) * 8;     // 8B half within segment

    float4 xv[8];
    auto loadx = [&](int c) {
        const float* xp = x + (size_t)(m0 + rowg) * EE + c * 64 + f4i * 4;
        #pragma unroll
        for (int i = 0; i < 8; i++)
            xv[i] = *(const float4*)(xp + (size_t)i * 16 * EE);
    };

    auto cvtstore = [&](int c, int buf) {
        char* abase = smem + 32768 + buf * 16384;
        __half* xhp = xh + (size_t)(m0 + rowg) * EE + c * 64 + f4i * 4;
        #pragma unroll
        for (int i = 0; i < 8; i++) {
            int row = rowg + i * 16;
            __half2 p0 = __floats2half2_rn(xv[i].x, xv[i].y);
            __half2 p1 = __floats2half2_rn(xv[i].z, xv[i].w);
            struct alignas(8) H2x2 { __half2 a, b; };
            H2x2 p = { p0, p1 };
            *(H2x2*)(abase + row * 128 + ((segA ^ (row & 7)) * 16) + off8) = p;
            *(H2x2*)(xhp + (size_t)i * 16 * EE) = p;
        }
    };

    loadx(0);
    cvtstore(0, 0);
    __syncthreads();

    const int rA  = ((lane >> 3) & 1) * 8 + (lane & 7);
    const int kA8 = lane >> 4;
    const int rB  = (lane >> 4) * 8 + (lane & 7);
    const int kB8 = (lane >> 3) & 1;
    const int wrow = wid * 16;

    float acc[2][4] = {{0.f,0.f,0.f,0.f},{0.f,0.f,0.f,0.f}};

    for (int c = 0; c < 16; c++) {
        if (c + 1 < 16) loadx(c + 1);
        const uint32_t aB = sb + 32768u + (uint32_t)(c & 1) * 16384u;
        #pragma unroll
        for (int ks = 0; ks < 4; ks++) {
            uint32_t af[4], bf[2][2];
            {
                int row = wrow + rA;
                int sh  = ks * 2 + kA8;
                ldsm_x4(af[0], af[1], af[2], af[3],
                        aB + (uint32_t)row * 128u + (uint32_t)((sh ^ (row & 7)) * 16));
            }
            {
                int row = c * 16 + rB;
                int sh  = ks * 2 + kB8;
                uint32_t r0, r1, r2, r3;
                ldsm_x4(r0, r1, r2, r3,
                        sb + (uint32_t)row * 128u + (uint32_t)((sh ^ (row & 7)) * 16));
                bf[0][0] = r0; bf[0][1] = r1;
                bf[1][0] = r2; bf[1][1] = r3;
            }
            mma16816(acc[0], af, bf[0]);
            mma16816(acc[1], af, bf[1]);
        }
        if (c + 1 < 16) cvtstore(c + 1, (c + 1) & 1);
        __syncthreads();
    }

    // epilogue: gate (cols 0-7) + si (cols 8-15)
    const int lr  = lane >> 2;
    const int lc2 = (lane & 3) * 2;
    const float bg0 = bg_eff[lc2],      bg1 = bg_eff[lc2 + 1];
    const float bi0 = b_in[EE + lc2],   bi1 = b_in[EE + lc2 + 1];
    const int r0 = m0 + wrow + lr;
    const int r1 = r0 + 8;
    float2 gg0 = { 1.0f / (1.0f + expf(-(acc[0][0] + bg0))),
                   1.0f / (1.0f + expf(-(acc[0][1] + bg1))) };
    float2 gg1 = { 1.0f / (1.0f + expf(-(acc[0][2] + bg0))),
                   1.0f / (1.0f + expf(-(acc[0][3] + bg1))) };
    *(float2*)(gate + (size_t)r0 * SD + lc2) = gg0;
    *(float2*)(gate + (size_t)r1 * SD + lc2) = gg1;
    float2 ss0 = { acc[1][0] + bi0, acc[1][1] + bi1 };
    float2 ss1 = { acc[1][2] + bi0, acc[1][3] + bi1 };
    *(float2*)(si + (size_t)r0 * SD + lc2) = ss0;
    *(float2*)(si + (size_t)r1 * SD + lc2) = ss1;
}

// ---------------- parallel linear-recurrence scan ----------------
__global__ __launch_bounds__(128)
void scan_par_kernel(const float* __restrict__ gate,
                     const float* __restrict__ si,
                     float* __restrict__ states,
                     float* __restrict__ final_state)
{
    const int chain = blockIdx.x;            // 0..63
    const int b = chain >> 3, d = chain & 7;
    const int t = threadIdx.x;               // 0..127
    const int lane = t & 31, warp = t >> 5;
    const float* gp = gate + (size_t)b * SS * SD + d;
    const float* sp = si   + (size_t)b * SS * SD + d;
    float*       op = states + (size_t)b * SS * SD + d;
    const int s0 = t * 32;

    float g[32], cc[32];
    float G = 1.f, C = 0.f;
    #pragma unroll
    for (int u = 0; u < 32; u++) {
        float gv = gp[(s0 + u) * SD];
        float sv = sp[(s0 + u) * SD];
        float cv = sv - gv * sv;
        g[u] = gv; cc[u] = cv;
        C = fmaf(gv, C, cv);
        G = gv * G;
    }
    #pragma unroll
    for (int off = 1; off < 32; off <<= 1) {
        float pG = __shfl_up_sync(0xffffffffu, G, off);
        float pC = __shfl_up_sync(0xffffffffu, C, off);
        if (lane >= off) { C = fmaf(G, pC, C); G *= pG; }
    }
    __shared__ float wG[4], wC[4];
    if (lane == 31) { wG[warp] = G; wC[warp] = C; }
    __syncthreads();
    float preC = 0.f;
    for (int w = 0; w < warp; w++) { preC = fmaf(wG[w], preC, wC[w]); }
    float eG = __shfl_up_sync(0xffffffffu, G, 1);
    float eC = __shfl_up_sync(0xffffffffu, C, 1);
    if (lane == 0) { eG = 1.f; eC = 0.f; }
    float s = fmaf(eG, preC, eC);
    #pragma unroll
    for (int u = 0; u < 32; u++) {
        s = fmaf(g[u], s, cc[u]);
        op[(s0 + u) * SD] = s;
    }
    if (t == 127) final_state[b * SD + d] = s;
}

// ---------------- launch ----------------
extern "C" void kernel_launch(void* const* d_in, const int* in_sizes, int n_in,
                              void* d_out, int out_size)
{
    const float* x     = (const float*)d_in[0];
    const float* W_in  = (const float*)d_in[1];
    const float* b_in  = (const float*)d_in[2];
    const float* W_g   = (const float*)d_in[3];
    const float* b_g   = (const float*)d_in[4];
    const float* W_out = (const float*)d_in[5];
    const float* b_out = (const float*)d_in[6];
    float* out = (float*)d_out;

    float *Wg_eff, *bg_eff, *bout_eff, *gate, *si, *states;
    __half *XHi, *WinHi, *WinLo, *WoutHi, *WoutLo, *BweffH, *Wcomb;
    cudaGetSymbolAddress((void**)&Wg_eff,   g_Wg_eff);
    cudaGetSymbolAddress((void**)&bg_eff,   g_bg_eff);
    cudaGetSymbolAddress((void**)&bout_eff, g_bout_eff);
    cudaGetSymbolAddress((void**)&gate,     g_gate);
    cudaGetSymbolAddress((void**)&si,       g_si);
    cudaGetSymbolAddress((void**)&states,   g_states);
    cudaGetSymbolAddress((void**)&XHi,      g_XHi);
    cudaGetSymbolAddress((void**)&WinHi,    g_WinHi);
    cudaGetSymbolAddress((void**)&WinLo,    g_WinLo);
    cudaGetSymbolAddress((void**)&WoutHi,   g_WoutHi);
    cudaGetSymbolAddress((void**)&WoutLo,   g_WoutLo);
    cudaGetSymbolAddress((void**)&BweffH,   g_BweffH);
    cudaGetSymbolAddress((void**)&Wcomb,    g_Wcomb);

    cudaFuncSetAttribute(gemm_f16x3_kernel,
                         cudaFuncAttributeMaxDynamicSharedMemorySize, 131072);
    cudaFuncSetAttribute(gemm_main_kernel,
                         cudaFuncAttributeMaxDynamicSharedMemorySize, 65536);
    cudaFuncSetAttribute(gate_si_tc_kernel,
                         cudaFuncAttributeMaxDynamicSharedMemorySize, 65536);

    // 0) small folded weights (warp per output)
    int nwarps = EE * SD + SD + EE;                 // 9224
    precompute_kernel<<<(nwarps * 32 + 255) / 256, 256>>>(
        W_in, W_g, b_g, b_in, W_out, b_out, Wg_eff, bg_eff, bout_eff);

    // 1) fused decompose: W_in rows + W_out^T (hi/lo) + Wcomb fp16
    fused_decompose_kernel<<<2112, 256>>>(W_in, W_out, Wg_eff,
                                          WinHi, WinLo, WoutHi, WoutLo, Wcomb);

    // 2) BweffH = fp16(Weff^T) = (W_out^T)@(W_in rows), 3-term; /1024 undoes 32*32
    gemm_f16x3_kernel<<<dim3(8, 8), 256, 131072>>>(
        WoutHi, WoutLo, WinHi, WinLo, BweffH, 1.0f / 1024.0f);

    // 3) gate + si + x->fp16 cast, tensor-core path (coalesced)
    gate_si_tc_kernel<<<MM / 128, 256, 65536>>>(x, Wcomb, bg_eff, b_in,
                                                gate, si, XHi);

    // 4) parallel scan (also writes final_state at tail of output)
    scan_par_kernel<<<64, 128>>>(gate, si, states, out + (size_t)MM * EE);

    // 5) out = x @ Weff + states @ W_out[E:, :] + bout_eff   (main; 2-stage)
    gemm_main_kernel<<<dim3(8, MM / 128), 256, 65536>>>(
        XHi, BweffH, out, bout_eff, states, W_out + (size_t)EE * EE);
}

// round 14
// speedup vs baseline: 1.7652x; 1.0648x over previous
#include <cuda_runtime.h>
#include <cuda_fp16.h>
#include <math.h>
#include <stdint.h>

// ---------------- problem constants ----------------
#define BB 8
#define SS 4096
#define EE 1024
#define SD 8
#define MM (BB*SS)          // 32768
#define LDIN 1032           // E + SD
#define NITER 16            // K=1024 / 64

// ================= portable PTX helpers (sm_80+) =================
__device__ __forceinline__ uint32_t smem_to_u32(const void* smem_ptr) {
    uint32_t addr;
    asm("{ .reg .u64 tmp; cvta.to.shared.u64 tmp, %1; cvt.u32.u64 %0, tmp; }"
        : "=r"(addr) : "l"(smem_ptr));
    return addr;
}

#define CP_ASYNC16(dst, src) \
    asm volatile("cp.async.cg.shared.global [%0], [%1], 16;" \
                 :: "r"(dst), "l"(src) : "memory")
#define CP_COMMIT() asm volatile("cp.async.commit_group;" ::: "memory")
#define CP_WAIT1()  asm volatile("cp.async.wait_group 1;"  ::: "memory")

__device__ __forceinline__ void ldsm_x4(uint32_t& r0, uint32_t& r1,
                                        uint32_t& r2, uint32_t& r3,
                                        uint32_t addr) {
    asm volatile("ldmatrix.sync.aligned.m8n8.x4.shared.b16 {%0,%1,%2,%3}, [%4];"
                 : "=r"(r0), "=r"(r1), "=r"(r2), "=r"(r3) : "r"(addr));
}

__device__ __forceinline__ void mma16816(float* d, const uint32_t* a,
                                         const uint32_t* b) {
    asm volatile("mma.sync.aligned.m16n8k16.row.col.f32.f16.f16.f32 "
                 "{%0,%1,%2,%3}, {%4,%5,%6,%7}, {%8,%9}, {%0,%1,%2,%3};"
                 : "+f"(d[0]), "+f"(d[1]), "+f"(d[2]), "+f"(d[3])
                 : "r"(a[0]), "r"(a[1]), "r"(a[2]), "r"(a[3]),
                   "r"(b[0]), "r"(b[1]));
}

// ---------------- scratch (device globals, no allocs) ----------------
__device__ float g_Wg_eff[EE * SD];
__device__ float g_bg_eff[SD];
__device__ float g_bout_eff[EE];
__device__ float g_gate[MM * SD];
__device__ float g_si[MM * SD];
__device__ float g_states[MM * SD];
__device__ __half g_XHi[(size_t)MM * EE];      // x fp16 (written by gate blocks)
__device__ __half g_WinHi[(size_t)EE * EE];    // 32*W_in top square, hi (rows)
__device__ __half g_WinLo[(size_t)EE * EE];
__device__ __half g_WoutHi[(size_t)EE * EE];   // 32*W_out top, transposed
__device__ __half g_WoutLo[(size_t)EE * EE];
__device__ __half g_BweffH[(size_t)EE * EE];   // Weff^T fp16 (written by x3)
__device__ __half g_Wcomb[16 * EE];            // [d][e]: gate 0-7, si 8-15

// ========== kernel 1: folded weights + Wcomb (warp per output) ==========
// warp ranges: [0,8192) Wg_eff+Wcomb gate cols; [8192,8200) bg_eff;
// [8200,9224) bout_eff; [9224,10248) Wcomb si cols.
__global__ void precompute_kernel(const float* __restrict__ W_in,
                                  const float* __restrict__ W_g,
                                  const float* __restrict__ b_g,
                                  const float* __restrict__ b_in,
                                  const float* __restrict__ W_out,
                                  const float* __restrict__ b_out,
                                  float* __restrict__ Wg_eff,
                                  float* __restrict__ bg_eff,
                                  float* __restrict__ bout_eff,
                                  __half* __restrict__ Wcomb)
{
    const int w    = (blockIdx.x * blockDim.x + threadIdx.x) >> 5;
    const int lane = threadIdx.x & 31;
    float s = 0.f;
    if (w < EE * SD) {
        int e = w >> 3, d = w & 7;
        const float* wr = W_in + (size_t)e * LDIN;
        for (int c = lane; c < LDIN; c += 32)
            s = fmaf(wr[c], W_g[c * SD + d], s);
        #pragma unroll
        for (int o = 16; o; o >>= 1) s += __shfl_xor_sync(0xffffffffu, s, o);
        if (lane == 0) {
            Wg_eff[w] = s;
            Wcomb[d * EE + e] = __float2half(s);
        }
    } else if (w < EE * SD + SD) {
        int d = w - EE * SD;
        for (int c = lane; c < LDIN; c += 32)
            s = fmaf(b_in[c], W_g[c * SD + d], s);
        #pragma unroll
        for (int o = 16; o; o >>= 1) s += __shfl_xor_sync(0xffffffffu, s, o);
        if (lane == 0) bg_eff[d] = s + b_g[d];
    } else if (w < EE * SD + SD + EE) {
        int n = w - (EE * SD + SD);
        for (int c = lane; c < EE; c += 32)
            s = fmaf(b_in[c], W_out[(size_t)c * EE + n], s);
        #pragma unroll
        for (int o = 16; o; o >>= 1) s += __shfl_xor_sync(0xffffffffu, s, o);
        if (lane == 0) bout_eff[n] = s + b_out[n];
    } else if (w < EE * SD + SD + EE + EE) {
        int e = w - (EE * SD + SD + EE);
        if (lane < 8)
            Wcomb[(8 + lane) * EE + e] =
                __float2half(W_in[(size_t)e * LDIN + EE + lane]);
    }
}

// ========== kernel 2: merged decompose (hi/lo) + gate_si_tc ==========
// blocks [0,256): gate_si tiles (128 rows each)
// blocks [256,1280): W_in rows hi/lo; [1280,2304): W_out^T tiles hi/lo.
__global__ void __launch_bounds__(256, 2)
merged_gatesi_decomp_kernel(const float* __restrict__ x,
                            const __half* __restrict__ Wcomb,
                            const float* __restrict__ bg_eff,
                            const float* __restrict__ b_in,
                            float* __restrict__ gate,
                            float* __restrict__ si,
                            __half* __restrict__ xh,
                            const float* __restrict__ W_in,
                            const float* __restrict__ W_out,
                            __half* __restrict__ WinHi,
                            __half* __restrict__ WinLo,
                            __half* __restrict__ WoutHi,
                            __half* __restrict__ WoutLo)
{
    extern __shared__ char smem[];
    const int tid = threadIdx.x;

    if (blockIdx.x >= 256) {
        int b2 = blockIdx.x - 256;
        if (b2 < 1024) {
            // W_in rows: 32 * W_in[r][0:1024]
            int r = b2;
            int c4 = tid * 4;
            float4 v = *(const float4*)(W_in + (size_t)r * LDIN + c4);
            struct alignas(8) H4 { __half h[4]; };
            H4 H, L;
            float vv[4] = {v.x, v.y, v.z, v.w};
            #pragma unroll
            for (int i = 0; i < 4; i++) {
                float sv = vv[i] * 32.0f;
                __half h = __float2half(sv);
                H.h[i] = h;
                L.h[i] = __float2half(sv - __half2float(h));
            }
            *(H4*)(WinHi + (size_t)r * EE + c4) = H;
            *(H4*)(WinLo + (size_t)r * EE + c4) = L;
        } else {
            // W_out^T tiles
            float* tile = (float*)smem;          // 32 x 33
            int b = b2 - 1024;
            int e0 = (b & 31) * 32, n0 = (b >> 5) * 32;
            int tx = tid & 31, ty = tid >> 5;
            #pragma unroll
            for (int i = 0; i < 4; i++)
                tile[(ty + i * 8) * 33 + tx] =
                    W_out[(size_t)(e0 + ty + i * 8) * 1024 + n0 + tx];
            __syncthreads();
            #pragma unroll
            for (int i = 0; i < 4; i++) {
                int n = n0 + ty + i * 8;
                float v = tile[tx * 33 + ty + i * 8] * 32.0f;
                __half h = __float2half(v);
                WoutHi[(size_t)n * EE + e0 + tx] = h;
                WoutLo[(size_t)n * EE + e0 + tx] = __float2half(v - __half2float(h));
            }
        }
        return;
    }

    // ---- gate_si tile (proven R13 body) ----
    const uint32_t sb = smem_to_u32(smem);
    const int lane = tid & 31;
    const int wid  = tid >> 5;
    const int m0   = blockIdx.x * 128;

    for (int i = tid; i < 2048; i += 256) {
        int h8 = i * 8;
        int d = h8 >> 10, k = h8 & 1023;
        int row = (k >> 6) * 16 + d;
        int seg = (k & 63) >> 3;
        uint4 v = *(const uint4*)(Wcomb + (size_t)d * 1024 + k);
        *(uint4*)(smem + row * 128 + ((seg ^ (row & 7)) * 16)) = v;
    }

    const int rowg = tid >> 4;
    const int f4i  = tid & 15;
    const int segA = f4i >> 1;
    const int off8 = (f4i & 1) * 8;

    float4 xv[8];
    auto loadx = [&](int c) {
        const float* xp = x + (size_t)(m0 + rowg) * EE + c * 64 + f4i * 4;
        #pragma unroll
        for (int i = 0; i < 8; i++)
            xv[i] = *(const float4*)(xp + (size_t)i * 16 * EE);
    };

    auto cvtstore = [&](int c, int buf) {
        char* abase = smem + 32768 + buf * 16384;
        __half* xhp = xh + (size_t)(m0 + rowg) * EE + c * 64 + f4i * 4;
        #pragma unroll
        for (int i = 0; i < 8; i++) {
            int row = rowg + i * 16;
            __half2 p0 = __floats2half2_rn(xv[i].x, xv[i].y);
            __half2 p1 = __floats2half2_rn(xv[i].z, xv[i].w);
            struct alignas(8) H2x2 { __half2 a, b; };
            H2x2 p = { p0, p1 };
            *(H2x2*)(abase + row * 128 + ((segA ^ (row & 7)) * 16) + off8) = p;
            *(H2x2*)(xhp + (size_t)i * 16 * EE) = p;
        }
    };

    loadx(0);
    cvtstore(0, 0);
    __syncthreads();

    const int rA  = ((lane >> 3) & 1) * 8 + (lane & 7);
    const int kA8 = lane >> 4;
    const int rB  = (lane >> 4) * 8 + (lane & 7);
    const int kB8 = (lane >> 3) & 1;
    const int wrow = wid * 16;

    float acc[2][4] = {{0.f,0.f,0.f,0.f},{0.f,0.f,0.f,0.f}};

    for (int c = 0; c < 16; c++) {
        if (c + 1 < 16) loadx(c + 1);
        const uint32_t aB = sb + 32768u + (uint32_t)(c & 1) * 16384u;
        #pragma unroll
        for (int ks = 0; ks < 4; ks++) {
            uint32_t af[4], bf[2][2];
            {
                int row = wrow + rA;
                int sh  = ks * 2 + kA8;
                ldsm_x4(af[0], af[1], af[2], af[3],
                        aB + (uint32_t)row * 128u + (uint32_t)((sh ^ (row & 7)) * 16));
            }
            {
                int row = c * 16 + rB;
                int sh  = ks * 2 + kB8;
                uint32_t r0, r1, r2, r3;
                ldsm_x4(r0, r1, r2, r3,
                        sb + (uint32_t)row * 128u + (uint32_t)((sh ^ (row & 7)) * 16));
                bf[0][0] = r0; bf[0][1] = r1;
                bf[1][0] = r2; bf[1][1] = r3;
            }
            mma16816(acc[0], af, bf[0]);
            mma16816(acc[1], af, bf[1]);
        }
        if (c + 1 < 16) cvtstore(c + 1, (c + 1) & 1);
        __syncthreads();
    }

    const int lr  = lane >> 2;
    const int lc2 = (lane & 3) * 2;
    const float bg0 = bg_eff[lc2],      bg1 = bg_eff[lc2 + 1];
    const float bi0 = b_in[EE + lc2],   bi1 = b_in[EE + lc2 + 1];
    const int r0 = m0 + wrow + lr;
    const int r1 = r0 + 8;
    float2 gg0 = { 1.0f / (1.0f + expf(-(acc[0][0] + bg0))),
                   1.0f / (1.0f + expf(-(acc[0][1] + bg1))) };
    float2 gg1 = { 1.0f / (1.0f + expf(-(acc[0][2] + bg0))),
                   1.0f / (1.0f + expf(-(acc[0][3] + bg1))) };
    *(float2*)(gate + (size_t)r0 * SD + lc2) = gg0;
    *(float2*)(gate + (size_t)r1 * SD + lc2) = gg1;
    float2 ss0 = { acc[1][0] + bi0, acc[1][1] + bi1 };
    float2 ss1 = { acc[1][2] + bi0, acc[1][3] + bi1 };
    *(float2*)(si + (size_t)r0 * SD + lc2) = ss0;
    *(float2*)(si + (size_t)r1 * SD + lc2) = ss1;
}

// ========== kernel 3: merged x3 (Weff^T) + scan ==========
// blocks [0,128): x3 tiles M=128 x N=64 (grid 16 N-tiles x 8 M-tiles flat)
// blocks [128,192): scan chains (256 threads, 16 steps each)
// x3 stage (48KB): Ahi@0 16K, Bhi@16K 8K, Blo@24K 8K, Alo@32K 16K; 2 stages.
__global__ void __launch_bounds__(256, 2)
merged_x3_scan_kernel(const __half* __restrict__ Ahi,
                      const __half* __restrict__ Alo,
                      const __half* __restrict__ Bhi,
                      const __half* __restrict__ Blo,
                      __half* __restrict__ C, float osc,
                      const float* __restrict__ gate,
                      const float* __restrict__ si,
                      float* __restrict__ states,
                      float* __restrict__ final_state)
{
    extern __shared__ char smem[];
    const int tid = threadIdx.x;

    if (blockIdx.x >= 128) {
        // ---- scan chain: 256 threads x 16 steps ----
        const int chain = blockIdx.x - 128;
        const int b = chain >> 3, d = chain & 7;
        const int lane = tid & 31, warp = tid >> 5;   // 8 warps
        const float* gp = gate + (size_t)b * SS * SD + d;
        const float* sp = si   + (size_t)b * SS * SD + d;
        float*       op = states + (size_t)b * SS * SD + d;
        const int s0 = tid * 16;

        float g[16], cc[16];
        float G = 1.f, Cc = 0.f;
        #pragma unroll
        for (int u = 0; u < 16; u++) {
            float gv = gp[(s0 + u) * SD];
            float sv = sp[(s0 + u) * SD];
            float cv = sv - gv * sv;
            g[u] = gv; cc[u] = cv;
            Cc = fmaf(gv, Cc, cv);
            G = gv * G;
        }
        #pragma unroll
        for (int off = 1; off < 32; off <<= 1) {
            float pG = __shfl_up_sync(0xffffffffu, G, off);
            float pC = __shfl_up_sync(0xffffffffu, Cc, off);
            if (lane >= off) { Cc = fmaf(G, pC, Cc); G *= pG; }
        }
        float* wG = (float*)smem;          // 8
        float* wC = (float*)smem + 8;      // 8
        if (lane == 31) { wG[warp] = G; wC[warp] = Cc; }
        __syncthreads();
        float preC = 0.f;
        for (int w = 0; w < warp; w++) { preC = fmaf(wG[w], preC, wC[w]); }
        float eG = __shfl_up_sync(0xffffffffu, G, 1);
        float eC = __shfl_up_sync(0xffffffffu, Cc, 1);
        if (lane == 0) { eG = 1.f; eC = 0.f; }
        float s = fmaf(eG, preC, eC);
        #pragma unroll
        for (int u = 0; u < 16; u++) {
            s = fmaf(g[u], s, cc[u]);
            op[(s0 + u) * SD] = s;
        }
        if (tid == 255) final_state[b * SD + d] = s;
        return;
    }

    // ---- x3 tile: M=128 x N=64 ----
    constexpr uint32_t STAGE = 49152u;
    const uint32_t sb = smem_to_u32(smem);
    const int lane = tid & 31;
    const int wid  = tid >> 5;
    const int wm   = wid >> 2;                 // 0..1
    const int wn   = wid & 3;                  // 0..3
    const int n0   = (blockIdx.x & 15) * 64;
    const int m0   = (blockIdx.x >> 4) * 128;

    float acc[4][2][4];
    #pragma unroll
    for (int mi = 0; mi < 4; mi++)
        #pragma unroll
        for (int ni = 0; ni < 2; ni++)
            #pragma unroll
            for (int e = 0; e < 4; e++) acc[mi][ni][e] = 0.f;

    const int row0 = tid >> 3;
    const int seg  = tid & 7;

    auto prefetch = [&](int buf, int kb) {
        const uint32_t st = sb + (uint32_t)buf * STAGE;
        #pragma unroll
        for (int i = 0; i < 4; i++) {
            int row = row0 + i * 32;
            uint32_t sw = (uint32_t)row * 128u + (uint32_t)((seg ^ (row & 7)) * 16);
            CP_ASYNC16(st + sw,          Ahi + (size_t)(m0 + row) * EE + kb + seg * 8);
            CP_ASYNC16(st + 32768u + sw, Alo + (size_t)(m0 + row) * EE + kb + seg * 8);
        }
        #pragma unroll
        for (int i = 0; i < 2; i++) {
            int row = row0 + i * 32;
            uint32_t sw = (uint32_t)row * 128u + (uint32_t)((seg ^ (row & 7)) * 16);
            CP_ASYNC16(st + 16384u + sw, Bhi + (size_t)(n0 + row) * EE + kb + seg * 8);
            CP_ASYNC16(st + 24576u + sw, Blo + (size_t)(n0 + row) * EE + kb + seg * 8);
        }
    };

    prefetch(0, 0);
    CP_COMMIT();

    const int rA  = ((lane >> 3) & 1) * 8 + (lane & 7);
    const int kA8 = lane >> 4;
    const int rB  = (lane >> 4) * 8 + (lane & 7);
    const int kB8 = (lane >> 3) & 1;

    for (int it = 0; it < NITER; it++) {
        if (it + 1 < NITER) prefetch((it + 1) & 1, (it + 1) * 64);
        CP_COMMIT();
        CP_WAIT1();
        __syncthreads();

        const uint32_t aB = sb + (uint32_t)(it & 1) * STAGE;

        #pragma unroll
        for (int ks = 0; ks < 4; ks++) {
            uint32_t af[4][4], afl[4][4], bh[2][2], bl[2][2];
            #pragma unroll
            for (int mi = 0; mi < 4; mi++) {
                int row = wm * 64 + mi * 16 + rA;
                int sh  = ks * 2 + kA8;
                uint32_t roff = (uint32_t)row * 128u + (uint32_t)((sh ^ (row & 7)) * 16);
                ldsm_x4(af[mi][0], af[mi][1], af[mi][2], af[mi][3], aB + roff);
                ldsm_x4(afl[mi][0], afl[mi][1], afl[mi][2], afl[mi][3],
                        aB + 32768u + roff);
            }
            {
                int row = wn * 16 + rB;
                int sh  = ks * 2 + kB8;
                uint32_t roff = (uint32_t)row * 128u + (uint32_t)((sh ^ (row & 7)) * 16);
                uint32_t r0, r1, r2, r3;
                ldsm_x4(r0, r1, r2, r3, aB + 16384u + roff);
                bh[0][0] = r0; bh[0][1] = r1;
                bh[1][0] = r2; bh[1][1] = r3;
                ldsm_x4(r0, r1, r2, r3, aB + 24576u + roff);
                bl[0][0] = r0; bl[0][1] = r1;
                bl[1][0] = r2; bl[1][1] = r3;
            }
            #pragma unroll
            for (int mi = 0; mi < 4; mi++)
                #pragma unroll
                for (int ni = 0; ni < 2; ni++) {
                    mma16816(acc[mi][ni], af[mi], bh[ni]);
                    mma16816(acc[mi][ni], af[mi], bl[ni]);
                    mma16816(acc[mi][ni], afl[mi], bh[ni]);
                }
        }
        __syncthreads();
    }

    const int lr  = lane >> 2;
    const int lc2 = (lane & 3) * 2;
    #pragma unroll
    for (int mi = 0; mi < 4; mi++) {
        int r0l = wm * 64 + mi * 16 + lr;
        int r1l = r0l + 8;
        #pragma unroll
        for (int ni = 0; ni < 2; ni++) {
            int cg = wn * 16 + ni * 8 + lc2;
            float* d = acc[mi][ni];
            __half2 o0 = { __float2half(d[0] * osc), __float2half(d[1] * osc) };
            __half2 o1 = { __float2half(d[2] * osc), __float2half(d[3] * osc) };
            *(__half2*)(C + (size_t)(m0 + r0l) * 1024 + n0 + cg) = o0;
            *(__half2*)(C + (size_t)(m0 + r1l) * 1024 + n0 + cg) = o1;
        }
    }
}

// ================= main 1-term fp16 GEMM (proven R8 2-stage config) ========
__global__ void __launch_bounds__(256, 2)
gemm_main_kernel(const __half* __restrict__ A,
                 const __half* __restrict__ Bm,
                 float* __restrict__ C,
                 const float* __restrict__ bias,
                 const float* __restrict__ Srank,
                 const float* __restrict__ Wbot)
{
    constexpr uint32_t STAGE = 32768u;
    extern __shared__ char smem[];
    const uint32_t sb = smem_to_u32(smem);
    const int tid  = threadIdx.x;
    const int lane = tid & 31;
    const int wid  = tid >> 5;
    const int wm   = wid >> 2;
    const int wn   = wid & 3;
    const int n0   = blockIdx.x * 128;
    const int m0   = blockIdx.y * 128;

    float acc[4][4][4];
    #pragma unroll
    for (int mi = 0; mi < 4; mi++)
        #pragma unroll
        for (int ni = 0; ni < 4; ni++)
            #pragma unroll
            for (int e = 0; e < 4; e++) acc[mi][ni][e] = 0.f;

    const int row0 = tid >> 3;
    const int seg  = tid & 7;

    auto prefetch = [&](int buf, int kb) {
        const uint32_t st = sb + (uint32_t)buf * STAGE;
        #pragma unroll
        for (int i = 0; i < 4; i++) {
            int row = row0 + i * 32;
            uint32_t sw = (uint32_t)row * 128u + (uint32_t)((seg ^ (row & 7)) * 16);
            CP_ASYNC16(st + sw,          A  + (size_t)(m0 + row) * EE + kb + seg * 8);
            CP_ASYNC16(st + 16384u + sw, Bm + (size_t)(n0 + row) * EE + kb + seg * 8);
        }
    };

    prefetch(0, 0);
    CP_COMMIT();

    const int rA  = ((lane >> 3) & 1) * 8 + (lane & 7);
    const int kA8 = lane >> 4;
    const int rB  = (lane >> 4) * 8 + (lane & 7);
    const int kB8 = (lane >> 3) & 1;

    for (int it = 0; it < NITER; it++) {
        if (it + 1 < NITER) prefetch((it + 1) & 1, (it + 1) * 64);
        CP_COMMIT();
        CP_WAIT1();
        __syncthreads();

        const uint32_t aB = sb + (uint32_t)(it & 1) * STAGE;
        const uint32_t bB = aB + 16384u;

        #pragma unroll
        for (int ks = 0; ks < 4; ks++) {
            uint32_t af[4][4], bf[4][2];
            #pragma unroll
            for (int mi = 0; mi < 4; mi++) {
                int row = wm * 64 + mi * 16 + rA;
                int sh  = ks * 2 + kA8;
                ldsm_x4(af[mi][0], af[mi][1], af[mi][2], af[mi][3],
                        aB + (uint32_t)row * 128u + (uint32_t)((sh ^ (row & 7)) * 16));
            }
            #pragma unroll
            for (int np = 0; np < 2; np++) {
                int row = wn * 32 + np * 16 + rB;
                int sh  = ks * 2 + kB8;
                uint32_t r0, r1, r2, r3;
                ldsm_x4(r0, r1, r2, r3,
                        bB + (uint32_t)row * 128u + (uint32_t)((sh ^ (row & 7)) * 16));
                bf[np * 2][0] = r0;     bf[np * 2][1] = r1;
                bf[np * 2 + 1][0] = r2; bf[np * 2 + 1][1] = r3;
            }
            #pragma unroll
            for (int mi = 0; mi < 4; mi++)
                #pragma unroll
                for (int ni = 0; ni < 4; ni++)
                    mma16816(acc[mi][ni], af[mi], bf[ni]);
        }
        __syncthreads();
    }

    // ---------------- epilogue ----------------
    float* const sBias = (float*)smem;                 // 128 f
    float* const sSt   = (float*)(smem + 512);         // 128 x 8
    float* const sWb   = (float*)(smem + 512 + 4096);  // 8 x 128
    if (tid < 128) sBias[tid] = bias[n0 + tid];
    ((float4*)sSt)[tid] = ((const float4*)(Srank + (size_t)m0 * SD))[tid];
    for (int i = tid; i < 1024; i += 256) {
        int d8 = i >> 7, nl = i & 127;
        sWb[d8 * 128 + nl] = Wbot[(size_t)d8 * 1024 + n0 + nl];
    }
    __syncthreads();

    const int lr  = lane >> 2;
    const int lc2 = (lane & 3) * 2;
    #pragma unroll
    for (int mi = 0; mi < 4; mi++) {
        int r0l = wm * 64 + mi * 16 + lr;
        int r1l = r0l + 8;
        float st0[SD], st1[SD];
        #pragma unroll
        for (int d = 0; d < SD; d++) {
            st0[d] = sSt[r0l * SD + d];
            st1[d] = sSt[r1l * SD + d];
        }
        #pragma unroll
        for (int ni = 0; ni < 4; ni++) {
            int cg = wn * 32 + ni * 8 + lc2;
            float* d = acc[mi][ni];
            float s00 = sBias[cg], s01 = sBias[cg + 1];
            float s10 = s00, s11 = s01;
            #pragma unroll
            for (int dd = 0; dd < SD; dd++) {
                float w0 = sWb[dd * 128 + cg], w1 = sWb[dd * 128 + cg + 1];
                s00 = fmaf(st0[dd], w0, s00); s01 = fmaf(st0[dd], w1, s01);
                s10 = fmaf(st1[dd], w0, s10); s11 = fmaf(st1[dd], w1, s11);
            }
            float2 o0 = { d[0] + s00, d[1] + s01 };
            float2 o1 = { d[2] + s10, d[3] + s11 };
            *(float2*)(C + (size_t)(m0 + r0l) * 1024 + n0 + cg) = o0;
            *(float2*)(C + (size_t)(m0 + r1l) * 1024 + n0 + cg) = o1;
        }
    }
}

// ---------------- launch ----------------
extern "C" void kernel_launch(void* const* d_in, const int* in_sizes, int n_in,
                              void* d_out, int out_size)
{
    const float* x     = (const float*)d_in[0];
    const float* W_in  = (const float*)d_in[1];
    const float* b_in  = (const float*)d_in[2];
    const float* W_g   = (const float*)d_in[3];
    const float* b_g   = (const float*)d_in[4];
    const float* W_out = (const float*)d_in[5];
    const float* b_out = (const float*)d_in[6];
    float* out = (float*)d_out;

    float *Wg_eff, *bg_eff, *bout_eff, *gate, *si, *states;
    __half *XHi, *WinHi, *WinLo, *WoutHi, *WoutLo, *BweffH, *Wcomb;
    cudaGetSymbolAddress((void**)&Wg_eff,   g_Wg_eff);
    cudaGetSymbolAddress((void**)&bg_eff,   g_bg_eff);
    cudaGetSymbolAddress((void**)&bout_eff, g_bout_eff);
    cudaGetSymbolAddress((void**)&gate,     g_gate);
    cudaGetSymbolAddress((void**)&si,       g_si);
    cudaGetSymbolAddress((void**)&states,   g_states);
    cudaGetSymbolAddress((void**)&XHi,      g_XHi);
    cudaGetSymbolAddress((void**)&WinHi,    g_WinHi);
    cudaGetSymbolAddress((void**)&WinLo,    g_WinLo);
    cudaGetSymbolAddress((void**)&WoutHi,   g_WoutHi);
    cudaGetSymbolAddress((void**)&WoutLo,   g_WoutLo);
    cudaGetSymbolAddress((void**)&BweffH,   g_BweffH);
    cudaGetSymbolAddress((void**)&Wcomb,    g_Wcomb);

    cudaFuncSetAttribute(merged_gatesi_decomp_kernel,
                         cudaFuncAttributeMaxDynamicSharedMemorySize, 65536);
    cudaFuncSetAttribute(merged_x3_scan_kernel,
                         cudaFuncAttributeMaxDynamicSharedMemorySize, 98304);
    cudaFuncSetAttribute(gemm_main_kernel,
                         cudaFuncAttributeMaxDynamicSharedMemorySize, 65536);

    // 1) folded weights + Wcomb (warp per output)
    int nwarps = EE * SD + SD + EE + EE;            // 10248
    precompute_kernel<<<(nwarps * 32 + 255) / 256, 256>>>(
        W_in, W_g, b_g, b_in, W_out, b_out, Wg_eff, bg_eff, bout_eff, Wcomb);

    // 2) merged: gate/si/x-cast (blocks 0-255) || weight decompose (256-2303)
    merged_gatesi_decomp_kernel<<<2304, 256, 65536>>>(
        x, Wcomb, bg_eff, b_in, gate, si, XHi,
        W_in, W_out, WinHi, WinLo, WoutHi, WoutLo);

    // 3) merged: Weff^T 3-term GEMM (blocks 0-127) || scan (128-191)
    merged_x3_scan_kernel<<<192, 256, 98304>>>(
        WoutHi, WoutLo, WinHi, WinLo, BweffH, 1.0f / 1024.0f,
        gate, si, states, out + (size_t)MM * EE);

    // 4) out = x @ Weff + states @ W_out[E:, :] + bout_eff
    gemm_main_kernel<<<dim3(8, MM / 128), 256, 65536>>>(
        XHi, BweffH, out, bout_eff, states, W_out + (size_t)EE * EE);
}

// round 15
// speedup vs baseline: 1.8014x; 1.0205x over previous
#include <cuda_runtime.h>
#include <cuda.h>
#include <cuda_fp16.h>
#include <math.h>
#include <stdint.h>

// ---------------- problem constants ----------------
#define BB 8
#define SS 4096
#define EE 1024
#define SD 8
#define MM (BB*SS)          // 32768
#define LDIN 1032           // E + SD
#define NITER 16            // K=1024 / 64

// ================= portable PTX helpers (sm_80+/sm_90) =================
__device__ __forceinline__ uint32_t smem_to_u32(const void* smem_ptr) {
    uint32_t addr;
    asm("{ .reg .u64 tmp; cvta.to.shared.u64 tmp, %1; cvt.u32.u64 %0, tmp; }"
        : "=r"(addr) : "l"(smem_ptr));
    return addr;
}

#define CP_ASYNC16(dst, src) \
    asm volatile("cp.async.cg.shared.global [%0], [%1], 16;" \
                 :: "r"(dst), "l"(src) : "memory")
#define CP_COMMIT() asm volatile("cp.async.commit_group;" ::: "memory")
#define CP_WAIT1()  asm volatile("cp.async.wait_group 1;"  ::: "memory")

#define MBARRIER_INIT(mbar, count) \
    asm volatile("mbarrier.init.shared.b64 [%0], %1;" \
                 :: "r"((uint32_t)(mbar)), "r"((uint32_t)(count)) : "memory")

#define MBARRIER_EXPECT_TX(mbar, bytes) \
    asm volatile("mbarrier.arrive.expect_tx.shared.b64 _, [%0], %1;" \
                 :: "r"((uint32_t)(mbar)), "r"((uint32_t)(bytes)) : "memory")

#define MBARRIER_WAIT_PARITY(mbar, parity) do { \
    uint32_t _mb = (uint32_t)(mbar); \
    uint32_t _ph = (uint32_t)(parity); \
    asm volatile( \
        "{\n\t" \
        ".reg .pred P1;\n\t" \
        "WAIT_LOOP_%=:\n\t" \
        "mbarrier.try_wait.parity.acquire.cta.shared::cta.b64 P1, [%0], %1, 0x989680;\n\t" \
        "@P1 bra.uni WAIT_DONE_%=;\n\t" \
        "bra.uni WAIT_LOOP_%=;\n\t" \
        "WAIT_DONE_%=:\n\t" \
        "}" :: "r"(_mb), "r"(_ph) : "memory"); \
} while(0)

__device__ __forceinline__ void ldsm_x4(uint32_t& r0, uint32_t& r1,
                                        uint32_t& r2, uint32_t& r3,
                                        uint32_t addr) {
    asm volatile("ldmatrix.sync.aligned.m8n8.x4.shared.b16 {%0,%1,%2,%3}, [%4];"
                 : "=r"(r0), "=r"(r1), "=r"(r2), "=r"(r3) : "r"(addr));
}

__device__ __forceinline__ void mma16816(float* d, const uint32_t* a,
                                         const uint32_t* b) {
    asm volatile("mma.sync.aligned.m16n8k16.row.col.f32.f16.f16.f32 "
                 "{%0,%1,%2,%3}, {%4,%5,%6,%7}, {%8,%9}, {%0,%1,%2,%3};"
                 : "+f"(d[0]), "+f"(d[1]), "+f"(d[2]), "+f"(d[3])
                 : "r"(a[0]), "r"(a[1]), "r"(a[2]), "r"(a[3]),
                   "r"(b[0]), "r"(b[1]));
}

// ---------------- scratch (device globals, no allocs) ----------------
__device__ float g_Wg_eff[EE * SD];
__device__ float g_bg_eff[SD];
__device__ float g_bout_eff[EE];
__device__ float g_gate[MM * SD];
__device__ float g_si[MM * SD];
__device__ float g_states[MM * SD];
__device__ __half g_XHi[(size_t)MM * EE];      // x fp16 (written by gate blocks)
__device__ __half g_WinHi[(size_t)EE * EE];    // 32*W_in top square, hi (rows)
__device__ __half g_WinLo[(size_t)EE * EE];
__device__ __half g_WoutHi[(size_t)EE * EE];   // 32*W_out top, transposed
__device__ __half g_WoutLo[(size_t)EE * EE];
__device__ __half g_BweffH[(size_t)EE * EE];   // Weff^T fp16 (written by x3)
__device__ __half g_Wcomb[16 * EE];            // [d][e]: gate 0-7, si 8-15

// ========== kernel 1: folded weights + Wcomb (warp per output) ==========
__global__ void precompute_kernel(const float* __restrict__ W_in,
                                  const float* __restrict__ W_g,
                                  const float* __restrict__ b_g,
                                  const float* __restrict__ b_in,
                                  const float* __restrict__ W_out,
                                  const float* __restrict__ b_out,
                                  float* __restrict__ Wg_eff,
                                  float* __restrict__ bg_eff,
                                  float* __restrict__ bout_eff,
                                  __half* __restrict__ Wcomb)
{
    const int w    = (blockIdx.x * blockDim.x + threadIdx.x) >> 5;
    const int lane = threadIdx.x & 31;
    float s = 0.f;
    if (w < EE * SD) {
        int e = w >> 3, d = w & 7;
        const float* wr = W_in + (size_t)e * LDIN;
        for (int c = lane; c < LDIN; c += 32)
            s = fmaf(wr[c], W_g[c * SD + d], s);
        #pragma unroll
        for (int o = 16; o; o >>= 1) s += __shfl_xor_sync(0xffffffffu, s, o);
        if (lane == 0) {
            Wg_eff[w] = s;
            Wcomb[d * EE + e] = __float2half(s);
        }
    } else if (w < EE * SD + SD) {
        int d = w - EE * SD;
        for (int c = lane; c < LDIN; c += 32)
            s = fmaf(b_in[c], W_g[c * SD + d], s);
        #pragma unroll
        for (int o = 16; o; o >>= 1) s += __shfl_xor_sync(0xffffffffu, s, o);
        if (lane == 0) bg_eff[d] = s + b_g[d];
    } else if (w < EE * SD + SD + EE) {
        int n = w - (EE * SD + SD);
        for (int c = lane; c < EE; c += 32)
            s = fmaf(b_in[c], W_out[(size_t)c * EE + n], s);
        #pragma unroll
        for (int o = 16; o; o >>= 1) s += __shfl_xor_sync(0xffffffffu, s, o);
        if (lane == 0) bout_eff[n] = s + b_out[n];
    } else if (w < EE * SD + SD + EE + EE) {
        int e = w - (EE * SD + SD + EE);
        if (lane < 8)
            Wcomb[(8 + lane) * EE + e] =
                __float2half(W_in[(size_t)e * LDIN + EE + lane]);
    }
}

// ========== kernel 2: merged decompose (hi/lo) + gate_si_tc ==========
__global__ void __launch_bounds__(256, 2)
merged_gatesi_decomp_kernel(const float* __restrict__ x,
                            const __half* __restrict__ Wcomb,
                            const float* __restrict__ bg_eff,
                            const float* __restrict__ b_in,
                            float* __restrict__ gate,
                            float* __restrict__ si,
                            __half* __restrict__ xh,
                            const float* __restrict__ W_in,
                            const float* __restrict__ W_out,
                            __half* __restrict__ WinHi,
                            __half* __restrict__ WinLo,
                            __half* __restrict__ WoutHi,
                            __half* __restrict__ WoutLo)
{
    extern __shared__ char smem[];
    const int tid = threadIdx.x;

    if (blockIdx.x >= 256) {
        int b2 = blockIdx.x - 256;
        if (b2 < 1024) {
            int r = b2;
            int c4 = tid * 4;
            float4 v = *(const float4*)(W_in + (size_t)r * LDIN + c4);
            struct alignas(8) H4 { __half h[4]; };
            H4 H, L;
            float vv[4] = {v.x, v.y, v.z, v.w};
            #pragma unroll
            for (int i = 0; i < 4; i++) {
                float sv = vv[i] * 32.0f;
                __half h = __float2half(sv);
                H.h[i] = h;
                L.h[i] = __float2half(sv - __half2float(h));
            }
            *(H4*)(WinHi + (size_t)r * EE + c4) = H;
            *(H4*)(WinLo + (size_t)r * EE + c4) = L;
        } else {
            float* tile = (float*)smem;          // 32 x 33
            int b = b2 - 1024;
            int e0 = (b & 31) * 32, n0 = (b >> 5) * 32;
            int tx = tid & 31, ty = tid >> 5;
            #pragma unroll
            for (int i = 0; i < 4; i++)
                tile[(ty + i * 8) * 33 + tx] =
                    W_out[(size_t)(e0 + ty + i * 8) * 1024 + n0 + tx];
            __syncthreads();
            #pragma unroll
            for (int i = 0; i < 4; i++) {
                int n = n0 + ty + i * 8;
                float v = tile[tx * 33 + ty + i * 8] * 32.0f;
                __half h = __float2half(v);
                WoutHi[(size_t)n * EE + e0 + tx] = h;
                WoutLo[(size_t)n * EE + e0 + tx] = __float2half(v - __half2float(h));
            }
        }
        return;
    }

    // ---- gate_si tile (proven R13 body) ----
    const uint32_t sb = smem_to_u32(smem);
    const int lane = tid & 31;
    const int wid  = tid >> 5;
    const int m0   = blockIdx.x * 128;

    for (int i = tid; i < 2048; i += 256) {
        int h8 = i * 8;
        int d = h8 >> 10, k = h8 & 1023;
        int row = (k >> 6) * 16 + d;
        int seg = (k & 63) >> 3;
        uint4 v = *(const uint4*)(Wcomb + (size_t)d * 1024 + k);
        *(uint4*)(smem + row * 128 + ((seg ^ (row & 7)) * 16)) = v;
    }

    const int rowg = tid >> 4;
    const int f4i  = tid & 15;
    const int segA = f4i >> 1;
    const int off8 = (f4i & 1) * 8;

    float4 xv[8];
    auto loadx = [&](int c) {
        const float* xp = x + (size_t)(m0 + rowg) * EE + c * 64 + f4i * 4;
        #pragma unroll
        for (int i = 0; i < 8; i++)
            xv[i] = *(const float4*)(xp + (size_t)i * 16 * EE);
    };

    auto cvtstore = [&](int c, int buf) {
        char* abase = smem + 32768 + buf * 16384;
        __half* xhp = xh + (size_t)(m0 + rowg) * EE + c * 64 + f4i * 4;
        #pragma unroll
        for (int i = 0; i < 8; i++) {
            int row = rowg + i * 16;
            __half2 p0 = __floats2half2_rn(xv[i].x, xv[i].y);
            __half2 p1 = __floats2half2_rn(xv[i].z, xv[i].w);
            struct alignas(8) H2x2 { __half2 a, b; };
            H2x2 p = { p0, p1 };
            *(H2x2*)(abase + row * 128 + ((segA ^ (row & 7)) * 16) + off8) = p;
            *(H2x2*)(xhp + (size_t)i * 16 * EE) = p;
        }
    };

    loadx(0);
    cvtstore(0, 0);
    __syncthreads();

    const int rA  = ((lane >> 3) & 1) * 8 + (lane & 7);
    const int kA8 = lane >> 4;
    const int rB  = (lane >> 4) * 8 + (lane & 7);
    const int kB8 = (lane >> 3) & 1;
    const int wrow = wid * 16;

    float acc[2][4] = {{0.f,0.f,0.f,0.f},{0.f,0.f,0.f,0.f}};

    for (int c = 0; c < 16; c++) {
        if (c + 1 < 16) loadx(c + 1);
        const uint32_t aB = sb + 32768u + (uint32_t)(c & 1) * 16384u;
        #pragma unroll
        for (int ks = 0; ks < 4; ks++) {
            uint32_t af[4], bf[2][2];
            {
                int row = wrow + rA;
                int sh  = ks * 2 + kA8;
                ldsm_x4(af[0], af[1], af[2], af[3],
                        aB + (uint32_t)row * 128u + (uint32_t)((sh ^ (row & 7)) * 16));
            }
            {
                int row = c * 16 + rB;
                int sh  = ks * 2 + kB8;
                uint32_t r0, r1, r2, r3;
                ldsm_x4(r0, r1, r2, r3,
                        sb + (uint32_t)row * 128u + (uint32_t)((sh ^ (row & 7)) * 16));
                bf[0][0] = r0; bf[0][1] = r1;
                bf[1][0] = r2; bf[1][1] = r3;
            }
            mma16816(acc[0], af, bf[0]);
            mma16816(acc[1], af, bf[1]);
        }
        if (c + 1 < 16) cvtstore(c + 1, (c + 1) & 1);
        __syncthreads();
    }

    const int lr  = lane >> 2;
    const int lc2 = (lane & 3) * 2;
    const float bg0 = bg_eff[lc2],      bg1 = bg_eff[lc2 + 1];
    const float bi0 = b_in[EE + lc2],   bi1 = b_in[EE + lc2 + 1];
    const int r0 = m0 + wrow + lr;
    const int r1 = r0 + 8;
    float2 gg0 = { 1.0f / (1.0f + expf(-(acc[0][0] + bg0))),
                   1.0f / (1.0f + expf(-(acc[0][1] + bg1))) };
    float2 gg1 = { 1.0f / (1.0f + expf(-(acc[0][2] + bg0))),
                   1.0f / (1.0f + expf(-(acc[0][3] + bg1))) };
    *(float2*)(gate + (size_t)r0 * SD + lc2) = gg0;
    *(float2*)(gate + (size_t)r1 * SD + lc2) = gg1;
    float2 ss0 = { acc[1][0] + bi0, acc[1][1] + bi1 };
    float2 ss1 = { acc[1][2] + bi0, acc[1][3] + bi1 };
    *(float2*)(si + (size_t)r0 * SD + lc2) = ss0;
    *(float2*)(si + (size_t)r1 * SD + lc2) = ss1;
}

// ========== kernel 3: merged x3 (Weff^T) + scan ==========
__global__ void __launch_bounds__(256, 2)
merged_x3_scan_kernel(const __half* __restrict__ Ahi,
                      const __half* __restrict__ Alo,
                      const __half* __restrict__ Bhi,
                      const __half* __restrict__ Blo,
                      __half* __restrict__ C, float osc,
                      const float* __restrict__ gate,
                      const float* __restrict__ si,
                      float* __restrict__ states,
                      float* __restrict__ final_state)
{
    extern __shared__ char smem[];
    const int tid = threadIdx.x;

    if (blockIdx.x >= 128) {
        const int chain = blockIdx.x - 128;
        const int b = chain >> 3, d = chain & 7;
        const int lane = tid & 31, warp = tid >> 5;
        const float* gp = gate + (size_t)b * SS * SD + d;
        const float* sp = si   + (size_t)b * SS * SD + d;
        float*       op = states + (size_t)b * SS * SD + d;
        const int s0 = tid * 16;

        float g[16], cc[16];
        float G = 1.f, Cc = 0.f;
        #pragma unroll
        for (int u = 0; u < 16; u++) {
            float gv = gp[(s0 + u) * SD];
            float sv = sp[(s0 + u) * SD];
            float cv = sv - gv * sv;
            g[u] = gv; cc[u] = cv;
            Cc = fmaf(gv, Cc, cv);
            G = gv * G;
        }
        #pragma unroll
        for (int off = 1; off < 32; off <<= 1) {
            float pG = __shfl_up_sync(0xffffffffu, G, off);
            float pC = __shfl_up_sync(0xffffffffu, Cc, off);
            if (lane >= off) { Cc = fmaf(G, pC, Cc); G *= pG; }
        }
        float* wG = (float*)smem;
        float* wC = (float*)smem + 8;
        if (lane == 31) { wG[warp] = G; wC[warp] = Cc; }
        __syncthreads();
        float preC = 0.f;
        for (int w = 0; w < warp; w++) { preC = fmaf(wG[w], preC, wC[w]); }
        float eG = __shfl_up_sync(0xffffffffu, G, 1);
        float eC = __shfl_up_sync(0xffffffffu, Cc, 1);
        if (lane == 0) { eG = 1.f; eC = 0.f; }
        float s = fmaf(eG, preC, eC);
        #pragma unroll
        for (int u = 0; u < 16; u++) {
            s = fmaf(g[u], s, cc[u]);
            op[(s0 + u) * SD] = s;
        }
        if (tid == 255) final_state[b * SD + d] = s;
        return;
    }

    constexpr uint32_t STAGE = 49152u;
    const uint32_t sb = smem_to_u32(smem);
    const int lane = tid & 31;
    const int wid  = tid >> 5;
    const int wm   = wid >> 2;
    const int wn   = wid & 3;
    const int n0   = (blockIdx.x & 15) * 64;
    const int m0   = (blockIdx.x >> 4) * 128;

    float acc[4][2][4];
    #pragma unroll
    for (int mi = 0; mi < 4; mi++)
        #pragma unroll
        for (int ni = 0; ni < 2; ni++)
            #pragma unroll
            for (int e = 0; e < 4; e++) acc[mi][ni][e] = 0.f;

    const int row0 = tid >> 3;
    const int seg  = tid & 7;

    auto prefetch = [&](int buf, int kb) {
        const uint32_t st = sb + (uint32_t)buf * STAGE;
        #pragma unroll
        for (int i = 0; i < 4; i++) {
            int row = row0 + i * 32;
            uint32_t sw = (uint32_t)row * 128u + (uint32_t)((seg ^ (row & 7)) * 16);
            CP_ASYNC16(st + sw,          Ahi + (size_t)(m0 + row) * EE + kb + seg * 8);
            CP_ASYNC16(st + 32768u + sw, Alo + (size_t)(m0 + row) * EE + kb + seg * 8);
        }
        #pragma unroll
        for (int i = 0; i < 2; i++) {
            int row = row0 + i * 32;
            uint32_t sw = (uint32_t)row * 128u + (uint32_t)((seg ^ (row & 7)) * 16);
            CP_ASYNC16(st + 16384u + sw, Bhi + (size_t)(n0 + row) * EE + kb + seg * 8);
            CP_ASYNC16(st + 24576u + sw, Blo + (size_t)(n0 + row) * EE + kb + seg * 8);
        }
    };

    prefetch(0, 0);
    CP_COMMIT();

    const int rA  = ((lane >> 3) & 1) * 8 + (lane & 7);
    const int kA8 = lane >> 4;
    const int rB  = (lane >> 4) * 8 + (lane & 7);
    const int kB8 = (lane >> 3) & 1;

    for (int it = 0; it < NITER; it++) {
        if (it + 1 < NITER) prefetch((it + 1) & 1, (it + 1) * 64);
        CP_COMMIT();
        CP_WAIT1();
        __syncthreads();

        const uint32_t aB = sb + (uint32_t)(it & 1) * STAGE;

        #pragma unroll
        for (int ks = 0; ks < 4; ks++) {
            uint32_t af[4][4], afl[4][4], bh[2][2], bl[2][2];
            #pragma unroll
            for (int mi = 0; mi < 4; mi++) {
                int row = wm * 64 + mi * 16 + rA;
                int sh  = ks * 2 + kA8;
                uint32_t roff = (uint32_t)row * 128u + (uint32_t)((sh ^ (row & 7)) * 16);
                ldsm_x4(af[mi][0], af[mi][1], af[mi][2], af[mi][3], aB + roff);
                ldsm_x4(afl[mi][0], afl[mi][1], afl[mi][2], afl[mi][3],
                        aB + 32768u + roff);
            }
            {
                int row = wn * 16 + rB;
                int sh  = ks * 2 + kB8;
                uint32_t roff = (uint32_t)row * 128u + (uint32_t)((sh ^ (row & 7)) * 16);
                uint32_t r0, r1, r2, r3;
                ldsm_x4(r0, r1, r2, r3, aB + 16384u + roff);
                bh[0][0] = r0; bh[0][1] = r1;
                bh[1][0] = r2; bh[1][1] = r3;
                ldsm_x4(r0, r1, r2, r3, aB + 24576u + roff);
                bl[0][0] = r0; bl[0][1] = r1;
                bl[1][0] = r2; bl[1][1] = r3;
            }
            #pragma unroll
            for (int mi = 0; mi < 4; mi++)
                #pragma unroll
                for (int ni = 0; ni < 2; ni++) {
                    mma16816(acc[mi][ni], af[mi], bh[ni]);
                    mma16816(acc[mi][ni], af[mi], bl[ni]);
                    mma16816(acc[mi][ni], afl[mi], bh[ni]);
                }
        }
        __syncthreads();
    }

    const int lr  = lane >> 2;
    const int lc2 = (lane & 3) * 2;
    #pragma unroll
    for (int mi = 0; mi < 4; mi++) {
        int r0l = wm * 64 + mi * 16 + lr;
        int r1l = r0l + 8;
        #pragma unroll
        for (int ni = 0; ni < 2; ni++) {
            int cg = wn * 16 + ni * 8 + lc2;
            float* d = acc[mi][ni];
            __half2 o0 = { __float2half(d[0] * osc), __float2half(d[1] * osc) };
            __half2 o1 = { __float2half(d[2] * osc), __float2half(d[3] * osc) };
            *(__half2*)(C + (size_t)(m0 + r0l) * 1024 + n0 + cg) = o0;
            *(__half2*)(C + (size_t)(m0 + r1l) * 1024 + n0 + cg) = o1;
        }
    }
}

// ================= main 1-term fp16 GEMM, TMA loader =================
// Same fragment/mma/epilogue as R14; loader = cp.async.bulk.tensor.2d + mbarrier.
// smem: stage0 @0 (A 16K + B 16K), stage1 @32K; mbarriers @65536.
__global__ void __launch_bounds__(256, 2)
gemm_main_kernel(const __grid_constant__ CUtensorMap mapA,
                 const __grid_constant__ CUtensorMap mapB,
                 float* __restrict__ C,
                 const float* __restrict__ bias,
                 const float* __restrict__ Srank,
                 const float* __restrict__ Wbot)
{
    extern __shared__ __align__(1024) char smem[];
    const uint32_t sb = smem_to_u32(smem);
    const int tid  = threadIdx.x;
    const int lane = tid & 31;
    const int wid  = tid >> 5;
    const int wm   = wid >> 2;
    const int wn   = wid & 3;
    const int n0   = blockIdx.x * 128;
    const int m0   = blockIdx.y * 128;

    if (tid == 0) {
        MBARRIER_INIT(sb + 65536u, 1);
        MBARRIER_INIT(sb + 65544u, 1);
        asm volatile("fence.proxy.async.shared::cta;" ::: "memory");
    }
    __syncthreads();

    auto issue = [&](int it) {
        uint32_t st = (uint32_t)(it & 1);
        uint32_t mb = sb + 65536u + st * 8u;
        uint32_t dst = sb + st * 32768u;
        MBARRIER_EXPECT_TX(mb, 32768u);
        asm volatile(
            "cp.async.bulk.tensor.2d.shared::cta.global.tile.mbarrier::complete_tx::bytes "
            "[%0], [%1, {%2, %3}], [%4];"
            :: "r"(dst), "l"(&mapA), "r"(it * 64), "r"(m0), "r"(mb) : "memory");
        asm volatile(
            "cp.async.bulk.tensor.2d.shared::cta.global.tile.mbarrier::complete_tx::bytes "
            "[%0], [%1, {%2, %3}], [%4];"
            :: "r"(dst + 16384u), "l"(&mapB), "r"(it * 64), "r"(n0), "r"(mb) : "memory");
    };
    if (tid == 0) { issue(0); issue(1); }

    float acc[4][4][4];
    #pragma unroll
    for (int mi = 0; mi < 4; mi++)
        #pragma unroll
        for (int ni = 0; ni < 4; ni++)
            #pragma unroll
            for (int e = 0; e < 4; e++) acc[mi][ni][e] = 0.f;

    const int rA  = ((lane >> 3) & 1) * 8 + (lane & 7);
    const int kA8 = lane >> 4;
    const int rB  = (lane >> 4) * 8 + (lane & 7);
    const int kB8 = (lane >> 3) & 1;

    for (int it = 0; it < NITER; it++) {
        MBARRIER_WAIT_PARITY(sb + 65536u + (uint32_t)(it & 1) * 8u,
                             (uint32_t)((it >> 1) & 1));

        const uint32_t aB = sb + (uint32_t)(it & 1) * 32768u;
        const uint32_t bB = aB + 16384u;

        #pragma unroll
        for (int ks = 0; ks < 4; ks++) {
            uint32_t af[4][4], bf[4][2];
            #pragma unroll
            for (int mi = 0; mi < 4; mi++) {
                int row = wm * 64 + mi * 16 + rA;
                int sh  = ks * 2 + kA8;
                ldsm_x4(af[mi][0], af[mi][1], af[mi][2], af[mi][3],
                        aB + (uint32_t)row * 128u + (uint32_t)((sh ^ (row & 7)) * 16));
            }
            #pragma unroll
            for (int np = 0; np < 2; np++) {
                int row = wn * 32 + np * 16 + rB;
                int sh  = ks * 2 + kB8;
                uint32_t r0, r1, r2, r3;
                ldsm_x4(r0, r1, r2, r3,
                        bB + (uint32_t)row * 128u + (uint32_t)((sh ^ (row & 7)) * 16));
                bf[np * 2][0] = r0;     bf[np * 2][1] = r1;
                bf[np * 2 + 1][0] = r2; bf[np * 2 + 1][1] = r3;
            }
            #pragma unroll
            for (int mi = 0; mi < 4; mi++)
                #pragma unroll
                for (int ni = 0; ni < 4; ni++)
                    mma16816(acc[mi][ni], af[mi], bf[ni]);
        }
        __syncthreads();
        if (tid == 0 && it + 2 < NITER) issue(it + 2);
    }

    // ---------------- epilogue ----------------
    float* const sBias = (float*)smem;                 // 128 f
    float* const sSt   = (float*)(smem + 512);         // 128 x 8
    float* const sWb   = (float*)(smem + 512 + 4096);  // 8 x 128
    if (tid < 128) sBias[tid] = bias[n0 + tid];
    ((float4*)sSt)[tid] = ((const float4*)(Srank + (size_t)m0 * SD))[tid];
    for (int i = tid; i < 1024; i += 256) {
        int d8 = i >> 7, nl = i & 127;
        sWb[d8 * 128 + nl] = Wbot[(size_t)d8 * 1024 + n0 + nl];
    }
    __syncthreads();

    const int lr  = lane >> 2;
    const int lc2 = (lane & 3) * 2;
    #pragma unroll
    for (int mi = 0; mi < 4; mi++) {
        int r0l = wm * 64 + mi * 16 + lr;
        int r1l = r0l + 8;
        float st0[SD], st1[SD];
        #pragma unroll
        for (int d = 0; d < SD; d++) {
            st0[d] = sSt[r0l * SD + d];
            st1[d] = sSt[r1l * SD + d];
        }
        #pragma unroll
        for (int ni = 0; ni < 4; ni++) {
            int cg = wn * 32 + ni * 8 + lc2;
            float* d = acc[mi][ni];
            float s00 = sBias[cg], s01 = sBias[cg + 1];
            float s10 = s00, s11 = s01;
            #pragma unroll
            for (int dd = 0; dd < SD; dd++) {
                float w0 = sWb[dd * 128 + cg], w1 = sWb[dd * 128 + cg + 1];
                s00 = fmaf(st0[dd], w0, s00); s01 = fmaf(st0[dd], w1, s01);
                s10 = fmaf(st1[dd], w0, s10); s11 = fmaf(st1[dd], w1, s11);
            }
            float2 o0 = { d[0] + s00, d[1] + s01 };
            float2 o1 = { d[2] + s10, d[3] + s11 };
            *(float2*)(C + (size_t)(m0 + r0l) * 1024 + n0 + cg) = o0;
            *(float2*)(C + (size_t)(m0 + r1l) * 1024 + n0 + cg) = o1;
        }
    }
}

// ---------------- host tensormap encode (via driver entry point) ----------
typedef CUresult (*encodeTiled_t)(CUtensorMap*, CUtensorMapDataType, cuuint32_t,
                                  void*, const cuuint64_t*, const cuuint64_t*,
                                  const cuuint32_t*, const cuuint32_t*,
                                  CUtensorMapInterleave, CUtensorMapSwizzle,
                                  CUtensorMapL2promotion, CUtensorMapFloatOOBfill);

// ---------------- launch ----------------
extern "C" void kernel_launch(void* const* d_in, const int* in_sizes, int n_in,
                              void* d_out, int out_size)
{
    const float* x     = (const float*)d_in[0];
    const float* W_in  = (const float*)d_in[1];
    const float* b_in  = (const float*)d_in[2];
    const float* W_g   = (const float*)d_in[3];
    const float* b_g   = (const float*)d_in[4];
    const float* W_out = (const float*)d_in[5];
    const float* b_out = (const float*)d_in[6];
    float* out = (float*)d_out;

    float *Wg_eff, *bg_eff, *bout_eff, *gate, *si, *states;
    __half *XHi, *WinHi, *WinLo, *WoutHi, *WoutLo, *BweffH, *Wcomb;
    cudaGetSymbolAddress((void**)&Wg_eff,   g_Wg_eff);
    cudaGetSymbolAddress((void**)&bg_eff,   g_bg_eff);
    cudaGetSymbolAddress((void**)&bout_eff, g_bout_eff);
    cudaGetSymbolAddress((void**)&gate,     g_gate);
    cudaGetSymbolAddress((void**)&si,       g_si);
    cudaGetSymbolAddress((void**)&states,   g_states);
    cudaGetSymbolAddress((void**)&XHi,      g_XHi);
    cudaGetSymbolAddress((void**)&WinHi,    g_WinHi);
    cudaGetSymbolAddress((void**)&WinLo,    g_WinLo);
    cudaGetSymbolAddress((void**)&WoutHi,   g_WoutHi);
    cudaGetSymbolAddress((void**)&WoutLo,   g_WoutLo);
    cudaGetSymbolAddress((void**)&BweffH,   g_BweffH);
    cudaGetSymbolAddress((void**)&Wcomb,    g_Wcomb);

    // tensormaps for main GEMM (XHi: [K=1024, M=32768], BweffH: [1024, 1024])
    void* encFn = nullptr;
    cudaDriverEntryPointQueryResult qr;
    cudaGetDriverEntryPointByVersion("cuTensorMapEncodeTiled", &encFn, 12000,
                                     cudaEnableDefault, &qr);
    encodeTiled_t enc = (encodeTiled_t)encFn;

    CUtensorMap mapA, mapB;
    cuuint64_t dimsA[2] = { 1024, 32768 };
    cuuint64_t dimsB[2] = { 1024, 1024 };
    cuuint64_t strides[1] = { 2048 };          // row pitch bytes
    cuuint32_t box[2] = { 64, 128 };
    cuuint32_t es[2]  = { 1, 1 };
    enc(&mapA, CU_TENSOR_MAP_DATA_TYPE_FLOAT16, 2, (void*)XHi,
        dimsA, strides, box, es,
        CU_TENSOR_MAP_INTERLEAVE_NONE, CU_TENSOR_MAP_SWIZZLE_128B,
        CU_TENSOR_MAP_L2_PROMOTION_L2_128B, CU_TENSOR_MAP_FLOAT_OOB_FILL_NONE);
    enc(&mapB, CU_TENSOR_MAP_DATA_TYPE_FLOAT16, 2, (void*)BweffH,
        dimsB, strides, box, es,
        CU_TENSOR_MAP_INTERLEAVE_NONE, CU_TENSOR_MAP_SWIZZLE_128B,
        CU_TENSOR_MAP_L2_PROMOTION_L2_128B, CU_TENSOR_MAP_FLOAT_OOB_FILL_NONE);

    cudaFuncSetAttribute(merged_gatesi_decomp_kernel,
                         cudaFuncAttributeMaxDynamicSharedMemorySize, 65536);
    cudaFuncSetAttribute(merged_x3_scan_kernel,
                         cudaFuncAttributeMaxDynamicSharedMemorySize, 98304);
    cudaFuncSetAttribute(gemm_main_kernel,
                         cudaFuncAttributeMaxDynamicSharedMemorySize, 66560);

    // 1) folded weights + Wcomb
    int nwarps = EE * SD + SD + EE + EE;            // 10248
    precompute_kernel<<<(nwarps * 32 + 255) / 256, 256>>>(
        W_in, W_g, b_g, b_in, W_out, b_out, Wg_eff, bg_eff, bout_eff, Wcomb);

    // 2) merged: gate/si/x-cast || weight decompose
    merged_gatesi_decomp_kernel<<<2304, 256, 65536>>>(
        x, Wcomb, bg_eff, b_in, gate, si, XHi,
        W_in, W_out, WinHi, WinLo, WoutHi, WoutLo);

    // 3) merged: Weff^T 3-term GEMM || scan
    merged_x3_scan_kernel<<<192, 256, 98304>>>(
        WoutHi, WoutLo, WinHi, WinLo, BweffH, 1.0f / 1024.0f,
        gate, si, states, out + (size_t)MM * EE);

    // 4) out = x @ Weff + states @ W_out[E:, :] + bout_eff   (TMA main)
    gemm_main_kernel<<<dim3(8, MM / 128), 256, 66560>>>(
        mapA, mapB, out, bout_eff, states, W_out + (size_t)EE * EE);
}

// round 16
// speedup vs baseline: 1.8455x; 1.0245x over previous
#include <cuda_runtime.h>
#include <cuda.h>
#include <cuda_fp16.h>
#include <math.h>
#include <stdint.h>

// ---------------- problem constants ----------------
#define BB 8
#define SS 4096
#define EE 1024
#define SD 8
#define MM (BB*SS)          // 32768
#define LDIN 1032           // E + SD
#define NITER 16            // K=1024 / 64

// ================= portable PTX helpers (sm_80+/sm_90) =================
__device__ __forceinline__ uint32_t smem_to_u32(const void* smem_ptr) {
    uint32_t addr;
    asm("{ .reg .u64 tmp; cvta.to.shared.u64 tmp, %1; cvt.u32.u64 %0, tmp; }"
        : "=r"(addr) : "l"(smem_ptr));
    return addr;
}

#define CP_ASYNC16(dst, src) \
    asm volatile("cp.async.cg.shared.global [%0], [%1], 16;" \
                 :: "r"(dst), "l"(src) : "memory")
#define CP_COMMIT() asm volatile("cp.async.commit_group;" ::: "memory")
#define CP_WAIT1()  asm volatile("cp.async.wait_group 1;"  ::: "memory")

#define MBARRIER_INIT(mbar, count) \
    asm volatile("mbarrier.init.shared.b64 [%0], %1;" \
                 :: "r"((uint32_t)(mbar)), "r"((uint32_t)(count)) : "memory")

#define MBARRIER_EXPECT_TX(mbar, bytes) \
    asm volatile("mbarrier.arrive.expect_tx.shared.b64 _, [%0], %1;" \
                 :: "r"((uint32_t)(mbar)), "r"((uint32_t)(bytes)) : "memory")

#define MBARRIER_WAIT_PARITY(mbar, parity) do { \
    uint32_t _mb = (uint32_t)(mbar); \
    uint32_t _ph = (uint32_t)(parity); \
    asm volatile( \
        "{\n\t" \
        ".reg .pred P1;\n\t" \
        "WAIT_LOOP_%=:\n\t" \
        "mbarrier.try_wait.parity.acquire.cta.shared::cta.b64 P1, [%0], %1, 0x989680;\n\t" \
        "@P1 bra.uni WAIT_DONE_%=;\n\t" \
        "bra.uni WAIT_LOOP_%=;\n\t" \
        "WAIT_DONE_%=:\n\t" \
        "}" :: "r"(_mb), "r"(_ph) : "memory"); \
} while(0)

__device__ __forceinline__ void ldsm_x4(uint32_t& r0, uint32_t& r1,
                                        uint32_t& r2, uint32_t& r3,
                                        uint32_t addr) {
    asm volatile("ldmatrix.sync.aligned.m8n8.x4.shared.b16 {%0,%1,%2,%3}, [%4];"
                 : "=r"(r0), "=r"(r1), "=r"(r2), "=r"(r3) : "r"(addr));
}

__device__ __forceinline__ void mma16816(float* d, const uint32_t* a,
                                         const uint32_t* b) {
    asm volatile("mma.sync.aligned.m16n8k16.row.col.f32.f16.f16.f32 "
                 "{%0,%1,%2,%3}, {%4,%5,%6,%7}, {%8,%9}, {%0,%1,%2,%3};"
                 : "+f"(d[0]), "+f"(d[1]), "+f"(d[2]), "+f"(d[3])
                 : "r"(a[0]), "r"(a[1]), "r"(a[2]), "r"(a[3]),
                   "r"(b[0]), "r"(b[1]));
}

// ---------------- scratch (device globals, no allocs) ----------------
__device__ float g_Wg_eff[EE * SD];
__device__ float g_bg_eff[SD];
__device__ float g_bout_eff[EE];
__device__ float g_gate[MM * SD];
__device__ float g_si[MM * SD];
__device__ float g_states[MM * SD];
__device__ __half g_XHi[(size_t)MM * EE];      // x fp16 (written by gate blocks)
__device__ __half g_WinHi[(size_t)EE * EE];    // 32*W_in top square, hi (rows)
__device__ __half g_WinLo[(size_t)EE * EE];
__device__ __half g_WoutHi[(size_t)EE * EE];   // 32*W_out top, transposed
__device__ __half g_WoutLo[(size_t)EE * EE];
__device__ __half g_BweffH[(size_t)EE * EE];   // Weff^T fp16 (written by x3)
__device__ __half g_Wcomb[16 * EE];            // [d][e]: gate 0-7, si 8-15

// ========== kernel 1: folded weights + Wcomb (warp per output) ==========
__global__ void precompute_kernel(const float* __restrict__ W_in,
                                  const float* __restrict__ W_g,
                                  const float* __restrict__ b_g,
                                  const float* __restrict__ b_in,
                                  const float* __restrict__ W_out,
                                  const float* __restrict__ b_out,
                                  float* __restrict__ Wg_eff,
                                  float* __restrict__ bg_eff,
                                  float* __restrict__ bout_eff,
                                  __half* __restrict__ Wcomb)
{
    const int w    = (blockIdx.x * blockDim.x + threadIdx.x) >> 5;
    const int lane = threadIdx.x & 31;
    float s = 0.f;
    if (w < EE * SD) {
        int e = w >> 3, d = w & 7;
        const float* wr = W_in + (size_t)e * LDIN;
        for (int c = lane; c < LDIN; c += 32)
            s = fmaf(wr[c], W_g[c * SD + d], s);
        #pragma unroll
        for (int o = 16; o; o >>= 1) s += __shfl_xor_sync(0xffffffffu, s, o);
        if (lane == 0) {
            Wg_eff[w] = s;
            Wcomb[d * EE + e] = __float2half(s);
        }
    } else if (w < EE * SD + SD) {
        int d = w - EE * SD;
        for (int c = lane; c < LDIN; c += 32)
            s = fmaf(b_in[c], W_g[c * SD + d], s);
        #pragma unroll
        for (int o = 16; o; o >>= 1) s += __shfl_xor_sync(0xffffffffu, s, o);
        if (lane == 0) bg_eff[d] = s + b_g[d];
    } else if (w < EE * SD + SD + EE) {
        int n = w - (EE * SD + SD);
        for (int c = lane; c < EE; c += 32)
            s = fmaf(b_in[c], W_out[(size_t)c * EE + n], s);
        #pragma unroll
        for (int o = 16; o; o >>= 1) s += __shfl_xor_sync(0xffffffffu, s, o);
        if (lane == 0) bout_eff[n] = s + b_out[n];
    } else if (w < EE * SD + SD + EE + EE) {
        int e = w - (EE * SD + SD + EE);
        if (lane < 8)
            Wcomb[(8 + lane) * EE + e] =
                __float2half(W_in[(size_t)e * LDIN + EE + lane]);
    }
}

// ========== kernel 2: merged decompose (hi/lo) + gate_si_tc ==========
__global__ void __launch_bounds__(256, 2)
merged_gatesi_decomp_kernel(const float* __restrict__ x,
                            const __half* __restrict__ Wcomb,
                            const float* __restrict__ bg_eff,
                            const float* __restrict__ b_in,
                            float* __restrict__ gate,
                            float* __restrict__ si,
                            __half* __restrict__ xh,
                            const float* __restrict__ W_in,
                            const float* __restrict__ W_out,
                            __half* __restrict__ WinHi,
                            __half* __restrict__ WinLo,
                            __half* __restrict__ WoutHi,
                            __half* __restrict__ WoutLo)
{
    extern __shared__ char smem[];
    const int tid = threadIdx.x;

    if (blockIdx.x >= 256) {
        int b2 = blockIdx.x - 256;
        if (b2 < 1024) {
            int r = b2;
            int c4 = tid * 4;
            float4 v = *(const float4*)(W_in + (size_t)r * LDIN + c4);
            struct alignas(8) H4 { __half h[4]; };
            H4 H, L;
            float vv[4] = {v.x, v.y, v.z, v.w};
            #pragma unroll
            for (int i = 0; i < 4; i++) {
                float sv = vv[i] * 32.0f;
                __half h = __float2half(sv);
                H.h[i] = h;
                L.h[i] = __float2half(sv - __half2float(h));
            }
            *(H4*)(WinHi + (size_t)r * EE + c4) = H;
            *(H4*)(WinLo + (size_t)r * EE + c4) = L;
        } else {
            float* tile = (float*)smem;          // 32 x 33
            int b = b2 - 1024;
            int e0 = (b & 31) * 32, n0 = (b >> 5) * 32;
            int tx = tid & 31, ty = tid >> 5;
            #pragma unroll
            for (int i = 0; i < 4; i++)
                tile[(ty + i * 8) * 33 + tx] =
                    W_out[(size_t)(e0 + ty + i * 8) * 1024 + n0 + tx];
            __syncthreads();
            #pragma unroll
            for (int i = 0; i < 4; i++) {
                int n = n0 + ty + i * 8;
                float v = tile[tx * 33 + ty + i * 8] * 32.0f;
                __half h = __float2half(v);
                WoutHi[(size_t)n * EE + e0 + tx] = h;
                WoutLo[(size_t)n * EE + e0 + tx] = __float2half(v - __half2float(h));
            }
        }
        return;
    }

    // ---- gate_si tile (proven R13 body) ----
    const uint32_t sb = smem_to_u32(smem);
    const int lane = tid & 31;
    const int wid  = tid >> 5;
    const int m0   = blockIdx.x * 128;

    for (int i = tid; i < 2048; i += 256) {
        int h8 = i * 8;
        int d = h8 >> 10, k = h8 & 1023;
        int row = (k >> 6) * 16 + d;
        int seg = (k & 63) >> 3;
        uint4 v = *(const uint4*)(Wcomb + (size_t)d * 1024 + k);
        *(uint4*)(smem + row * 128 + ((seg ^ (row & 7)) * 16)) = v;
    }

    const int rowg = tid >> 4;
    const int f4i  = tid & 15;
    const int segA = f4i >> 1;
    const int off8 = (f4i & 1) * 8;

    float4 xv[8];
    auto loadx = [&](int c) {
        const float* xp = x + (size_t)(m0 + rowg) * EE + c * 64 + f4i * 4;
        #pragma unroll
        for (int i = 0; i < 8; i++)
            xv[i] = *(const float4*)(xp + (size_t)i * 16 * EE);
    };

    auto cvtstore = [&](int c, int buf) {
        char* abase = smem + 32768 + buf * 16384;
        __half* xhp = xh + (size_t)(m0 + rowg) * EE + c * 64 + f4i * 4;
        #pragma unroll
        for (int i = 0; i < 8; i++) {
            int row = rowg + i * 16;
            __half2 p0 = __floats2half2_rn(xv[i].x, xv[i].y);
            __half2 p1 = __floats2half2_rn(xv[i].z, xv[i].w);
            struct alignas(8) H2x2 { __half2 a, b; };
            H2x2 p = { p0, p1 };
            *(H2x2*)(abase + row * 128 + ((segA ^ (row & 7)) * 16) + off8) = p;
            *(H2x2*)(xhp + (size_t)i * 16 * EE) = p;
        }
    };

    loadx(0);
    cvtstore(0, 0);
    __syncthreads();

    const int rA  = ((lane >> 3) & 1) * 8 + (lane & 7);
    const int kA8 = lane >> 4;
    const int rB  = (lane >> 4) * 8 + (lane & 7);
    const int kB8 = (lane >> 3) & 1;
    const int wrow = wid * 16;

    float acc[2][4] = {{0.f,0.f,0.f,0.f},{0.f,0.f,0.f,0.f}};

    for (int c = 0; c < 16; c++) {
        if (c + 1 < 16) loadx(c + 1);
        const uint32_t aB = sb + 32768u + (uint32_t)(c & 1) * 16384u;
        #pragma unroll
        for (int ks = 0; ks < 4; ks++) {
            uint32_t af[4], bf[2][2];
            {
                int row = wrow + rA;
                int sh  = ks * 2 + kA8;
                ldsm_x4(af[0], af[1], af[2], af[3],
                        aB + (uint32_t)row * 128u + (uint32_t)((sh ^ (row & 7)) * 16));
            }
            {
                int row = c * 16 + rB;
                int sh  = ks * 2 + kB8;
                uint32_t r0, r1, r2, r3;
                ldsm_x4(r0, r1, r2, r3,
                        sb + (uint32_t)row * 128u + (uint32_t)((sh ^ (row & 7)) * 16));
                bf[0][0] = r0; bf[0][1] = r1;
                bf[1][0] = r2; bf[1][1] = r3;
            }
            mma16816(acc[0], af, bf[0]);
            mma16816(acc[1], af, bf[1]);
        }
        if (c + 1 < 16) cvtstore(c + 1, (c + 1) & 1);
        __syncthreads();
    }

    const int lr  = lane >> 2;
    const int lc2 = (lane & 3) * 2;
    const float bg0 = bg_eff[lc2],      bg1 = bg_eff[lc2 + 1];
    const float bi0 = b_in[EE + lc2],   bi1 = b_in[EE + lc2 + 1];
    const int r0 = m0 + wrow + lr;
    const int r1 = r0 + 8;
    float2 gg0 = { 1.0f / (1.0f + expf(-(acc[0][0] + bg0))),
                   1.0f / (1.0f + expf(-(acc[0][1] + bg1))) };
    float2 gg1 = { 1.0f / (1.0f + expf(-(acc[0][2] + bg0))),
                   1.0f / (1.0f + expf(-(acc[0][3] + bg1))) };
    *(float2*)(gate + (size_t)r0 * SD + lc2) = gg0;
    *(float2*)(gate + (size_t)r1 * SD + lc2) = gg1;
    float2 ss0 = { acc[1][0] + bi0, acc[1][1] + bi1 };
    float2 ss1 = { acc[1][2] + bi0, acc[1][3] + bi1 };
    *(float2*)(si + (size_t)r0 * SD + lc2) = ss0;
    *(float2*)(si + (size_t)r1 * SD + lc2) = ss1;
}

// ========== kernel 3: merged x3 (Weff^T) + scan ==========
__global__ void __launch_bounds__(256, 2)
merged_x3_scan_kernel(const __half* __restrict__ Ahi,
                      const __half* __restrict__ Alo,
                      const __half* __restrict__ Bhi,
                      const __half* __restrict__ Blo,
                      __half* __restrict__ C, float osc,
                      const float* __restrict__ gate,
                      const float* __restrict__ si,
                      float* __restrict__ states,
                      float* __restrict__ final_state)
{
    extern __shared__ char smem[];
    const int tid = threadIdx.x;

    if (blockIdx.x >= 128) {
        const int chain = blockIdx.x - 128;
        const int b = chain >> 3, d = chain & 7;
        const int lane = tid & 31, warp = tid >> 5;
        const float* gp = gate + (size_t)b * SS * SD + d;
        const float* sp = si   + (size_t)b * SS * SD + d;
        float*       op = states + (size_t)b * SS * SD + d;
        const int s0 = tid * 16;

        float g[16], cc[16];
        float G = 1.f, Cc = 0.f;
        #pragma unroll
        for (int u = 0; u < 16; u++) {
            float gv = gp[(s0 + u) * SD];
            float sv = sp[(s0 + u) * SD];
            float cv = sv - gv * sv;
            g[u] = gv; cc[u] = cv;
            Cc = fmaf(gv, Cc, cv);
            G = gv * G;
        }
        #pragma unroll
        for (int off = 1; off < 32; off <<= 1) {
            float pG = __shfl_up_sync(0xffffffffu, G, off);
            float pC = __shfl_up_sync(0xffffffffu, Cc, off);
            if (lane >= off) { Cc = fmaf(G, pC, Cc); G *= pG; }
        }
        float* wG = (float*)smem;
        float* wC = (float*)smem + 8;
        if (lane == 31) { wG[warp] = G; wC[warp] = Cc; }
        __syncthreads();
        float preC = 0.f;
        for (int w = 0; w < warp; w++) { preC = fmaf(wG[w], preC, wC[w]); }
        float eG = __shfl_up_sync(0xffffffffu, G, 1);
        float eC = __shfl_up_sync(0xffffffffu, Cc, 1);
        if (lane == 0) { eG = 1.f; eC = 0.f; }
        float s = fmaf(eG, preC, eC);
        #pragma unroll
        for (int u = 0; u < 16; u++) {
            s = fmaf(g[u], s, cc[u]);
            op[(s0 + u) * SD] = s;
        }
        if (tid == 255) final_state[b * SD + d] = s;
        return;
    }

    constexpr uint32_t STAGE = 49152u;
    const uint32_t sb = smem_to_u32(smem);
    const int lane = tid & 31;
    const int wid  = tid >> 5;
    const int wm   = wid >> 2;
    const int wn   = wid & 3;
    const int n0   = (blockIdx.x & 15) * 64;
    const int m0   = (blockIdx.x >> 4) * 128;

    float acc[4][2][4];
    #pragma unroll
    for (int mi = 0; mi < 4; mi++)
        #pragma unroll
        for (int ni = 0; ni < 2; ni++)
            #pragma unroll
            for (int e = 0; e < 4; e++) acc[mi][ni][e] = 0.f;

    const int row0 = tid >> 3;
    const int seg  = tid & 7;

    auto prefetch = [&](int buf, int kb) {
        const uint32_t st = sb + (uint32_t)buf * STAGE;
        #pragma unroll
        for (int i = 0; i < 4; i++) {
            int row = row0 + i * 32;
            uint32_t sw = (uint32_t)row * 128u + (uint32_t)((seg ^ (row & 7)) * 16);
            CP_ASYNC16(st + sw,          Ahi + (size_t)(m0 + row) * EE + kb + seg * 8);
            CP_ASYNC16(st + 32768u + sw, Alo + (size_t)(m0 + row) * EE + kb + seg * 8);
        }
        #pragma unroll
        for (int i = 0; i < 2; i++) {
            int row = row0 + i * 32;
            uint32_t sw = (uint32_t)row * 128u + (uint32_t)((seg ^ (row & 7)) * 16);
            CP_ASYNC16(st + 16384u + sw, Bhi + (size_t)(n0 + row) * EE + kb + seg * 8);
            CP_ASYNC16(st + 24576u + sw, Blo + (size_t)(n0 + row) * EE + kb + seg * 8);
        }
    };

    prefetch(0, 0);
    CP_COMMIT();

    const int rA  = ((lane >> 3) & 1) * 8 + (lane & 7);
    const int kA8 = lane >> 4;
    const int rB  = (lane >> 4) * 8 + (lane & 7);
    const int kB8 = (lane >> 3) & 1;

    for (int it = 0; it < NITER; it++) {
        if (it + 1 < NITER) prefetch((it + 1) & 1, (it + 1) * 64);
        CP_COMMIT();
        CP_WAIT1();
        __syncthreads();

        const uint32_t aB = sb + (uint32_t)(it & 1) * STAGE;

        #pragma unroll
        for (int ks = 0; ks < 4; ks++) {
            uint32_t af[4][4], afl[4][4], bh[2][2], bl[2][2];
            #pragma unroll
            for (int mi = 0; mi < 4; mi++) {
                int row = wm * 64 + mi * 16 + rA;
                int sh  = ks * 2 + kA8;
                uint32_t roff = (uint32_t)row * 128u + (uint32_t)((sh ^ (row & 7)) * 16);
                ldsm_x4(af[mi][0], af[mi][1], af[mi][2], af[mi][3], aB + roff);
                ldsm_x4(afl[mi][0], afl[mi][1], afl[mi][2], afl[mi][3],
                        aB + 32768u + roff);
            }
            {
                int row = wn * 16 + rB;
                int sh  = ks * 2 + kB8;
                uint32_t roff = (uint32_t)row * 128u + (uint32_t)((sh ^ (row & 7)) * 16);
                uint32_t r0, r1, r2, r3;
                ldsm_x4(r0, r1, r2, r3, aB + 16384u + roff);
                bh[0][0] = r0; bh[0][1] = r1;
                bh[1][0] = r2; bh[1][1] = r3;
                ldsm_x4(r0, r1, r2, r3, aB + 24576u + roff);
                bl[0][0] = r0; bl[0][1] = r1;
                bl[1][0] = r2; bl[1][1] = r3;
            }
            #pragma unroll
            for (int mi = 0; mi < 4; mi++)
                #pragma unroll
                for (int ni = 0; ni < 2; ni++) {
                    mma16816(acc[mi][ni], af[mi], bh[ni]);
                    mma16816(acc[mi][ni], af[mi], bl[ni]);
                    mma16816(acc[mi][ni], afl[mi], bh[ni]);
                }
        }
        __syncthreads();
    }

    const int lr  = lane >> 2;
    const int lc2 = (lane & 3) * 2;
    #pragma unroll
    for (int mi = 0; mi < 4; mi++) {
        int r0l = wm * 64 + mi * 16 + lr;
        int r1l = r0l + 8;
        #pragma unroll
        for (int ni = 0; ni < 2; ni++) {
            int cg = wn * 16 + ni * 8 + lc2;
            float* d = acc[mi][ni];
            __half2 o0 = { __float2half(d[0] * osc), __float2half(d[1] * osc) };
            __half2 o1 = { __float2half(d[2] * osc), __float2half(d[3] * osc) };
            *(__half2*)(C + (size_t)(m0 + r0l) * 1024 + n0 + cg) = o0;
            *(__half2*)(C + (size_t)(m0 + r1l) * 1024 + n0 + cg) = o1;
        }
    }
}

// ================= main 1-term fp16 GEMM, TMA loader, 64x64 warp tiles =====
// CTA 128x128, 4 warps (2x2 of 64x64), 128 threads, 2 CTA/SM.
// Per ks: 4 A-ldsm + 4 B-ldsm feed 32 MMAs (128B smem per MMA, was 192B).
// smem: stage0 @0 (A 16K + B 16K), stage1 @32K; mbarriers @65536.
__global__ void __launch_bounds__(128, 2)
gemm_main_kernel(const __grid_constant__ CUtensorMap mapA,
                 const __grid_constant__ CUtensorMap mapB,
                 float* __restrict__ C,
                 const float* __restrict__ bias,
                 const float* __restrict__ Srank,
                 const float* __restrict__ Wbot)
{
    extern __shared__ __align__(1024) char smem[];
    const uint32_t sb = smem_to_u32(smem);
    const int tid  = threadIdx.x;
    const int lane = tid & 31;
    const int wid  = tid >> 5;            // 0..3
    const int wm   = wid >> 1;            // 0..1
    const int wn   = wid & 1;             // 0..1
    const int n0   = blockIdx.x * 128;
    const int m0   = blockIdx.y * 128;

    if (tid == 0) {
        MBARRIER_INIT(sb + 65536u, 1);
        MBARRIER_INIT(sb + 65544u, 1);
        asm volatile("fence.proxy.async.shared::cta;" ::: "memory");
    }
    __syncthreads();

    auto issue = [&](int it) {
        uint32_t st = (uint32_t)(it & 1);
        uint32_t mb = sb + 65536u + st * 8u;
        uint32_t dst = sb + st * 32768u;
        MBARRIER_EXPECT_TX(mb, 32768u);
        asm volatile(
            "cp.async.bulk.tensor.2d.shared::cta.global.tile.mbarrier::complete_tx::bytes "
            "[%0], [%1, {%2, %3}], [%4];"
            :: "r"(dst), "l"(&mapA), "r"(it * 64), "r"(m0), "r"(mb) : "memory");
        asm volatile(
            "cp.async.bulk.tensor.2d.shared::cta.global.tile.mbarrier::complete_tx::bytes "
            "[%0], [%1, {%2, %3}], [%4];"
            :: "r"(dst + 16384u), "l"(&mapB), "r"(it * 64), "r"(n0), "r"(mb) : "memory");
    };
    if (tid == 0) { issue(0); issue(1); }

    float acc[4][8][4];
    #pragma unroll
    for (int mi = 0; mi < 4; mi++)
        #pragma unroll
        for (int ni = 0; ni < 8; ni++)
            #pragma unroll
            for (int e = 0; e < 4; e++) acc[mi][ni][e] = 0.f;

    const int rA  = ((lane >> 3) & 1) * 8 + (lane & 7);
    const int kA8 = lane >> 4;
    const int rB  = (lane >> 4) * 8 + (lane & 7);
    const int kB8 = (lane >> 3) & 1;

    for (int it = 0; it < NITER; it++) {
        MBARRIER_WAIT_PARITY(sb + 65536u + (uint32_t)(it & 1) * 8u,
                             (uint32_t)((it >> 1) & 1));

        const uint32_t aB = sb + (uint32_t)(it & 1) * 32768u;
        const uint32_t bB = aB + 16384u;

        #pragma unroll
        for (int ks = 0; ks < 4; ks++) {
            uint32_t af[4][4], bf[8][2];
            #pragma unroll
            for (int mi = 0; mi < 4; mi++) {
                int row = wm * 64 + mi * 16 + rA;
                int sh  = ks * 2 + kA8;
                ldsm_x4(af[mi][0], af[mi][1], af[mi][2], af[mi][3],
                        aB + (uint32_t)row * 128u + (uint32_t)((sh ^ (row & 7)) * 16));
            }
            #pragma unroll
            for (int np = 0; np < 4; np++) {
                int row = wn * 64 + np * 16 + rB;
                int sh  = ks * 2 + kB8;
                uint32_t r0, r1, r2, r3;
                ldsm_x4(r0, r1, r2, r3,
                        bB + (uint32_t)row * 128u + (uint32_t)((sh ^ (row & 7)) * 16));
                bf[np * 2][0] = r0;     bf[np * 2][1] = r1;
                bf[np * 2 + 1][0] = r2; bf[np * 2 + 1][1] = r3;
            }
            #pragma unroll
            for (int mi = 0; mi < 4; mi++)
                #pragma unroll
                for (int ni = 0; ni < 8; ni++)
                    mma16816(acc[mi][ni], af[mi], bf[ni]);
        }
        __syncthreads();
        if (tid == 0 && it + 2 < NITER) issue(it + 2);
    }

    // ---------------- epilogue ----------------
    float* const sBias = (float*)smem;                 // 128 f
    float* const sSt   = (float*)(smem + 512);         // 128 x 8
    float* const sWb   = (float*)(smem + 512 + 4096);  // 8 x 128
    sBias[tid] = bias[n0 + tid];
    ((float4*)sSt)[tid]       = ((const float4*)(Srank + (size_t)m0 * SD))[tid];
    ((float4*)sSt)[tid + 128] = ((const float4*)(Srank + (size_t)m0 * SD))[tid + 128];
    for (int i = tid; i < 1024; i += 128) {
        int d8 = i >> 7, nl = i & 127;
        sWb[d8 * 128 + nl] = Wbot[(size_t)d8 * 1024 + n0 + nl];
    }
    __syncthreads();

    const int lr  = lane >> 2;
    const int lc2 = (lane & 3) * 2;
    #pragma unroll
    for (int mi = 0; mi < 4; mi++) {
        int r0l = wm * 64 + mi * 16 + lr;
        int r1l = r0l + 8;
        float st0[SD], st1[SD];
        #pragma unroll
        for (int d = 0; d < SD; d++) {
            st0[d] = sSt[r0l * SD + d];
            st1[d] = sSt[r1l * SD + d];
        }
        #pragma unroll
        for (int ni = 0; ni < 8; ni++) {
            int cg = wn * 64 + ni * 8 + lc2;
            float* d = acc[mi][ni];
            float s00 = sBias[cg], s01 = sBias[cg + 1];
            float s10 = s00, s11 = s01;
            #pragma unroll
            for (int dd = 0; dd < SD; dd++) {
                float w0 = sWb[dd * 128 + cg], w1 = sWb[dd * 128 + cg + 1];
                s00 = fmaf(st0[dd], w0, s00); s01 = fmaf(st0[dd], w1, s01);
                s10 = fmaf(st1[dd], w0, s10); s11 = fmaf(st1[dd], w1, s11);
            }
            float2 o0 = { d[0] + s00, d[1] + s01 };
            float2 o1 = { d[2] + s10, d[3] + s11 };
            *(float2*)(C + (size_t)(m0 + r0l) * 1024 + n0 + cg) = o0;
            *(float2*)(C + (size_t)(m0 + r1l) * 1024 + n0 + cg) = o1;
        }
    }
}

// ---------------- host tensormap encode (via driver entry point) ----------
typedef CUresult (*encodeTiled_t)(CUtensorMap*, CUtensorMapDataType, cuuint32_t,
                                  void*, const cuuint64_t*, const cuuint64_t*,
                                  const cuuint32_t*, const cuuint32_t*,
                                  CUtensorMapInterleave, CUtensorMapSwizzle,
                                  CUtensorMapL2promotion, CUtensorMapFloatOOBfill);

// ---------------- launch ----------------
extern "C" void kernel_launch(void* const* d_in, const int* in_sizes, int n_in,
                              void* d_out, int out_size)
{
    const float* x     = (const float*)d_in[0];
    const float* W_in  = (const float*)d_in[1];
    const float* b_in  = (const float*)d_in[2];
    const float* W_g   = (const float*)d_in[3];
    const float* b_g   = (const float*)d_in[4];
    const float* W_out = (const float*)d_in[5];
    const float* b_out = (const float*)d_in[6];
    float* out = (float*)d_out;

    float *Wg_eff, *bg_eff, *bout_eff, *gate, *si, *states;
    __half *XHi, *WinHi, *WinLo, *WoutHi, *WoutLo, *BweffH, *Wcomb;
    cudaGetSymbolAddress((void**)&Wg_eff,   g_Wg_eff);
    cudaGetSymbolAddress((void**)&bg_eff,   g_bg_eff);
    cudaGetSymbolAddress((void**)&bout_eff, g_bout_eff);
    cudaGetSymbolAddress((void**)&gate,     g_gate);
    cudaGetSymbolAddress((void**)&si,       g_si);
    cudaGetSymbolAddress((void**)&states,   g_states);
    cudaGetSymbolAddress((void**)&XHi,      g_XHi);
    cudaGetSymbolAddress((void**)&WinHi,    g_WinHi);
    cudaGetSymbolAddress((void**)&WinLo,    g_WinLo);
    cudaGetSymbolAddress((void**)&WoutHi,   g_WoutHi);
    cudaGetSymbolAddress((void**)&WoutLo,   g_WoutLo);
    cudaGetSymbolAddress((void**)&BweffH,   g_BweffH);
    cudaGetSymbolAddress((void**)&Wcomb,    g_Wcomb);

    // tensormaps for main GEMM (XHi: [K=1024, M=32768], BweffH: [1024, 1024])
    void* encFn = nullptr;
    cudaDriverEntryPointQueryResult qr;
    cudaGetDriverEntryPointByVersion("cuTensorMapEncodeTiled", &encFn, 12000,
                                     cudaEnableDefault, &qr);
    encodeTiled_t enc = (encodeTiled_t)encFn;

    CUtensorMap mapA, mapB;
    cuuint64_t dimsA[2] = { 1024, 32768 };
    cuuint64_t dimsB[2] = { 1024, 1024 };
    cuuint64_t strides[1] = { 2048 };          // row pitch bytes
    cuuint32_t box[2] = { 64, 128 };
    cuuint32_t es[2]  = { 1, 1 };
    enc(&mapA, CU_TENSOR_MAP_DATA_TYPE_FLOAT16, 2, (void*)XHi,
        dimsA, strides, box, es,
        CU_TENSOR_MAP_INTERLEAVE_NONE, CU_TENSOR_MAP_SWIZZLE_128B,
        CU_TENSOR_MAP_L2_PROMOTION_L2_128B, CU_TENSOR_MAP_FLOAT_OOB_FILL_NONE);
    enc(&mapB, CU_TENSOR_MAP_DATA_TYPE_FLOAT16, 2, (void*)BweffH,
        dimsB, strides, box, es,
        CU_TENSOR_MAP_INTERLEAVE_NONE, CU_TENSOR_MAP_SWIZZLE_128B,
        CU_TENSOR_MAP_L2_PROMOTION_L2_128B, CU_TENSOR_MAP_FLOAT_OOB_FILL_NONE);

    cudaFuncSetAttribute(merged_gatesi_decomp_kernel,
                         cudaFuncAttributeMaxDynamicSharedMemorySize, 65536);
    cudaFuncSetAttribute(merged_x3_scan_kernel,
                         cudaFuncAttributeMaxDynamicSharedMemorySize, 98304);
    cudaFuncSetAttribute(gemm_main_kernel,
                         cudaFuncAttributeMaxDynamicSharedMemorySize, 66560);

    // 1) folded weights + Wcomb
    int nwarps = EE * SD + SD + EE + EE;            // 10248
    precompute_kernel<<<(nwarps * 32 + 255) / 256, 256>>>(
        W_in, W_g, b_g, b_in, W_out, b_out, Wg_eff, bg_eff, bout_eff, Wcomb);

    // 2) merged: gate/si/x-cast || weight decompose
    merged_gatesi_decomp_kernel<<<2304, 256, 65536>>>(
        x, Wcomb, bg_eff, b_in, gate, si, XHi,
        W_in, W_out, WinHi, WinLo, WoutHi, WoutLo);

    // 3) merged: Weff^T 3-term GEMM || scan
    merged_x3_scan_kernel<<<192, 256, 98304>>>(
        WoutHi, WoutLo, WinHi, WinLo, BweffH, 1.0f / 1024.0f,
        gate, si, states, out + (size_t)MM * EE);

    // 4) out = x @ Weff + states @ W_out[E:, :] + bout_eff   (TMA, 64x64 warps)
    gemm_main_kernel<<<dim3(8, MM / 128), 128, 66560>>>(
        mapA, mapB, out, bout_eff, states, W_out + (size_t)EE * EE);
}